// round 1
// baseline (speedup 1.0000x reference)
#include <cuda_runtime.h>
#include <cstddef>

#define BB 2
#define SS 2048
#define DD 1024
#define HH 16
#define HDIM 64
#define MTOT (BB*SS)   // 4096

// Scratch: device globals (no allocations allowed)
__device__ float g_Q[MTOT*DD];
__device__ float g_K[MTOT*DD];
__device__ float g_V[MTOT*DD];
__device__ float g_C[MTOT*DD];

// ---------------------------------------------------------------------------
// Tiled SGEMM (NT): C[m,n] = sum_k A[m,k] * W[n,k]  (+ bias[n])
// BM=BN=128, BK=16, 256 threads, 8x8 per-thread micro-tile.
// ---------------------------------------------------------------------------
__device__ __forceinline__ void sgemm_tile_nt(const float* __restrict__ A,
                                              const float* __restrict__ W,
                                              const float* __restrict__ bias,
                                              float* __restrict__ C,
                                              int M, int N, int K)
{
    __shared__ float As[16][128];
    __shared__ float Ws[16][128];

    const int tid = threadIdx.x;
    const int r0 = blockIdx.y * 128;
    const int c0 = blockIdx.x * 128;
    const int ty = tid >> 4;   // 0..15
    const int tx = tid & 15;   // 0..15

    float acc[8][8];
#pragma unroll
    for (int i = 0; i < 8; ++i)
#pragma unroll
        for (int j = 0; j < 8; ++j) acc[i][j] = 0.f;

    for (int kt = 0; kt < K; kt += 16) {
        // Cooperative load: 512 float4 per operand, 2 per thread
#pragma unroll
        for (int it = 0; it < 2; ++it) {
            int idx = tid + it * 256;        // 0..511
            int row = idx >> 2;              // 0..127
            int k4  = idx & 3;               // 0..3 (float4 within 16-wide K slab)
            float4 va = *(const float4*)&A[(size_t)(r0 + row) * K + kt + k4 * 4];
            As[k4*4+0][row] = va.x; As[k4*4+1][row] = va.y;
            As[k4*4+2][row] = va.z; As[k4*4+3][row] = va.w;
            float4 vw = *(const float4*)&W[(size_t)(c0 + row) * K + kt + k4 * 4];
            Ws[k4*4+0][row] = vw.x; Ws[k4*4+1][row] = vw.y;
            Ws[k4*4+2][row] = vw.z; Ws[k4*4+3][row] = vw.w;
        }
        __syncthreads();

#pragma unroll
        for (int kk = 0; kk < 16; ++kk) {
            float a[8], b[8];
            *(float4*)&a[0] = *(const float4*)&As[kk][ty * 8];
            *(float4*)&a[4] = *(const float4*)&As[kk][ty * 8 + 4];
            *(float4*)&b[0] = *(const float4*)&Ws[kk][tx * 8];
            *(float4*)&b[4] = *(const float4*)&Ws[kk][tx * 8 + 4];
#pragma unroll
            for (int i = 0; i < 8; ++i)
#pragma unroll
                for (int j = 0; j < 8; ++j)
                    acc[i][j] = fmaf(a[i], b[j], acc[i][j]);
        }
        __syncthreads();
    }

    // Epilogue
#pragma unroll
    for (int i = 0; i < 8; ++i) {
        int row = r0 + ty * 8 + i;
#pragma unroll
        for (int j = 0; j < 8; j += 4) {
            int col = c0 + tx * 8 + j;
            float4 o;
            float b0 = bias ? bias[col + 0] : 0.f;
            float b1 = bias ? bias[col + 1] : 0.f;
            float b2 = bias ? bias[col + 2] : 0.f;
            float b3 = bias ? bias[col + 3] : 0.f;
            o.x = acc[i][j + 0] + b0;
            o.y = acc[i][j + 1] + b1;
            o.z = acc[i][j + 2] + b2;
            o.w = acc[i][j + 3] + b3;
            *(float4*)&C[(size_t)row * N + col] = o;
        }
    }
}

// Fused QKV projections: blockIdx.z selects which weight/output
__global__ __launch_bounds__(256) void qkv_kernel(const float* __restrict__ x,
                                                  const float* __restrict__ Wq,
                                                  const float* __restrict__ Wk,
                                                  const float* __restrict__ Wv)
{
    const float* W;
    float* out;
    if (blockIdx.z == 0)      { W = Wq; out = g_Q; }
    else if (blockIdx.z == 1) { W = Wk; out = g_K; }
    else                      { W = Wv; out = g_V; }
    sgemm_tile_nt(x, W, nullptr, out, MTOT, DD, DD);
}

// Output projection: ctx @ Wo.T + bo
__global__ __launch_bounds__(256) void out_kernel(const float* __restrict__ Wo,
                                                  const float* __restrict__ bo,
                                                  float* __restrict__ out)
{
    sgemm_tile_nt(g_C, Wo, bo, out, MTOT, DD, DD);
}

// ---------------------------------------------------------------------------
// Causal flash attention, fp32.
// grid: (S/64, H, B); block: 64 threads; one query row per thread.
// Online softmax in 16-key chunks keeps everything register-resident.
// ---------------------------------------------------------------------------
__global__ __launch_bounds__(64) void attn_kernel()
{
    __shared__ float Ks[64][64];
    __shared__ float Vs[64][64];

    const int tid  = threadIdx.x;
    const int bx   = blockIdx.x;           // query tile
    const int h    = blockIdx.y;
    const int b    = blockIdx.z;
    const int qrow = bx * 64 + tid;

    const size_t qbase = ((size_t)(b * SS + qrow)) * DD + h * HDIM;
    const float scale = 0.125f;            // 1/sqrt(64)

    float q[64];
#pragma unroll
    for (int d4 = 0; d4 < 16; ++d4) {
        float4 v = *(const float4*)&g_Q[qbase + d4 * 4];
        q[d4*4+0] = v.x * scale; q[d4*4+1] = v.y * scale;
        q[d4*4+2] = v.z * scale; q[d4*4+3] = v.w * scale;
    }

    float o[64];
#pragma unroll
    for (int d = 0; d < 64; ++d) o[d] = 0.f;
    float m = -1e30f, l = 0.f;

    const int nkb = bx + 1;
    for (int kb = 0; kb < nkb; ++kb) {
        const int jg0 = kb * 64;
        // Cooperative coalesced tile load: 16 float4 per thread per operand
        {
            const size_t tbase = ((size_t)(b * SS + jg0)) * DD + h * HDIM;
#pragma unroll
            for (int p = 0; p < 16; ++p) {
                int fidx = p * 64 + tid;     // 0..1023
                int row  = fidx >> 4;        // 0..63
                int c4   = fidx & 15;        // 0..15
                size_t gaddr = tbase + (size_t)row * DD + c4 * 4;
                *(float4*)&Ks[row][c4 * 4] = *(const float4*)&g_K[gaddr];
                *(float4*)&Vs[row][c4 * 4] = *(const float4*)&g_V[gaddr];
            }
        }
        __syncthreads();

        const bool diag = (kb == bx);
#pragma unroll 1
        for (int jc = 0; jc < 4; ++jc) {
            float s16[16];
            float mloc = -1e30f;
#pragma unroll
            for (int j = 0; j < 16; ++j) {
                const int jj = jc * 16 + j;
                float acc = 0.f;
#pragma unroll
                for (int d = 0; d < 64; ++d)
                    acc = fmaf(q[d], Ks[jj][d], acc);
                if (diag && (jg0 + jj > qrow)) acc = -1e30f;
                s16[j] = acc;
                mloc = fmaxf(mloc, acc);
            }
            float mnew = fmaxf(m, mloc);
            float corr = __expf(m - mnew);
            l *= corr;
#pragma unroll
            for (int d = 0; d < 64; ++d) o[d] *= corr;
#pragma unroll
            for (int j = 0; j < 16; ++j) {
                float p = __expf(s16[j] - mnew);
                l += p;
                const int jj = jc * 16 + j;
#pragma unroll
                for (int d = 0; d < 64; ++d)
                    o[d] = fmaf(p, Vs[jj][d], o[d]);
            }
            m = mnew;
        }
        __syncthreads();
    }

    const float inv = 1.f / l;
#pragma unroll
    for (int d4 = 0; d4 < 16; ++d4) {
        float4 v;
        v.x = o[d4*4+0] * inv; v.y = o[d4*4+1] * inv;
        v.z = o[d4*4+2] * inv; v.w = o[d4*4+3] * inv;
        *(float4*)&g_C[qbase + d4 * 4] = v;
    }
}

extern "C" void kernel_launch(void* const* d_in, const int* in_sizes, int n_in,
                              void* d_out, int out_size)
{
    const float* x  = (const float*)d_in[0];
    const float* Wq = (const float*)d_in[1];
    const float* Wk = (const float*)d_in[2];
    const float* Wv = (const float*)d_in[3];
    const float* Wo = (const float*)d_in[4];
    const float* bo = (const float*)d_in[5];
    float* out = (float*)d_out;

    (void)in_sizes; (void)n_in; (void)out_size;

    dim3 gemm_grid(DD / 128, MTOT / 128, 3);
    qkv_kernel<<<gemm_grid, 256>>>(x, Wq, Wk, Wv);

    dim3 attn_grid(SS / 64, HH, BB);
    attn_kernel<<<attn_grid, 64>>>();

    dim3 out_grid(DD / 128, MTOT / 128, 1);
    out_kernel<<<out_grid, 256>>>(Wo, bo, out);
}

// round 3
// speedup vs baseline: 2.9939x; 2.9939x over previous
#include <cuda_runtime.h>
#include <cuda_bf16.h>
#include <cstdint>
#include <cstddef>

#define BB 2
#define SS 2048
#define DD 1024
#define HH 16
#define HDIM 64
#define MTOT (BB*SS)   // 4096

typedef __nv_bfloat16 bf16;

// ---------------- device-global scratch (no allocs allowed) ----------------
__device__ bf16 g_xhi[MTOT*DD], g_xlo[MTOT*DD];
__device__ bf16 g_Wqhi[DD*DD], g_Wqlo[DD*DD];
__device__ bf16 g_Wkhi[DD*DD], g_Wklo[DD*DD];
__device__ bf16 g_Wvhi[DD*DD], g_Wvlo[DD*DD];
__device__ bf16 g_Wohi[DD*DD], g_Wolo[DD*DD];
// Q/K/V in [b][h][s][hd] layout, bf16 hi/lo (Q pre-scaled by 1/8)
__device__ bf16 g_Qhi[MTOT*DD], g_Qlo[MTOT*DD];
__device__ bf16 g_Khi[MTOT*DD], g_Klo[MTOT*DD];
__device__ bf16 g_Vhi[MTOT*DD], g_Vlo[MTOT*DD];
// ctx in [token][d] layout, bf16 hi/lo
__device__ bf16 g_Chi[MTOT*DD], g_Clo[MTOT*DD];

// ---------------- helpers ----------------
__device__ __forceinline__ uint32_t smem_u32(const void* p) {
    uint32_t a;
    asm("{ .reg .u64 t; cvta.to.shared.u64 t, %1; cvt.u32.u64 %0, t; }" : "=r"(a) : "l"(p));
    return a;
}
#define SWZ(o) ((uint32_t)(o) ^ ((((uint32_t)(o)) >> 3) & 0x70))

__device__ __forceinline__ void ldsm4(uint32_t* r, uint32_t a) {
    asm volatile("ldmatrix.sync.aligned.m8n8.x4.shared.b16 {%0,%1,%2,%3}, [%4];"
        : "=r"(r[0]), "=r"(r[1]), "=r"(r[2]), "=r"(r[3]) : "r"(a));
}
__device__ __forceinline__ void ldsm4t(uint32_t* r, uint32_t a) {
    asm volatile("ldmatrix.sync.aligned.m8n8.x4.trans.shared.b16 {%0,%1,%2,%3}, [%4];"
        : "=r"(r[0]), "=r"(r[1]), "=r"(r[2]), "=r"(r[3]) : "r"(a));
}
__device__ __forceinline__ void mma16816(float* c, const uint32_t* a, const uint32_t* b) {
    asm volatile("mma.sync.aligned.m16n8k16.row.col.f32.bf16.bf16.f32 "
        "{%0,%1,%2,%3}, {%4,%5,%6,%7}, {%8,%9}, {%0,%1,%2,%3};"
        : "+f"(c[0]), "+f"(c[1]), "+f"(c[2]), "+f"(c[3])
        : "r"(a[0]), "r"(a[1]), "r"(a[2]), "r"(a[3]), "r"(b[0]), "r"(b[1]));
}

// split two floats into packed bf16x2 hi and lo registers
__device__ __forceinline__ void pk_split(uint32_t& hi, uint32_t& lo, float x, float y) {
    bf16 hx = __float2bfloat16_rn(x), hy = __float2bfloat16_rn(y);
    __nv_bfloat162 ph; ph.x = hx; ph.y = hy;
    float rx = x - __bfloat162float(hx), ry = y - __bfloat162float(hy);
    __nv_bfloat162 pl; pl.x = __float2bfloat16_rn(rx); pl.y = __float2bfloat16_rn(ry);
    hi = *(uint32_t*)&ph;
    lo = *(uint32_t*)&pl;
}
__device__ __forceinline__ void split_store(bf16* hi, bf16* lo, size_t off, float v0, float v1) {
    uint32_t h, l;
    pk_split(h, l, v0, v1);
    *(uint32_t*)(hi + off) = h;
    *(uint32_t*)(lo + off) = l;
}

// ---------------- fp32 -> bf16 hi/lo split ----------------
__global__ __launch_bounds__(256) void split_kernel(const float* __restrict__ s,
                                                    bf16* __restrict__ hi,
                                                    bf16* __restrict__ lo, int n4)
{
    int i = blockIdx.x * blockDim.x + threadIdx.x;
    if (i >= n4) return;
    float4 v = ((const float4*)s)[i];
    uint32_t h0, l0, h1, l1;
    pk_split(h0, l0, v.x, v.y);
    pk_split(h1, l1, v.z, v.w);
    ((uint32_t*)hi)[i*2+0] = h0; ((uint32_t*)hi)[i*2+1] = h1;
    ((uint32_t*)lo)[i*2+0] = l0; ((uint32_t*)lo)[i*2+1] = l1;
}

// ---------------- HMMA split-bf16 GEMM core ----------------
// C[128,128] tile of A[M,1024] @ W[1024,1024]^T.  512 threads, warps 4x4,
// warp tile 32x32 (mt2 x nt4).  Smem: 4 operand tiles 128x64 bf16, SW128.
#define SM_AHI 0u
#define SM_ALO 16384u
#define SM_BHI 32768u
#define SM_BLO 49152u
#define GEMM_SMEM 65536

__device__ __forceinline__ void hgemm_core(const bf16* __restrict__ Ahi, const bf16* __restrict__ Alo,
                                           const bf16* __restrict__ Bhi, const bf16* __restrict__ Blo,
                                           int r0, int c0, float acc[2][4][4])
{
    extern __shared__ char smem[];
    const uint32_t sb = smem_u32(smem);
    const int tid = threadIdx.x, lane = tid & 31, wid = tid >> 5;
    const int wr = wid >> 2, wc = wid & 3;

#pragma unroll
    for (int i = 0; i < 2; ++i)
#pragma unroll
        for (int j = 0; j < 4; ++j)
#pragma unroll
            for (int e = 0; e < 4; ++e) acc[i][j][e] = 0.f;

    const int arow  = 32*wr + (lane & 15);
    const int acol8 = (lane >> 4) * 8;
    const int brow  = 32*wc + (lane & 7) + ((lane & 16) >> 1);
    const int bk8   = lane & 8;

    for (int ch = 0; ch < 16; ++ch) {
        const int kt = ch * 64;
        __syncthreads();
#pragma unroll
        for (int i = 0; i < 2; ++i) {
            int idx = tid + i*512;            // 0..1023
            int row = idx >> 3, c16 = idx & 7;
            uint32_t so = SWZ(row*128 + c16*16);
            size_t ga = (size_t)(r0+row)*DD + kt + c16*8;
            size_t gb = (size_t)(c0+row)*DD + kt + c16*8;
            *(uint4*)(smem + SM_AHI + so) = *(const uint4*)(Ahi + ga);
            *(uint4*)(smem + SM_ALO + so) = *(const uint4*)(Alo + ga);
            *(uint4*)(smem + SM_BHI + so) = *(const uint4*)(Bhi + gb);
            *(uint4*)(smem + SM_BLO + so) = *(const uint4*)(Blo + gb);
        }
        __syncthreads();

#pragma unroll
        for (int t = 0; t < 4; ++t) {
            uint32_t fahi[2][4], falo[2][4], fbhi[2][4], fblo[2][4];
#pragma unroll
            for (int mt = 0; mt < 2; ++mt) {
                uint32_t ao = SWZ((arow + 16*mt)*128 + (t*16 + acol8)*2);
                ldsm4(fahi[mt], sb + SM_AHI + ao);
                ldsm4(falo[mt], sb + SM_ALO + ao);
            }
#pragma unroll
            for (int p = 0; p < 2; ++p) {
                uint32_t bo = SWZ((brow + 16*p)*128 + (t*16 + bk8)*2);
                ldsm4(fbhi[p], sb + SM_BHI + bo);
                ldsm4(fblo[p], sb + SM_BLO + bo);
            }
#pragma unroll
            for (int mt = 0; mt < 2; ++mt)
#pragma unroll
                for (int p = 0; p < 2; ++p) {
                    mma16816(acc[mt][2*p],   fahi[mt], &fbhi[p][0]);
                    mma16816(acc[mt][2*p+1], fahi[mt], &fbhi[p][2]);
                    mma16816(acc[mt][2*p],   fahi[mt], &fblo[p][0]);
                    mma16816(acc[mt][2*p+1], fahi[mt], &fblo[p][2]);
                    mma16816(acc[mt][2*p],   falo[mt], &fbhi[p][0]);
                    mma16816(acc[mt][2*p+1], falo[mt], &fbhi[p][2]);
                }
        }
    }
}

// QKV projection: z selects weight/output; writes bf16 hi/lo in head layout.
__global__ __launch_bounds__(512) void qkv_hmma()
{
    const bf16 *Bhi, *Blo;
    bf16 *Ohi, *Olo;
    float scale;
    if (blockIdx.z == 0)      { Bhi = g_Wqhi; Blo = g_Wqlo; Ohi = g_Qhi; Olo = g_Qlo; scale = 0.125f; }
    else if (blockIdx.z == 1) { Bhi = g_Wkhi; Blo = g_Wklo; Ohi = g_Khi; Olo = g_Klo; scale = 1.f; }
    else                      { Bhi = g_Wvhi; Blo = g_Wvlo; Ohi = g_Vhi; Olo = g_Vlo; scale = 1.f; }

    float acc[2][4][4];
    const int r0 = blockIdx.y * 128, c0 = blockIdx.x * 128;
    hgemm_core(g_xhi, g_xlo, Bhi, Blo, r0, c0, acc);

    const int tid = threadIdx.x, lane = tid & 31, wid = tid >> 5;
    const int wr = wid >> 2, wc = wid & 3;
#pragma unroll
    for (int mt = 0; mt < 2; ++mt)
#pragma unroll
        for (int nt = 0; nt < 4; ++nt) {
            int rg = r0 + 32*wr + 16*mt + (lane >> 2);
            int cg = c0 + 32*wc + 8*nt + 2*(lane & 3);
            int bidx = rg >> 11, s = rg & 2047, h = cg >> 6, hd = cg & 63;
            size_t base = (((size_t)bidx*HH + h)*SS + s)*HDIM + hd;
            split_store(Ohi, Olo, base, acc[mt][nt][0]*scale, acc[mt][nt][1]*scale);
            split_store(Ohi, Olo, base + 8*HDIM, acc[mt][nt][2]*scale, acc[mt][nt][3]*scale);
        }
}

// Output projection: ctx @ Wo^T + bo, fp32 out.
__global__ __launch_bounds__(512) void out_hmma(float* __restrict__ out,
                                                const float* __restrict__ bo)
{
    float acc[2][4][4];
    const int r0 = blockIdx.y * 128, c0 = blockIdx.x * 128;
    hgemm_core(g_Chi, g_Clo, g_Wohi, g_Wolo, r0, c0, acc);

    const int tid = threadIdx.x, lane = tid & 31, wid = tid >> 5;
    const int wr = wid >> 2, wc = wid & 3;
#pragma unroll
    for (int mt = 0; mt < 2; ++mt)
#pragma unroll
        for (int nt = 0; nt < 4; ++nt) {
            int rg = r0 + 32*wr + 16*mt + (lane >> 2);
            int cg = c0 + 32*wc + 8*nt + 2*(lane & 3);
            float b0v = bo[cg], b1v = bo[cg+1];
            float2 o0 = make_float2(acc[mt][nt][0] + b0v, acc[mt][nt][1] + b1v);
            float2 o1 = make_float2(acc[mt][nt][2] + b0v, acc[mt][nt][3] + b1v);
            *(float2*)&out[(size_t)rg * DD + cg] = o0;
            *(float2*)&out[(size_t)(rg+8) * DD + cg] = o1;
        }
}

// ---------------- HMMA causal flash attention ----------------
// CTA: 128 q-rows, 8 warps x 16 rows. kv tiles of 64 keys.
#define AQHI 0u
#define AQLO 16384u
#define AKHI 32768u
#define AKLO 40960u
#define AVHI 49152u
#define AVLO 57344u
#define ATTN_SMEM 65536

__global__ __launch_bounds__(256) void attn_hmma()
{
    extern __shared__ char smem[];
    const uint32_t sb = smem_u32(smem);
    const int tid = threadIdx.x, lane = tid & 31, wid = tid >> 5;
    const int qb = blockIdx.x, h = blockIdx.y, b = blockIdx.z;
    const int q0 = qb * 128;
    const size_t hb = ((size_t)b*HH + h) * SS;   // token base for this (b,h)

    // load Q tile (128 x 64, hi/lo)
#pragma unroll
    for (int i = 0; i < 4; ++i) {
        int idx = tid + i*256;               // 0..1023
        int row = idx >> 3, c16 = idx & 7;
        uint32_t so = SWZ(row*128 + c16*16);
        size_t g = (hb + q0 + row)*HDIM + c16*8;
        *(uint4*)(smem + AQHI + so) = *(const uint4*)(g_Qhi + g);
        *(uint4*)(smem + AQLO + so) = *(const uint4*)(g_Qlo + g);
    }
    __syncthreads();

    uint32_t fqhi[4][4], fqlo[4][4];
#pragma unroll
    for (int t = 0; t < 4; ++t) {
        uint32_t ao = SWZ((16*wid + (lane & 15))*128 + (t*16 + (lane >> 4)*8)*2);
        ldsm4(fqhi[t], sb + AQHI + ao);
        ldsm4(fqlo[t], sb + AQLO + ao);
    }

    float oacc[8][4];
#pragma unroll
    for (int nt = 0; nt < 8; ++nt)
#pragma unroll
        for (int e = 0; e < 4; ++e) oacc[nt][e] = 0.f;
    float m0 = -1e30f, m1 = -1e30f, l0 = 0.f, l1 = 0.f;

    const int rbase = q0 + 16*wid + (lane >> 2);
    const int ntiles = 2*qb + 2;

    for (int kt = 0; kt < ntiles; ++kt) {
        const int j0 = kt * 64;
        __syncthreads();
#pragma unroll
        for (int i = 0; i < 2; ++i) {
            int idx = tid + i*256;           // 0..511
            int row = idx >> 3, c16 = idx & 7;
            uint32_t so = SWZ(row*128 + c16*16);
            size_t g = (hb + j0 + row)*HDIM + c16*8;
            *(uint4*)(smem + AKHI + so) = *(const uint4*)(g_Khi + g);
            *(uint4*)(smem + AKLO + so) = *(const uint4*)(g_Klo + g);
            *(uint4*)(smem + AVHI + so) = *(const uint4*)(g_Vhi + g);
            *(uint4*)(smem + AVLO + so) = *(const uint4*)(g_Vlo + g);
        }
        __syncthreads();

        // S = Q K^T (3-pass split)
        float sacc[8][4];
#pragma unroll
        for (int nt = 0; nt < 8; ++nt)
#pragma unroll
            for (int e = 0; e < 4; ++e) sacc[nt][e] = 0.f;

#pragma unroll
        for (int t = 0; t < 4; ++t)
#pragma unroll
            for (int p = 0; p < 4; ++p) {
                uint32_t bo_ = SWZ((16*p + (lane & 7) + ((lane & 16) >> 1))*128 + (t*16 + (lane & 8))*2);
                uint32_t kbh[4], kbl[4];
                ldsm4(kbh, sb + AKHI + bo_);
                ldsm4(kbl, sb + AKLO + bo_);
                mma16816(sacc[2*p],   fqhi[t], &kbh[0]);
                mma16816(sacc[2*p+1], fqhi[t], &kbh[2]);
                mma16816(sacc[2*p],   fqhi[t], &kbl[0]);
                mma16816(sacc[2*p+1], fqhi[t], &kbl[2]);
                mma16816(sacc[2*p],   fqlo[t], &kbh[0]);
                mma16816(sacc[2*p+1], fqlo[t], &kbh[2]);
            }

        // causal mask (only when the tile crosses the diagonal for this thread's rows)
        if (j0 + 63 > rbase) {
#pragma unroll
            for (int nt = 0; nt < 8; ++nt) {
                int cg = j0 + 8*nt + 2*(lane & 3);
                if (cg   > rbase)     sacc[nt][0] = -1e30f;
                if (cg+1 > rbase)     sacc[nt][1] = -1e30f;
                if (cg   > rbase + 8) sacc[nt][2] = -1e30f;
                if (cg+1 > rbase + 8) sacc[nt][3] = -1e30f;
            }
        }

        // online softmax (rows rbase, rbase+8)
        float mx0 = -1e30f, mx1 = -1e30f;
#pragma unroll
        for (int nt = 0; nt < 8; ++nt) {
            mx0 = fmaxf(mx0, fmaxf(sacc[nt][0], sacc[nt][1]));
            mx1 = fmaxf(mx1, fmaxf(sacc[nt][2], sacc[nt][3]));
        }
        mx0 = fmaxf(mx0, __shfl_xor_sync(0xffffffffu, mx0, 1));
        mx0 = fmaxf(mx0, __shfl_xor_sync(0xffffffffu, mx0, 2));
        mx1 = fmaxf(mx1, __shfl_xor_sync(0xffffffffu, mx1, 1));
        mx1 = fmaxf(mx1, __shfl_xor_sync(0xffffffffu, mx1, 2));
        const float mn0 = fmaxf(m0, mx0), mn1 = fmaxf(m1, mx1);
        const float c0f = __expf(m0 - mn0), c1f = __expf(m1 - mn1);
        float s0 = 0.f, s1 = 0.f;
#pragma unroll
        for (int nt = 0; nt < 8; ++nt) {
            sacc[nt][0] = __expf(sacc[nt][0] - mn0); s0 += sacc[nt][0];
            sacc[nt][1] = __expf(sacc[nt][1] - mn0); s0 += sacc[nt][1];
            sacc[nt][2] = __expf(sacc[nt][2] - mn1); s1 += sacc[nt][2];
            sacc[nt][3] = __expf(sacc[nt][3] - mn1); s1 += sacc[nt][3];
        }
        s0 += __shfl_xor_sync(0xffffffffu, s0, 1);
        s0 += __shfl_xor_sync(0xffffffffu, s0, 2);
        s1 += __shfl_xor_sync(0xffffffffu, s1, 1);
        s1 += __shfl_xor_sync(0xffffffffu, s1, 2);
        l0 = l0 * c0f + s0;
        l1 = l1 * c1f + s1;
        m0 = mn0; m1 = mn1;
#pragma unroll
        for (int nt = 0; nt < 8; ++nt) {
            oacc[nt][0] *= c0f; oacc[nt][1] *= c0f;
            oacc[nt][2] *= c1f; oacc[nt][3] *= c1f;
        }

        // O += P V  (3-pass split; P frags built in registers)
#pragma unroll
        for (int t = 0; t < 4; ++t) {
            uint32_t pahi[4], palo[4];
            pk_split(pahi[0], palo[0], sacc[2*t][0],   sacc[2*t][1]);
            pk_split(pahi[1], palo[1], sacc[2*t][2],   sacc[2*t][3]);
            pk_split(pahi[2], palo[2], sacc[2*t+1][0], sacc[2*t+1][1]);
            pk_split(pahi[3], palo[3], sacc[2*t+1][2], sacc[2*t+1][3]);
#pragma unroll
            for (int p = 0; p < 4; ++p) {
                uint32_t vo = SWZ((t*16 + (lane & 15))*128 + (16*p + ((lane >> 1) & 8))*2);
                uint32_t vbh[4], vbl[4];
                ldsm4t(vbh, sb + AVHI + vo);
                ldsm4t(vbl, sb + AVLO + vo);
                mma16816(oacc[2*p],   pahi, &vbh[0]);
                mma16816(oacc[2*p+1], pahi, &vbh[2]);
                mma16816(oacc[2*p],   pahi, &vbl[0]);
                mma16816(oacc[2*p+1], pahi, &vbl[2]);
                mma16816(oacc[2*p],   palo, &vbh[0]);
                mma16816(oacc[2*p+1], palo, &vbh[2]);
            }
        }
    }

    // epilogue: normalize, write ctx as bf16 hi/lo [token][d]
    const float inv0 = 1.f / l0, inv1 = 1.f / l1;
    const size_t tok = ((size_t)b*SS + rbase)*DD + h*HDIM;
#pragma unroll
    for (int nt = 0; nt < 8; ++nt) {
        int col = 8*nt + 2*(lane & 3);
        split_store(g_Chi, g_Clo, tok + col,          oacc[nt][0]*inv0, oacc[nt][1]*inv0);
        split_store(g_Chi, g_Clo, tok + 8*DD + col,   oacc[nt][2]*inv1, oacc[nt][3]*inv1);
    }
}

// ---------------- launch ----------------
extern "C" void kernel_launch(void* const* d_in, const int* in_sizes, int n_in,
                              void* d_out, int out_size)
{
    const float* x  = (const float*)d_in[0];
    const float* Wq = (const float*)d_in[1];
    const float* Wk = (const float*)d_in[2];
    const float* Wv = (const float*)d_in[3];
    const float* Wo = (const float*)d_in[4];
    const float* bo = (const float*)d_in[5];
    float* out = (float*)d_out;
    (void)in_sizes; (void)n_in; (void)out_size;

    static bool attr_done = false;
    if (!attr_done) {
        cudaFuncSetAttribute(qkv_hmma, cudaFuncAttributeMaxDynamicSharedMemorySize, GEMM_SMEM);
        cudaFuncSetAttribute(out_hmma, cudaFuncAttributeMaxDynamicSharedMemorySize, GEMM_SMEM);
        cudaFuncSetAttribute(attn_hmma, cudaFuncAttributeMaxDynamicSharedMemorySize, ATTN_SMEM);
        attr_done = true;
    }

    bf16 *xhi, *xlo, *wqh, *wql, *wkh, *wkl, *wvh, *wvl, *woh, *wol;
    cudaGetSymbolAddress((void**)&xhi, g_xhi); cudaGetSymbolAddress((void**)&xlo, g_xlo);
    cudaGetSymbolAddress((void**)&wqh, g_Wqhi); cudaGetSymbolAddress((void**)&wql, g_Wqlo);
    cudaGetSymbolAddress((void**)&wkh, g_Wkhi); cudaGetSymbolAddress((void**)&wkl, g_Wklo);
    cudaGetSymbolAddress((void**)&wvh, g_Wvhi); cudaGetSymbolAddress((void**)&wvl, g_Wvlo);
    cudaGetSymbolAddress((void**)&woh, g_Wohi); cudaGetSymbolAddress((void**)&wol, g_Wolo);

    split_kernel<<<(MTOT*DD/4 + 255)/256, 256>>>(x,  xhi, xlo, MTOT*DD/4);
    split_kernel<<<(DD*DD/4   + 255)/256, 256>>>(Wq, wqh, wql, DD*DD/4);
    split_kernel<<<(DD*DD/4   + 255)/256, 256>>>(Wk, wkh, wkl, DD*DD/4);
    split_kernel<<<(DD*DD/4   + 255)/256, 256>>>(Wv, wvh, wvl, DD*DD/4);
    split_kernel<<<(DD*DD/4   + 255)/256, 256>>>(Wo, woh, wol, DD*DD/4);

    dim3 qkv_grid(DD/128, MTOT/128, 3);
    qkv_hmma<<<qkv_grid, 512, GEMM_SMEM>>>();

    dim3 attn_grid(SS/128, HH, BB);
    attn_hmma<<<attn_grid, 256, ATTN_SMEM>>>();

    dim3 out_grid(DD/128, MTOT/128, 1);
    out_hmma<<<out_grid, 512, GEMM_SMEM>>>(out, bo);
}

// round 4
// speedup vs baseline: 3.5247x; 1.1773x over previous
#include <cuda_runtime.h>
#include <cuda_bf16.h>
#include <cstdint>
#include <cstddef>

#define BB 2
#define SS 2048
#define DD 1024
#define HH 16
#define HDIM 64
#define MTOT (BB*SS)   // 4096

typedef __nv_bfloat16 bf16;

// ---------------- device-global scratch (no allocs allowed) ----------------
__device__ bf16 g_xhi[MTOT*DD], g_xlo[MTOT*DD];
__device__ bf16 g_Wqhi[DD*DD], g_Wqlo[DD*DD];
__device__ bf16 g_Wkhi[DD*DD], g_Wklo[DD*DD];
__device__ bf16 g_Wvhi[DD*DD], g_Wvlo[DD*DD];
__device__ bf16 g_Wohi[DD*DD], g_Wolo[DD*DD];
// Q/K/V in [b][h][s][hd] layout, bf16 hi/lo (Q pre-scaled by 1/8)
__device__ bf16 g_Qhi[MTOT*DD], g_Qlo[MTOT*DD];
__device__ bf16 g_Khi[MTOT*DD], g_Klo[MTOT*DD];
__device__ bf16 g_Vhi[MTOT*DD], g_Vlo[MTOT*DD];
// ctx in [token][d] layout, bf16 hi/lo
__device__ bf16 g_Chi[MTOT*DD], g_Clo[MTOT*DD];

// ---------------- helpers ----------------
__device__ __forceinline__ uint32_t smem_u32(const void* p) {
    uint32_t a;
    asm("{ .reg .u64 t; cvta.to.shared.u64 t, %1; cvt.u32.u64 %0, t; }" : "=r"(a) : "l"(p));
    return a;
}
#define SWZ(o) ((uint32_t)(o) ^ ((((uint32_t)(o)) >> 3) & 0x70))

__device__ __forceinline__ void cp16(uint32_t d, const void* s) {
    asm volatile("cp.async.cg.shared.global [%0], [%1], 16;" :: "r"(d), "l"(s));
}
#define CP_COMMIT() asm volatile("cp.async.commit_group;" ::: "memory")
#define CP_WAIT1()  asm volatile("cp.async.wait_group 1;" ::: "memory")
#define CP_WAIT0()  asm volatile("cp.async.wait_group 0;" ::: "memory")

__device__ __forceinline__ void ldsm4(uint32_t* r, uint32_t a) {
    asm volatile("ldmatrix.sync.aligned.m8n8.x4.shared.b16 {%0,%1,%2,%3}, [%4];"
        : "=r"(r[0]), "=r"(r[1]), "=r"(r[2]), "=r"(r[3]) : "r"(a));
}
__device__ __forceinline__ void ldsm4t(uint32_t* r, uint32_t a) {
    asm volatile("ldmatrix.sync.aligned.m8n8.x4.trans.shared.b16 {%0,%1,%2,%3}, [%4];"
        : "=r"(r[0]), "=r"(r[1]), "=r"(r[2]), "=r"(r[3]) : "r"(a));
}
__device__ __forceinline__ void mma16816(float* c, const uint32_t* a, const uint32_t* b) {
    asm volatile("mma.sync.aligned.m16n8k16.row.col.f32.bf16.bf16.f32 "
        "{%0,%1,%2,%3}, {%4,%5,%6,%7}, {%8,%9}, {%0,%1,%2,%3};"
        : "+f"(c[0]), "+f"(c[1]), "+f"(c[2]), "+f"(c[3])
        : "r"(a[0]), "r"(a[1]), "r"(a[2]), "r"(a[3]), "r"(b[0]), "r"(b[1]));
}

__device__ __forceinline__ void pk_split(uint32_t& hi, uint32_t& lo, float x, float y) {
    bf16 hx = __float2bfloat16_rn(x), hy = __float2bfloat16_rn(y);
    __nv_bfloat162 ph; ph.x = hx; ph.y = hy;
    float rx = x - __bfloat162float(hx), ry = y - __bfloat162float(hy);
    __nv_bfloat162 pl; pl.x = __float2bfloat16_rn(rx); pl.y = __float2bfloat16_rn(ry);
    hi = *(uint32_t*)&ph;
    lo = *(uint32_t*)&pl;
}
__device__ __forceinline__ void split_store(bf16* hi, bf16* lo, size_t off, float v0, float v1) {
    uint32_t h, l;
    pk_split(h, l, v0, v1);
    *(uint32_t*)(hi + off) = h;
    *(uint32_t*)(lo + off) = l;
}

// ---------------- fp32 -> bf16 hi/lo split ----------------
__global__ __launch_bounds__(256) void split_kernel(const float* __restrict__ s,
                                                    bf16* __restrict__ hi,
                                                    bf16* __restrict__ lo, int n4)
{
    int i = blockIdx.x * blockDim.x + threadIdx.x;
    if (i >= n4) return;
    float4 v = ((const float4*)s)[i];
    uint32_t h0, l0, h1, l1;
    pk_split(h0, l0, v.x, v.y);
    pk_split(h1, l1, v.z, v.w);
    ((uint32_t*)hi)[i*2+0] = h0; ((uint32_t*)hi)[i*2+1] = h1;
    ((uint32_t*)lo)[i*2+0] = l0; ((uint32_t*)lo)[i*2+1] = l1;
}

// ---------------- HMMA split-bf16 GEMM core (2-stage cp.async pipeline) -----
// C[128,128] tile of A[M,1024] @ W[1024,1024]^T.  512 threads, warps 4x4,
// warp tile 32x32.  Per stage: 4 operand tiles 128x64 bf16 (16KB each).
#define SM_AHI 0u
#define SM_ALO 16384u
#define SM_BHI 32768u
#define SM_BLO 49152u
#define STG    65536u
#define GEMM_SMEM (2*65536)

__device__ __forceinline__ void gemm_load(uint32_t sb, int st,
    const bf16* __restrict__ Ahi, const bf16* __restrict__ Alo,
    const bf16* __restrict__ Bhi, const bf16* __restrict__ Blo,
    int r0, int c0, int kt, int tid)
{
    const uint32_t base = sb + (uint32_t)st * STG;
#pragma unroll
    for (int i = 0; i < 2; ++i) {
        int idx = tid + i*512;                // 0..1023
        int row = idx >> 3, c16 = idx & 7;
        uint32_t so = SWZ(row*128 + c16*16);
        size_t ga = (size_t)(r0+row)*DD + kt + c16*8;
        size_t gb = (size_t)(c0+row)*DD + kt + c16*8;
        cp16(base + SM_AHI + so, Ahi + ga);
        cp16(base + SM_ALO + so, Alo + ga);
        cp16(base + SM_BHI + so, Bhi + gb);
        cp16(base + SM_BLO + so, Blo + gb);
    }
}

__device__ __forceinline__ void hgemm_core(const bf16* __restrict__ Ahi, const bf16* __restrict__ Alo,
                                           const bf16* __restrict__ Bhi, const bf16* __restrict__ Blo,
                                           int r0, int c0, float acc[2][4][4])
{
    extern __shared__ char smem[];
    const uint32_t sb = smem_u32(smem);
    const int tid = threadIdx.x, lane = tid & 31, wid = tid >> 5;
    const int wr = wid >> 2, wc = wid & 3;

#pragma unroll
    for (int i = 0; i < 2; ++i)
#pragma unroll
        for (int j = 0; j < 4; ++j)
#pragma unroll
            for (int e = 0; e < 4; ++e) acc[i][j][e] = 0.f;

    const int arow  = 32*wr + (lane & 15);
    const int acol8 = (lane >> 4) * 8;
    const int brow  = 32*wc + (lane & 7) + ((lane & 16) >> 1);
    const int bk8   = lane & 8;

    gemm_load(sb, 0, Ahi, Alo, Bhi, Blo, r0, c0, 0, tid);
    CP_COMMIT();

    for (int ch = 0; ch < 16; ++ch) {
        if (ch < 15) {
            gemm_load(sb, (ch+1) & 1, Ahi, Alo, Bhi, Blo, r0, c0, (ch+1)*64, tid);
            CP_COMMIT();
            CP_WAIT1();
        } else {
            CP_WAIT0();
        }
        __syncthreads();

        const uint32_t cb = sb + (uint32_t)(ch & 1) * STG;
#pragma unroll
        for (int t = 0; t < 4; ++t) {
            uint32_t fahi[2][4], falo[2][4], fbhi[2][4], fblo[2][4];
#pragma unroll
            for (int mt = 0; mt < 2; ++mt) {
                uint32_t ao = SWZ((arow + 16*mt)*128 + (t*16 + acol8)*2);
                ldsm4(fahi[mt], cb + SM_AHI + ao);
                ldsm4(falo[mt], cb + SM_ALO + ao);
            }
#pragma unroll
            for (int p = 0; p < 2; ++p) {
                uint32_t bo = SWZ((brow + 16*p)*128 + (t*16 + bk8)*2);
                ldsm4(fbhi[p], cb + SM_BHI + bo);
                ldsm4(fblo[p], cb + SM_BLO + bo);
            }
#pragma unroll
            for (int mt = 0; mt < 2; ++mt)
#pragma unroll
                for (int p = 0; p < 2; ++p) {
                    mma16816(acc[mt][2*p],   fahi[mt], &fbhi[p][0]);
                    mma16816(acc[mt][2*p+1], fahi[mt], &fbhi[p][2]);
                    mma16816(acc[mt][2*p],   fahi[mt], &fblo[p][0]);
                    mma16816(acc[mt][2*p+1], fahi[mt], &fblo[p][2]);
                    mma16816(acc[mt][2*p],   falo[mt], &fbhi[p][0]);
                    mma16816(acc[mt][2*p+1], falo[mt], &fbhi[p][2]);
                }
        }
        __syncthreads();
    }
}

// QKV projection: z selects weight/output; writes bf16 hi/lo in head layout.
__global__ __launch_bounds__(512) void qkv_hmma()
{
    const bf16 *Bhi, *Blo;
    bf16 *Ohi, *Olo;
    float scale;
    if (blockIdx.z == 0)      { Bhi = g_Wqhi; Blo = g_Wqlo; Ohi = g_Qhi; Olo = g_Qlo; scale = 0.125f; }
    else if (blockIdx.z == 1) { Bhi = g_Wkhi; Blo = g_Wklo; Ohi = g_Khi; Olo = g_Klo; scale = 1.f; }
    else                      { Bhi = g_Wvhi; Blo = g_Wvlo; Ohi = g_Vhi; Olo = g_Vlo; scale = 1.f; }

    float acc[2][4][4];
    const int r0 = blockIdx.y * 128, c0 = blockIdx.x * 128;
    hgemm_core(g_xhi, g_xlo, Bhi, Blo, r0, c0, acc);

    const int tid = threadIdx.x, lane = tid & 31, wid = tid >> 5;
    const int wr = wid >> 2, wc = wid & 3;
#pragma unroll
    for (int mt = 0; mt < 2; ++mt)
#pragma unroll
        for (int nt = 0; nt < 4; ++nt) {
            int rg = r0 + 32*wr + 16*mt + (lane >> 2);
            int cg = c0 + 32*wc + 8*nt + 2*(lane & 3);
            int bidx = rg >> 11, s = rg & 2047, h = cg >> 6, hd = cg & 63;
            size_t base = (((size_t)bidx*HH + h)*SS + s)*HDIM + hd;
            split_store(Ohi, Olo, base, acc[mt][nt][0]*scale, acc[mt][nt][1]*scale);
            split_store(Ohi, Olo, base + 8*HDIM, acc[mt][nt][2]*scale, acc[mt][nt][3]*scale);
        }
}

// Output projection: ctx @ Wo^T + bo, fp32 out.
__global__ __launch_bounds__(512) void out_hmma(float* __restrict__ out,
                                                const float* __restrict__ bo)
{
    float acc[2][4][4];
    const int r0 = blockIdx.y * 128, c0 = blockIdx.x * 128;
    hgemm_core(g_Chi, g_Clo, g_Wohi, g_Wolo, r0, c0, acc);

    const int tid = threadIdx.x, lane = tid & 31, wid = tid >> 5;
    const int wr = wid >> 2, wc = wid & 3;
#pragma unroll
    for (int mt = 0; mt < 2; ++mt)
#pragma unroll
        for (int nt = 0; nt < 4; ++nt) {
            int rg = r0 + 32*wr + 16*mt + (lane >> 2);
            int cg = c0 + 32*wc + 8*nt + 2*(lane & 3);
            float b0v = bo[cg], b1v = bo[cg+1];
            float2 o0 = make_float2(acc[mt][nt][0] + b0v, acc[mt][nt][1] + b1v);
            float2 o1 = make_float2(acc[mt][nt][2] + b0v, acc[mt][nt][3] + b1v);
            *(float2*)&out[(size_t)rg * DD + cg] = o0;
            *(float2*)&out[(size_t)(rg+8) * DD + cg] = o1;
        }
}

// ---------------- HMMA causal flash attention (2-stage cp.async) -----------
// CTA: 128 q-rows, 8 warps x 16 rows. kv tiles of 64 keys.
// Smem: Q hi/lo 32KB + 2 KV stages x 32KB = 96KB -> 2 CTAs/SM.
#define AQHI 0u
#define AQLO 16384u
#define AKV  32768u
#define KSTG 32768u
#define AKHI 0u
#define AKLO 8192u
#define AVHI 16384u
#define AVLO 24576u
#define ATTN_SMEM (32768 + 2*32768)

__device__ __forceinline__ void attn_load_kv(uint32_t sb, int st, size_t hb, int j0, int tid)
{
    const uint32_t base = sb + AKV + (uint32_t)st * KSTG;
#pragma unroll
    for (int i = 0; i < 2; ++i) {
        int idx = tid + i*256;               // 0..511
        int row = idx >> 3, c16 = idx & 7;
        uint32_t so = SWZ(row*128 + c16*16);
        size_t g = (hb + j0 + row)*HDIM + c16*8;
        cp16(base + AKHI + so, g_Khi + g);
        cp16(base + AKLO + so, g_Klo + g);
        cp16(base + AVHI + so, g_Vhi + g);
        cp16(base + AVLO + so, g_Vlo + g);
    }
}

__global__ __launch_bounds__(256, 2) void attn_hmma()
{
    extern __shared__ char smem[];
    const uint32_t sb = smem_u32(smem);
    const int tid = threadIdx.x, lane = tid & 31, wid = tid >> 5;
    const int qb = blockIdx.x, h = blockIdx.y, b = blockIdx.z;
    const int q0 = qb * 128;
    const size_t hb = ((size_t)b*HH + h) * SS;

    // group 0: Q tile (128x64 hi/lo) + KV tile 0
#pragma unroll
    for (int i = 0; i < 4; ++i) {
        int idx = tid + i*256;               // 0..1023
        int row = idx >> 3, c16 = idx & 7;
        uint32_t so = SWZ(row*128 + c16*16);
        size_t g = (hb + q0 + row)*HDIM + c16*8;
        cp16(sb + AQHI + so, g_Qhi + g);
        cp16(sb + AQLO + so, g_Qlo + g);
    }
    attn_load_kv(sb, 0, hb, 0, tid);
    CP_COMMIT();

    uint32_t fqhi[4][4], fqlo[4][4];
    float oacc[8][4];
#pragma unroll
    for (int nt = 0; nt < 8; ++nt)
#pragma unroll
        for (int e = 0; e < 4; ++e) oacc[nt][e] = 0.f;
    float m0 = -1e30f, m1 = -1e30f, l0 = 0.f, l1 = 0.f;

    const int rbase = q0 + 16*wid + (lane >> 2);
    const int ntiles = 2*qb + 2;

    for (int kt = 0; kt < ntiles; ++kt) {
        const int j0 = kt * 64;
        if (kt + 1 < ntiles) {
            attn_load_kv(sb, (kt+1) & 1, hb, j0 + 64, tid);
            CP_COMMIT();
            CP_WAIT1();
        } else {
            CP_WAIT0();
        }
        __syncthreads();

        if (kt == 0) {
#pragma unroll
            for (int t = 0; t < 4; ++t) {
                uint32_t ao = SWZ((16*wid + (lane & 15))*128 + (t*16 + (lane >> 4)*8)*2);
                ldsm4(fqhi[t], sb + AQHI + ao);
                ldsm4(fqlo[t], sb + AQLO + ao);
            }
        }

        const uint32_t kb = sb + AKV + (uint32_t)(kt & 1) * KSTG;

        // S = Q K^T (3-pass split)
        float sacc[8][4];
#pragma unroll
        for (int nt = 0; nt < 8; ++nt)
#pragma unroll
            for (int e = 0; e < 4; ++e) sacc[nt][e] = 0.f;

#pragma unroll
        for (int t = 0; t < 4; ++t)
#pragma unroll
            for (int p = 0; p < 4; ++p) {
                uint32_t bo_ = SWZ((16*p + (lane & 7) + ((lane & 16) >> 1))*128 + (t*16 + (lane & 8))*2);
                uint32_t kbh[4], kbl[4];
                ldsm4(kbh, kb + AKHI + bo_);
                ldsm4(kbl, kb + AKLO + bo_);
                mma16816(sacc[2*p],   fqhi[t], &kbh[0]);
                mma16816(sacc[2*p+1], fqhi[t], &kbh[2]);
                mma16816(sacc[2*p],   fqhi[t], &kbl[0]);
                mma16816(sacc[2*p+1], fqhi[t], &kbl[2]);
                mma16816(sacc[2*p],   fqlo[t], &kbh[0]);
                mma16816(sacc[2*p+1], fqlo[t], &kbh[2]);
            }

        if (j0 + 63 > rbase) {
#pragma unroll
            for (int nt = 0; nt < 8; ++nt) {
                int cg = j0 + 8*nt + 2*(lane & 3);
                if (cg   > rbase)     sacc[nt][0] = -1e30f;
                if (cg+1 > rbase)     sacc[nt][1] = -1e30f;
                if (cg   > rbase + 8) sacc[nt][2] = -1e30f;
                if (cg+1 > rbase + 8) sacc[nt][3] = -1e30f;
            }
        }

        float mx0 = -1e30f, mx1 = -1e30f;
#pragma unroll
        for (int nt = 0; nt < 8; ++nt) {
            mx0 = fmaxf(mx0, fmaxf(sacc[nt][0], sacc[nt][1]));
            mx1 = fmaxf(mx1, fmaxf(sacc[nt][2], sacc[nt][3]));
        }
        mx0 = fmaxf(mx0, __shfl_xor_sync(0xffffffffu, mx0, 1));
        mx0 = fmaxf(mx0, __shfl_xor_sync(0xffffffffu, mx0, 2));
        mx1 = fmaxf(mx1, __shfl_xor_sync(0xffffffffu, mx1, 1));
        mx1 = fmaxf(mx1, __shfl_xor_sync(0xffffffffu, mx1, 2));
        const float mn0 = fmaxf(m0, mx0), mn1 = fmaxf(m1, mx1);
        const float c0f = __expf(m0 - mn0), c1f = __expf(m1 - mn1);
        float s0 = 0.f, s1 = 0.f;
#pragma unroll
        for (int nt = 0; nt < 8; ++nt) {
            sacc[nt][0] = __expf(sacc[nt][0] - mn0); s0 += sacc[nt][0];
            sacc[nt][1] = __expf(sacc[nt][1] - mn0); s0 += sacc[nt][1];
            sacc[nt][2] = __expf(sacc[nt][2] - mn1); s1 += sacc[nt][2];
            sacc[nt][3] = __expf(sacc[nt][3] - mn1); s1 += sacc[nt][3];
        }
        s0 += __shfl_xor_sync(0xffffffffu, s0, 1);
        s0 += __shfl_xor_sync(0xffffffffu, s0, 2);
        s1 += __shfl_xor_sync(0xffffffffu, s1, 1);
        s1 += __shfl_xor_sync(0xffffffffu, s1, 2);
        l0 = l0 * c0f + s0;
        l1 = l1 * c1f + s1;
        m0 = mn0; m1 = mn1;
#pragma unroll
        for (int nt = 0; nt < 8; ++nt) {
            oacc[nt][0] *= c0f; oacc[nt][1] *= c0f;
            oacc[nt][2] *= c1f; oacc[nt][3] *= c1f;
        }

        // O += P V  (3-pass split; P frags in registers)
#pragma unroll
        for (int t = 0; t < 4; ++t) {
            uint32_t pahi[4], palo[4];
            pk_split(pahi[0], palo[0], sacc[2*t][0],   sacc[2*t][1]);
            pk_split(pahi[1], palo[1], sacc[2*t][2],   sacc[2*t][3]);
            pk_split(pahi[2], palo[2], sacc[2*t+1][0], sacc[2*t+1][1]);
            pk_split(pahi[3], palo[3], sacc[2*t+1][2], sacc[2*t+1][3]);
#pragma unroll
            for (int p = 0; p < 4; ++p) {
                uint32_t vo = SWZ((t*16 + (lane & 15))*128 + (16*p + ((lane >> 1) & 8))*2);
                uint32_t vbh[4], vbl[4];
                ldsm4t(vbh, kb + AVHI + vo);
                ldsm4t(vbl, kb + AVLO + vo);
                mma16816(oacc[2*p],   pahi, &vbh[0]);
                mma16816(oacc[2*p+1], pahi, &vbh[2]);
                mma16816(oacc[2*p],   pahi, &vbl[0]);
                mma16816(oacc[2*p+1], pahi, &vbl[2]);
                mma16816(oacc[2*p],   palo, &vbh[0]);
                mma16816(oacc[2*p+1], palo, &vbh[2]);
            }
        }
        __syncthreads();
    }

    const float inv0 = 1.f / l0, inv1 = 1.f / l1;
    const size_t tok = ((size_t)b*SS + rbase)*DD + h*HDIM;
#pragma unroll
    for (int nt = 0; nt < 8; ++nt) {
        int col = 8*nt + 2*(lane & 3);
        split_store(g_Chi, g_Clo, tok + col,        oacc[nt][0]*inv0, oacc[nt][1]*inv0);
        split_store(g_Chi, g_Clo, tok + 8*DD + col, oacc[nt][2]*inv1, oacc[nt][3]*inv1);
    }
}

// ---------------- launch ----------------
extern "C" void kernel_launch(void* const* d_in, const int* in_sizes, int n_in,
                              void* d_out, int out_size)
{
    const float* x  = (const float*)d_in[0];
    const float* Wq = (const float*)d_in[1];
    const float* Wk = (const float*)d_in[2];
    const float* Wv = (const float*)d_in[3];
    const float* Wo = (const float*)d_in[4];
    const float* bo = (const float*)d_in[5];
    float* out = (float*)d_out;
    (void)in_sizes; (void)n_in; (void)out_size;

    static bool attr_done = false;
    if (!attr_done) {
        cudaFuncSetAttribute(qkv_hmma, cudaFuncAttributeMaxDynamicSharedMemorySize, GEMM_SMEM);
        cudaFuncSetAttribute(out_hmma, cudaFuncAttributeMaxDynamicSharedMemorySize, GEMM_SMEM);
        cudaFuncSetAttribute(attn_hmma, cudaFuncAttributeMaxDynamicSharedMemorySize, ATTN_SMEM);
        attr_done = true;
    }

    bf16 *xhi, *xlo, *wqh, *wql, *wkh, *wkl, *wvh, *wvl, *woh, *wol;
    cudaGetSymbolAddress((void**)&xhi, g_xhi); cudaGetSymbolAddress((void**)&xlo, g_xlo);
    cudaGetSymbolAddress((void**)&wqh, g_Wqhi); cudaGetSymbolAddress((void**)&wql, g_Wqlo);
    cudaGetSymbolAddress((void**)&wkh, g_Wkhi); cudaGetSymbolAddress((void**)&wkl, g_Wklo);
    cudaGetSymbolAddress((void**)&wvh, g_Wvhi); cudaGetSymbolAddress((void**)&wvl, g_Wvlo);
    cudaGetSymbolAddress((void**)&woh, g_Wohi); cudaGetSymbolAddress((void**)&wol, g_Wolo);

    split_kernel<<<(MTOT*DD/4 + 255)/256, 256>>>(x,  xhi, xlo, MTOT*DD/4);
    split_kernel<<<(DD*DD/4   + 255)/256, 256>>>(Wq, wqh, wql, DD*DD/4);
    split_kernel<<<(DD*DD/4   + 255)/256, 256>>>(Wk, wkh, wkl, DD*DD/4);
    split_kernel<<<(DD*DD/4   + 255)/256, 256>>>(Wv, wvh, wvl, DD*DD/4);
    split_kernel<<<(DD*DD/4   + 255)/256, 256>>>(Wo, woh, wol, DD*DD/4);

    dim3 qkv_grid(DD/128, MTOT/128, 3);
    qkv_hmma<<<qkv_grid, 512, GEMM_SMEM>>>();

    dim3 attn_grid(SS/128, HH, BB);
    attn_hmma<<<attn_grid, 256, ATTN_SMEM>>>();

    dim3 out_grid(DD/128, MTOT/128, 1);
    out_hmma<<<out_grid, 512, GEMM_SMEM>>>(out, bo);
}

// round 5
// speedup vs baseline: 3.6994x; 1.0496x over previous
#include <cuda_runtime.h>
#include <cuda_bf16.h>
#include <cstdint>
#include <cstddef>

#define BB 2
#define SS 2048
#define DD 1024
#define HH 16
#define HDIM 64
#define MTOT (BB*SS)   // 4096

typedef __nv_bfloat16 bf16;

// ---------------- device-global scratch ----------------
__device__ bf16 g_xhi[MTOT*DD], g_xlo[MTOT*DD];
__device__ bf16 g_Wqhi[DD*DD], g_Wqlo[DD*DD];
__device__ bf16 g_Wkhi[DD*DD], g_Wklo[DD*DD];
__device__ bf16 g_Wvhi[DD*DD], g_Wvlo[DD*DD];
__device__ bf16 g_Wohi[DD*DD], g_Wolo[DD*DD];
__device__ bf16 g_Qhi[MTOT*DD], g_Qlo[MTOT*DD];
__device__ bf16 g_Khi[MTOT*DD], g_Klo[MTOT*DD];
__device__ bf16 g_Vhi[MTOT*DD], g_Vlo[MTOT*DD];
__device__ bf16 g_Chi[MTOT*DD], g_Clo[MTOT*DD];

// ---------------- helpers ----------------
__device__ __forceinline__ uint32_t smem_u32(const void* p) {
    uint32_t a;
    asm("{ .reg .u64 t; cvta.to.shared.u64 t, %1; cvt.u32.u64 %0, t; }" : "=r"(a) : "l"(p));
    return a;
}
#define SWZ(o) ((uint32_t)(o) ^ ((((uint32_t)(o)) >> 3) & 0x70))

__device__ __forceinline__ void cp16(uint32_t d, const void* s) {
    asm volatile("cp.async.cg.shared.global [%0], [%1], 16;" :: "r"(d), "l"(s));
}
#define CP_COMMIT() asm volatile("cp.async.commit_group;" ::: "memory")
#define CP_WAIT1()  asm volatile("cp.async.wait_group 1;" ::: "memory")
#define CP_WAIT0()  asm volatile("cp.async.wait_group 0;" ::: "memory")

__device__ __forceinline__ void ldsm4(uint32_t* r, uint32_t a) {
    asm volatile("ldmatrix.sync.aligned.m8n8.x4.shared.b16 {%0,%1,%2,%3}, [%4];"
        : "=r"(r[0]), "=r"(r[1]), "=r"(r[2]), "=r"(r[3]) : "r"(a));
}
__device__ __forceinline__ void ldsm4t(uint32_t* r, uint32_t a) {
    asm volatile("ldmatrix.sync.aligned.m8n8.x4.trans.shared.b16 {%0,%1,%2,%3}, [%4];"
        : "=r"(r[0]), "=r"(r[1]), "=r"(r[2]), "=r"(r[3]) : "r"(a));
}
__device__ __forceinline__ void mma16816(float* c, const uint32_t* a, const uint32_t* b) {
    asm volatile("mma.sync.aligned.m16n8k16.row.col.f32.bf16.bf16.f32 "
        "{%0,%1,%2,%3}, {%4,%5,%6,%7}, {%8,%9}, {%0,%1,%2,%3};"
        : "+f"(c[0]), "+f"(c[1]), "+f"(c[2]), "+f"(c[3])
        : "r"(a[0]), "r"(a[1]), "r"(a[2]), "r"(a[3]), "r"(b[0]), "r"(b[1]));
}

__device__ __forceinline__ void pk_split(uint32_t& hi, uint32_t& lo, float x, float y) {
    bf16 hx = __float2bfloat16_rn(x), hy = __float2bfloat16_rn(y);
    __nv_bfloat162 ph; ph.x = hx; ph.y = hy;
    float rx = x - __bfloat162float(hx), ry = y - __bfloat162float(hy);
    __nv_bfloat162 pl; pl.x = __float2bfloat16_rn(rx); pl.y = __float2bfloat16_rn(ry);
    hi = *(uint32_t*)&ph;
    lo = *(uint32_t*)&pl;
}
__device__ __forceinline__ void split_store(bf16* hi, bf16* lo, size_t off, float v0, float v1) {
    uint32_t h, l;
    pk_split(h, l, v0, v1);
    *(uint32_t*)(hi + off) = h;
    *(uint32_t*)(lo + off) = l;
}

// ---------------- fp32 -> bf16 hi/lo split ----------------
__global__ __launch_bounds__(256) void split_kernel(const float* __restrict__ s,
                                                    bf16* __restrict__ hi,
                                                    bf16* __restrict__ lo, int n4)
{
    int i = blockIdx.x * blockDim.x + threadIdx.x;
    if (i >= n4) return;
    float4 v = ((const float4*)s)[i];
    uint32_t h0, l0, h1, l1;
    pk_split(h0, l0, v.x, v.y);
    pk_split(h1, l1, v.z, v.w);
    ((uint32_t*)hi)[i*2+0] = h0; ((uint32_t*)hi)[i*2+1] = h1;
    ((uint32_t*)lo)[i*2+0] = l0; ((uint32_t*)lo)[i*2+1] = l1;
}

// ---------------- HMMA split-bf16 GEMM core (2-stage cp.async) --------------
// CTA tile 256x128, 512 threads, warps 4(row)x4(col), warp tile 64x32.
#define SM_AHI 0u
#define SM_ALO 32768u
#define SM_BHI 65536u
#define SM_BLO 81920u
#define STG    98304u
#define GEMM_SMEM (2*98304)

__device__ __forceinline__ void gemm_load(uint32_t sb, int st,
    const bf16* __restrict__ Ahi, const bf16* __restrict__ Alo,
    const bf16* __restrict__ Bhi, const bf16* __restrict__ Blo,
    int r0, int c0, int kt, int tid)
{
    const uint32_t base = sb + (uint32_t)st * STG;
#pragma unroll
    for (int i = 0; i < 4; ++i) {
        int idx = tid + i*512;                // 0..2047
        int row = idx >> 3, c16 = idx & 7;
        uint32_t so = SWZ(row*128 + c16*16);
        size_t ga = (size_t)(r0+row)*DD + kt + c16*8;
        cp16(base + SM_AHI + so, Ahi + ga);
        cp16(base + SM_ALO + so, Alo + ga);
    }
#pragma unroll
    for (int i = 0; i < 2; ++i) {
        int idx = tid + i*512;                // 0..1023
        int row = idx >> 3, c16 = idx & 7;
        uint32_t so = SWZ(row*128 + c16*16);
        size_t gb = (size_t)(c0+row)*DD + kt + c16*8;
        cp16(base + SM_BHI + so, Bhi + gb);
        cp16(base + SM_BLO + so, Blo + gb);
    }
}

__device__ __forceinline__ void hgemm_core(const bf16* __restrict__ Ahi, const bf16* __restrict__ Alo,
                                           const bf16* __restrict__ Bhi, const bf16* __restrict__ Blo,
                                           int r0, int c0, float acc[4][4][4])
{
    extern __shared__ char smem[];
    const uint32_t sb = smem_u32(smem);
    const int tid = threadIdx.x, lane = tid & 31, wid = tid >> 5;
    const int wr = wid >> 2, wc = wid & 3;

#pragma unroll
    for (int i = 0; i < 4; ++i)
#pragma unroll
        for (int j = 0; j < 4; ++j)
#pragma unroll
            for (int e = 0; e < 4; ++e) acc[i][j][e] = 0.f;

    const int arow  = 64*wr + (lane & 15);
    const int acol8 = (lane >> 4) * 8;
    const int brow  = 32*wc + (lane & 7) + ((lane & 16) >> 1);
    const int bk8   = lane & 8;

    gemm_load(sb, 0, Ahi, Alo, Bhi, Blo, r0, c0, 0, tid);
    CP_COMMIT();

    for (int ch = 0; ch < 16; ++ch) {
        if (ch < 15) {
            gemm_load(sb, (ch+1) & 1, Ahi, Alo, Bhi, Blo, r0, c0, (ch+1)*64, tid);
            CP_COMMIT();
            CP_WAIT1();
        } else {
            CP_WAIT0();
        }
        __syncthreads();

        const uint32_t cb = sb + (uint32_t)(ch & 1) * STG;
#pragma unroll
        for (int t = 0; t < 4; ++t) {
            uint32_t fahi[4][4], falo[4][4], fbhi[2][4], fblo[2][4];
#pragma unroll
            for (int mt = 0; mt < 4; ++mt) {
                uint32_t ao = SWZ((arow + 16*mt)*128 + (t*16 + acol8)*2);
                ldsm4(fahi[mt], cb + SM_AHI + ao);
                ldsm4(falo[mt], cb + SM_ALO + ao);
            }
#pragma unroll
            for (int p = 0; p < 2; ++p) {
                uint32_t bo = SWZ((brow + 16*p)*128 + (t*16 + bk8)*2);
                ldsm4(fbhi[p], cb + SM_BHI + bo);
                ldsm4(fblo[p], cb + SM_BLO + bo);
            }
#pragma unroll
            for (int mt = 0; mt < 4; ++mt)
#pragma unroll
                for (int p = 0; p < 2; ++p) {
                    mma16816(acc[mt][2*p],   fahi[mt], &fbhi[p][0]);
                    mma16816(acc[mt][2*p+1], fahi[mt], &fbhi[p][2]);
                    mma16816(acc[mt][2*p],   fahi[mt], &fblo[p][0]);
                    mma16816(acc[mt][2*p+1], fahi[mt], &fblo[p][2]);
                    mma16816(acc[mt][2*p],   falo[mt], &fbhi[p][0]);
                    mma16816(acc[mt][2*p+1], falo[mt], &fbhi[p][2]);
                }
        }
        __syncthreads();
    }
}

__global__ __launch_bounds__(512) void qkv_hmma()
{
    const bf16 *Bhi, *Blo;
    bf16 *Ohi, *Olo;
    float scale;
    if (blockIdx.z == 0)      { Bhi = g_Wqhi; Blo = g_Wqlo; Ohi = g_Qhi; Olo = g_Qlo; scale = 0.125f; }
    else if (blockIdx.z == 1) { Bhi = g_Wkhi; Blo = g_Wklo; Ohi = g_Khi; Olo = g_Klo; scale = 1.f; }
    else                      { Bhi = g_Wvhi; Blo = g_Wvlo; Ohi = g_Vhi; Olo = g_Vlo; scale = 1.f; }

    float acc[4][4][4];
    const int r0 = blockIdx.y * 256, c0 = blockIdx.x * 128;
    hgemm_core(g_xhi, g_xlo, Bhi, Blo, r0, c0, acc);

    const int tid = threadIdx.x, lane = tid & 31, wid = tid >> 5;
    const int wr = wid >> 2, wc = wid & 3;
#pragma unroll
    for (int mt = 0; mt < 4; ++mt)
#pragma unroll
        for (int nt = 0; nt < 4; ++nt) {
            int rg = r0 + 64*wr + 16*mt + (lane >> 2);
            int cg = c0 + 32*wc + 8*nt + 2*(lane & 3);
            int bidx = rg >> 11, s = rg & 2047, h = cg >> 6, hd = cg & 63;
            size_t base = (((size_t)bidx*HH + h)*SS + s)*HDIM + hd;
            split_store(Ohi, Olo, base, acc[mt][nt][0]*scale, acc[mt][nt][1]*scale);
            split_store(Ohi, Olo, base + 8*HDIM, acc[mt][nt][2]*scale, acc[mt][nt][3]*scale);
        }
}

__global__ __launch_bounds__(512) void out_hmma(float* __restrict__ out,
                                                const float* __restrict__ bo)
{
    float acc[4][4][4];
    const int r0 = blockIdx.y * 256, c0 = blockIdx.x * 128;
    hgemm_core(g_Chi, g_Clo, g_Wohi, g_Wolo, r0, c0, acc);

    const int tid = threadIdx.x, lane = tid & 31, wid = tid >> 5;
    const int wr = wid >> 2, wc = wid & 3;
#pragma unroll
    for (int mt = 0; mt < 4; ++mt)
#pragma unroll
        for (int nt = 0; nt < 4; ++nt) {
            int rg = r0 + 64*wr + 16*mt + (lane >> 2);
            int cg = c0 + 32*wc + 8*nt + 2*(lane & 3);
            float b0v = bo[cg], b1v = bo[cg+1];
            float2 o0 = make_float2(acc[mt][nt][0] + b0v, acc[mt][nt][1] + b1v);
            float2 o1 = make_float2(acc[mt][nt][2] + b0v, acc[mt][nt][3] + b1v);
            *(float2*)&out[(size_t)rg * DD + cg] = o0;
            *(float2*)&out[(size_t)(rg+8) * DD + cg] = o1;
        }
}

// ---------------- HMMA causal flash attention ------------------------------
// CTA: 128 q-rows, 4 warps x 32 rows (mt=2), kv tiles of 64 keys, 2-stage.
#define AQHI 0u
#define AQLO 16384u
#define AKV  32768u
#define KSTG 32768u
#define AKHI 0u
#define AKLO 8192u
#define AVHI 16384u
#define AVLO 24576u
#define ATTN_SMEM (32768 + 2*32768)

__device__ __forceinline__ void attn_load_kv(uint32_t sb, int st, size_t hb, int j0, int tid)
{
    const uint32_t base = sb + AKV + (uint32_t)st * KSTG;
#pragma unroll
    for (int i = 0; i < 4; ++i) {
        int idx = tid + i*128;               // 0..511
        int row = idx >> 3, c16 = idx & 7;
        uint32_t so = SWZ(row*128 + c16*16);
        size_t g = (hb + j0 + row)*HDIM + c16*8;
        cp16(base + AKHI + so, g_Khi + g);
        cp16(base + AKLO + so, g_Klo + g);
        cp16(base + AVHI + so, g_Vhi + g);
        cp16(base + AVLO + so, g_Vlo + g);
    }
}

__global__ __launch_bounds__(128, 2) void attn_hmma()
{
    extern __shared__ char smem[];
    const uint32_t sb = smem_u32(smem);
    const int tid = threadIdx.x, lane = tid & 31, wid = tid >> 5;
    const int qb = gridDim.x - 1 - blockIdx.x;   // heavy CTAs first
    const int h = blockIdx.y, b = blockIdx.z;
    const int q0 = qb * 128;
    const size_t hb = ((size_t)b*HH + h) * SS;

    // group 0: Q tile (128x64 hi/lo) + KV tile 0
#pragma unroll
    for (int i = 0; i < 8; ++i) {
        int idx = tid + i*128;               // 0..1023
        int row = idx >> 3, c16 = idx & 7;
        uint32_t so = SWZ(row*128 + c16*16);
        size_t g = (hb + q0 + row)*HDIM + c16*8;
        cp16(sb + AQHI + so, g_Qhi + g);
        cp16(sb + AQLO + so, g_Qlo + g);
    }
    attn_load_kv(sb, 0, hb, 0, tid);
    CP_COMMIT();

    uint32_t fqhi[2][4][4];
    float oacc[2][8][4];
#pragma unroll
    for (int mt = 0; mt < 2; ++mt)
#pragma unroll
        for (int nt = 0; nt < 8; ++nt)
#pragma unroll
            for (int e = 0; e < 4; ++e) oacc[mt][nt][e] = 0.f;
    float m[2][2] = {{-1e30f,-1e30f},{-1e30f,-1e30f}};
    float l[2][2] = {{0.f,0.f},{0.f,0.f}};

    const int rb0 = q0 + 32*wid + (lane >> 2);   // row for mt, element 0/1; +8 for 2/3
    const int ntiles = 2*qb + 2;

    for (int kt = 0; kt < ntiles; ++kt) {
        const int j0 = kt * 64;
        if (kt + 1 < ntiles) {
            attn_load_kv(sb, (kt+1) & 1, hb, j0 + 64, tid);
            CP_COMMIT();
            CP_WAIT1();
        } else {
            CP_WAIT0();
        }
        __syncthreads();

        if (kt == 0) {
#pragma unroll
            for (int mt = 0; mt < 2; ++mt)
#pragma unroll
                for (int t = 0; t < 4; ++t) {
                    uint32_t ao = SWZ((32*wid + 16*mt + (lane & 15))*128 + (t*16 + (lane >> 4)*8)*2);
                    ldsm4(fqhi[mt][t], sb + AQHI + ao);
                }
        }

        const uint32_t kb = sb + AKV + (uint32_t)(kt & 1) * KSTG;

        // S = Q K^T (3-pass split; Q-lo reloaded from smem)
        float sacc[2][8][4];
#pragma unroll
        for (int mt = 0; mt < 2; ++mt)
#pragma unroll
            for (int nt = 0; nt < 8; ++nt)
#pragma unroll
                for (int e = 0; e < 4; ++e) sacc[mt][nt][e] = 0.f;

#pragma unroll
        for (int t = 0; t < 4; ++t) {
            uint32_t fql[2][4];
#pragma unroll
            for (int mt = 0; mt < 2; ++mt) {
                uint32_t ao = SWZ((32*wid + 16*mt + (lane & 15))*128 + (t*16 + (lane >> 4)*8)*2);
                ldsm4(fql[mt], sb + AQLO + ao);
            }
#pragma unroll
            for (int p = 0; p < 4; ++p) {
                uint32_t bo_ = SWZ((16*p + (lane & 7) + ((lane & 16) >> 1))*128 + (t*16 + (lane & 8))*2);
                uint32_t kbh[4], kbl[4];
                ldsm4(kbh, kb + AKHI + bo_);
                ldsm4(kbl, kb + AKLO + bo_);
#pragma unroll
                for (int mt = 0; mt < 2; ++mt) {
                    mma16816(sacc[mt][2*p],   fqhi[mt][t], &kbh[0]);
                    mma16816(sacc[mt][2*p+1], fqhi[mt][t], &kbh[2]);
                    mma16816(sacc[mt][2*p],   fqhi[mt][t], &kbl[0]);
                    mma16816(sacc[mt][2*p+1], fqhi[mt][t], &kbl[2]);
                    mma16816(sacc[mt][2*p],   fql[mt], &kbh[0]);
                    mma16816(sacc[mt][2*p+1], fql[mt], &kbh[2]);
                }
            }
        }

        // causal mask + online softmax per mt
#pragma unroll
        for (int mt = 0; mt < 2; ++mt) {
            const int rbase = rb0 + 16*mt;
            if (j0 + 63 > rbase) {
#pragma unroll
                for (int nt = 0; nt < 8; ++nt) {
                    int cg = j0 + 8*nt + 2*(lane & 3);
                    if (cg   > rbase)     sacc[mt][nt][0] = -1e30f;
                    if (cg+1 > rbase)     sacc[mt][nt][1] = -1e30f;
                    if (cg   > rbase + 8) sacc[mt][nt][2] = -1e30f;
                    if (cg+1 > rbase + 8) sacc[mt][nt][3] = -1e30f;
                }
            }
            float mx0 = -1e30f, mx1 = -1e30f;
#pragma unroll
            for (int nt = 0; nt < 8; ++nt) {
                mx0 = fmaxf(mx0, fmaxf(sacc[mt][nt][0], sacc[mt][nt][1]));
                mx1 = fmaxf(mx1, fmaxf(sacc[mt][nt][2], sacc[mt][nt][3]));
            }
            mx0 = fmaxf(mx0, __shfl_xor_sync(0xffffffffu, mx0, 1));
            mx0 = fmaxf(mx0, __shfl_xor_sync(0xffffffffu, mx0, 2));
            mx1 = fmaxf(mx1, __shfl_xor_sync(0xffffffffu, mx1, 1));
            mx1 = fmaxf(mx1, __shfl_xor_sync(0xffffffffu, mx1, 2));
            const float mn0 = fmaxf(m[mt][0], mx0), mn1 = fmaxf(m[mt][1], mx1);
            const float c0f = __expf(m[mt][0] - mn0), c1f = __expf(m[mt][1] - mn1);
            float s0 = 0.f, s1 = 0.f;
#pragma unroll
            for (int nt = 0; nt < 8; ++nt) {
                sacc[mt][nt][0] = __expf(sacc[mt][nt][0] - mn0); s0 += sacc[mt][nt][0];
                sacc[mt][nt][1] = __expf(sacc[mt][nt][1] - mn0); s0 += sacc[mt][nt][1];
                sacc[mt][nt][2] = __expf(sacc[mt][nt][2] - mn1); s1 += sacc[mt][nt][2];
                sacc[mt][nt][3] = __expf(sacc[mt][nt][3] - mn1); s1 += sacc[mt][nt][3];
            }
            s0 += __shfl_xor_sync(0xffffffffu, s0, 1);
            s0 += __shfl_xor_sync(0xffffffffu, s0, 2);
            s1 += __shfl_xor_sync(0xffffffffu, s1, 1);
            s1 += __shfl_xor_sync(0xffffffffu, s1, 2);
            l[mt][0] = l[mt][0] * c0f + s0;
            l[mt][1] = l[mt][1] * c1f + s1;
            m[mt][0] = mn0; m[mt][1] = mn1;
#pragma unroll
            for (int nt = 0; nt < 8; ++nt) {
                oacc[mt][nt][0] *= c0f; oacc[mt][nt][1] *= c0f;
                oacc[mt][nt][2] *= c1f; oacc[mt][nt][3] *= c1f;
            }
        }

        // O += P V  (3-pass; V frags shared across mt)
#pragma unroll
        for (int kc = 0; kc < 4; ++kc) {
            uint32_t pahi[2][4], palo[2][4];
#pragma unroll
            for (int mt = 0; mt < 2; ++mt) {
                pk_split(pahi[mt][0], palo[mt][0], sacc[mt][2*kc][0],   sacc[mt][2*kc][1]);
                pk_split(pahi[mt][1], palo[mt][1], sacc[mt][2*kc][2],   sacc[mt][2*kc][3]);
                pk_split(pahi[mt][2], palo[mt][2], sacc[mt][2*kc+1][0], sacc[mt][2*kc+1][1]);
                pk_split(pahi[mt][3], palo[mt][3], sacc[mt][2*kc+1][2], sacc[mt][2*kc+1][3]);
            }
#pragma unroll
            for (int p = 0; p < 4; ++p) {
                uint32_t vo = SWZ((kc*16 + (lane & 15))*128 + (16*p + ((lane >> 1) & 8))*2);
                uint32_t vbh[4], vbl[4];
                ldsm4t(vbh, kb + AVHI + vo);
                ldsm4t(vbl, kb + AVLO + vo);
#pragma unroll
                for (int mt = 0; mt < 2; ++mt) {
                    mma16816(oacc[mt][2*p],   pahi[mt], &vbh[0]);
                    mma16816(oacc[mt][2*p+1], pahi[mt], &vbh[2]);
                    mma16816(oacc[mt][2*p],   pahi[mt], &vbl[0]);
                    mma16816(oacc[mt][2*p+1], pahi[mt], &vbl[2]);
                    mma16816(oacc[mt][2*p],   palo[mt], &vbh[0]);
                    mma16816(oacc[mt][2*p+1], palo[mt], &vbh[2]);
                }
            }
        }
        __syncthreads();
    }

    // epilogue
#pragma unroll
    for (int mt = 0; mt < 2; ++mt) {
        const float inv0 = 1.f / l[mt][0], inv1 = 1.f / l[mt][1];
        const size_t tok = ((size_t)b*SS + rb0 + 16*mt)*DD + h*HDIM;
#pragma unroll
        for (int nt = 0; nt < 8; ++nt) {
            int col = 8*nt + 2*(lane & 3);
            split_store(g_Chi, g_Clo, tok + col,        oacc[mt][nt][0]*inv0, oacc[mt][nt][1]*inv0);
            split_store(g_Chi, g_Clo, tok + 8*DD + col, oacc[mt][nt][2]*inv1, oacc[mt][nt][3]*inv1);
        }
    }
}

// ---------------- launch ----------------
extern "C" void kernel_launch(void* const* d_in, const int* in_sizes, int n_in,
                              void* d_out, int out_size)
{
    const float* x  = (const float*)d_in[0];
    const float* Wq = (const float*)d_in[1];
    const float* Wk = (const float*)d_in[2];
    const float* Wv = (const float*)d_in[3];
    const float* Wo = (const float*)d_in[4];
    const float* bo = (const float*)d_in[5];
    float* out = (float*)d_out;
    (void)in_sizes; (void)n_in; (void)out_size;

    static bool attr_done = false;
    if (!attr_done) {
        cudaFuncSetAttribute(qkv_hmma, cudaFuncAttributeMaxDynamicSharedMemorySize, GEMM_SMEM);
        cudaFuncSetAttribute(out_hmma, cudaFuncAttributeMaxDynamicSharedMemorySize, GEMM_SMEM);
        cudaFuncSetAttribute(attn_hmma, cudaFuncAttributeMaxDynamicSharedMemorySize, ATTN_SMEM);
        attr_done = true;
    }

    bf16 *xhi, *xlo, *wqh, *wql, *wkh, *wkl, *wvh, *wvl, *woh, *wol;
    cudaGetSymbolAddress((void**)&xhi, g_xhi); cudaGetSymbolAddress((void**)&xlo, g_xlo);
    cudaGetSymbolAddress((void**)&wqh, g_Wqhi); cudaGetSymbolAddress((void**)&wql, g_Wqlo);
    cudaGetSymbolAddress((void**)&wkh, g_Wkhi); cudaGetSymbolAddress((void**)&wkl, g_Wklo);
    cudaGetSymbolAddress((void**)&wvh, g_Wvhi); cudaGetSymbolAddress((void**)&wvl, g_Wvlo);
    cudaGetSymbolAddress((void**)&woh, g_Wohi); cudaGetSymbolAddress((void**)&wol, g_Wolo);

    split_kernel<<<(MTOT*DD/4 + 255)/256, 256>>>(x,  xhi, xlo, MTOT*DD/4);
    split_kernel<<<(DD*DD/4   + 255)/256, 256>>>(Wq, wqh, wql, DD*DD/4);
    split_kernel<<<(DD*DD/4   + 255)/256, 256>>>(Wk, wkh, wkl, DD*DD/4);
    split_kernel<<<(DD*DD/4   + 255)/256, 256>>>(Wv, wvh, wvl, DD*DD/4);
    split_kernel<<<(DD*DD/4   + 255)/256, 256>>>(Wo, woh, wol, DD*DD/4);

    dim3 qkv_grid(DD/128, MTOT/256, 3);
    qkv_hmma<<<qkv_grid, 512, GEMM_SMEM>>>();

    dim3 attn_grid(SS/128, HH, BB);
    attn_hmma<<<attn_grid, 128, ATTN_SMEM>>>();

    dim3 out_grid(DD/128, MTOT/256, 1);
    out_hmma<<<out_grid, 512, GEMM_SMEM>>>(out, bo);
}

// round 6
// speedup vs baseline: 3.7858x; 1.0234x over previous
#include <cuda_runtime.h>
#include <cuda_bf16.h>
#include <cstdint>
#include <cstddef>

#define BB 2
#define SS 2048
#define DD 1024
#define HH 16
#define HDIM 64
#define MTOT (BB*SS)   // 4096

typedef __nv_bfloat16 bf16;

// ---------------- device-global scratch ----------------
__device__ bf16 g_xhi[MTOT*DD], g_xlo[MTOT*DD];
__device__ bf16 g_Wqhi[DD*DD], g_Wqlo[DD*DD];
__device__ bf16 g_Wkhi[DD*DD], g_Wklo[DD*DD];
__device__ bf16 g_Wvhi[DD*DD], g_Wvlo[DD*DD];
__device__ bf16 g_Wohi[DD*DD], g_Wolo[DD*DD];
__device__ bf16 g_Qhi[MTOT*DD], g_Qlo[MTOT*DD];
__device__ bf16 g_Khi[MTOT*DD], g_Klo[MTOT*DD];
__device__ bf16 g_Vhi[MTOT*DD], g_Vlo[MTOT*DD];
__device__ bf16 g_Chi[MTOT*DD], g_Clo[MTOT*DD];

// ---------------- helpers ----------------
__device__ __forceinline__ uint32_t smem_u32(const void* p) {
    uint32_t a;
    asm("{ .reg .u64 t; cvta.to.shared.u64 t, %1; cvt.u32.u64 %0, t; }" : "=r"(a) : "l"(p));
    return a;
}
#define SWZ(o) ((uint32_t)(o) ^ ((((uint32_t)(o)) >> 3) & 0x70))

__device__ __forceinline__ void cp16(uint32_t d, const void* s) {
    asm volatile("cp.async.cg.shared.global [%0], [%1], 16;" :: "r"(d), "l"(s));
}
#define CP_COMMIT() asm volatile("cp.async.commit_group;" ::: "memory")
#define CP_WAIT1()  asm volatile("cp.async.wait_group 1;" ::: "memory")
#define CP_WAIT0()  asm volatile("cp.async.wait_group 0;" ::: "memory")

__device__ __forceinline__ void ldsm4(uint32_t* r, uint32_t a) {
    asm volatile("ldmatrix.sync.aligned.m8n8.x4.shared.b16 {%0,%1,%2,%3}, [%4];"
        : "=r"(r[0]), "=r"(r[1]), "=r"(r[2]), "=r"(r[3]) : "r"(a));
}
__device__ __forceinline__ void ldsm4t(uint32_t* r, uint32_t a) {
    asm volatile("ldmatrix.sync.aligned.m8n8.x4.trans.shared.b16 {%0,%1,%2,%3}, [%4];"
        : "=r"(r[0]), "=r"(r[1]), "=r"(r[2]), "=r"(r[3]) : "r"(a));
}
__device__ __forceinline__ void mma16816(float* c, const uint32_t* a, const uint32_t* b) {
    asm volatile("mma.sync.aligned.m16n8k16.row.col.f32.bf16.bf16.f32 "
        "{%0,%1,%2,%3}, {%4,%5,%6,%7}, {%8,%9}, {%0,%1,%2,%3};"
        : "+f"(c[0]), "+f"(c[1]), "+f"(c[2]), "+f"(c[3])
        : "r"(a[0]), "r"(a[1]), "r"(a[2]), "r"(a[3]), "r"(b[0]), "r"(b[1]));
}

__device__ __forceinline__ void pk_split(uint32_t& hi, uint32_t& lo, float x, float y) {
    bf16 hx = __float2bfloat16_rn(x), hy = __float2bfloat16_rn(y);
    __nv_bfloat162 ph; ph.x = hx; ph.y = hy;
    float rx = x - __bfloat162float(hx), ry = y - __bfloat162float(hy);
    __nv_bfloat162 pl; pl.x = __float2bfloat16_rn(rx); pl.y = __float2bfloat16_rn(ry);
    hi = *(uint32_t*)&ph;
    lo = *(uint32_t*)&pl;
}
__device__ __forceinline__ void split_store(bf16* hi, bf16* lo, size_t off, float v0, float v1) {
    uint32_t h, l;
    pk_split(h, l, v0, v1);
    *(uint32_t*)(hi + off) = h;
    *(uint32_t*)(lo + off) = l;
}

// ---------------- fused fp32 -> bf16 hi/lo split (all 5 tensors) ------------
#define XN4 (MTOT*DD/4)          // 1048576
#define WN4 (DD*DD/4)            // 262144  (= 1<<18)

__global__ __launch_bounds__(256) void split_all(const float* __restrict__ x,
                                                 const float* __restrict__ Wq,
                                                 const float* __restrict__ Wk,
                                                 const float* __restrict__ Wv,
                                                 const float* __restrict__ Wo)
{
    int i = blockIdx.x * blockDim.x + threadIdx.x;
    const float* s;
    bf16 *hi, *lo;
    int off;
    if (i < XN4) { s = x; hi = g_xhi; lo = g_xlo; off = i; }
    else {
        int j = i - XN4;
        int w = j >> 18;
        off = j & (WN4 - 1);
        if (w == 0)      { s = Wq; hi = g_Wqhi; lo = g_Wqlo; }
        else if (w == 1) { s = Wk; hi = g_Wkhi; lo = g_Wklo; }
        else if (w == 2) { s = Wv; hi = g_Wvhi; lo = g_Wvlo; }
        else             { s = Wo; hi = g_Wohi; lo = g_Wolo; }
    }
    float4 v = ((const float4*)s)[off];
    uint32_t h0, l0, h1, l1;
    pk_split(h0, l0, v.x, v.y);
    pk_split(h1, l1, v.z, v.w);
    ((uint32_t*)hi)[off*2+0] = h0; ((uint32_t*)hi)[off*2+1] = h1;
    ((uint32_t*)lo)[off*2+0] = l0; ((uint32_t*)lo)[off*2+1] = l1;
}

// ---------------- HMMA split-bf16 GEMM core (2-stage, 256 thr, 64x64 warp) --
// CTA tile 256x128, 8 warps as 4(row)x2(col), warp tile 64x64. No spills.
#define SM_AHI 0u
#define SM_ALO 32768u
#define SM_BHI 65536u
#define SM_BLO 81920u
#define STG    98304u
#define GEMM_SMEM (2*98304)

__device__ __forceinline__ void gemm_load(uint32_t sb, int st,
    const bf16* __restrict__ Ahi, const bf16* __restrict__ Alo,
    const bf16* __restrict__ Bhi, const bf16* __restrict__ Blo,
    int r0, int c0, int kt, int tid)
{
    const uint32_t base = sb + (uint32_t)st * STG;
#pragma unroll
    for (int i = 0; i < 8; ++i) {
        int idx = tid + i*256;                // 0..2047
        int row = idx >> 3, c16 = idx & 7;
        uint32_t so = SWZ(row*128 + c16*16);
        size_t ga = (size_t)(r0+row)*DD + kt + c16*8;
        cp16(base + SM_AHI + so, Ahi + ga);
        cp16(base + SM_ALO + so, Alo + ga);
    }
#pragma unroll
    for (int i = 0; i < 4; ++i) {
        int idx = tid + i*256;                // 0..1023
        int row = idx >> 3, c16 = idx & 7;
        uint32_t so = SWZ(row*128 + c16*16);
        size_t gb = (size_t)(c0+row)*DD + kt + c16*8;
        cp16(base + SM_BHI + so, Bhi + gb);
        cp16(base + SM_BLO + so, Blo + gb);
    }
}

__device__ __forceinline__ void hgemm_core(const bf16* __restrict__ Ahi, const bf16* __restrict__ Alo,
                                           const bf16* __restrict__ Bhi, const bf16* __restrict__ Blo,
                                           int r0, int c0, float acc[4][8][4])
{
    extern __shared__ char smem[];
    const uint32_t sb = smem_u32(smem);
    const int tid = threadIdx.x, lane = tid & 31, wid = tid >> 5;
    const int wr = wid >> 1, wc = wid & 1;

#pragma unroll
    for (int i = 0; i < 4; ++i)
#pragma unroll
        for (int j = 0; j < 8; ++j)
#pragma unroll
            for (int e = 0; e < 4; ++e) acc[i][j][e] = 0.f;

    const int arow  = 64*wr + (lane & 15);
    const int acol8 = (lane >> 4) * 8;
    const int brow  = 64*wc + (lane & 7) + ((lane & 16) >> 1);
    const int bk8   = lane & 8;

    gemm_load(sb, 0, Ahi, Alo, Bhi, Blo, r0, c0, 0, tid);
    CP_COMMIT();

    for (int ch = 0; ch < 16; ++ch) {
        if (ch < 15) {
            gemm_load(sb, (ch+1) & 1, Ahi, Alo, Bhi, Blo, r0, c0, (ch+1)*64, tid);
            CP_COMMIT();
            CP_WAIT1();
        } else {
            CP_WAIT0();
        }
        __syncthreads();

        const uint32_t cb = sb + (uint32_t)(ch & 1) * STG;
#pragma unroll
        for (int t = 0; t < 4; ++t) {
            uint32_t fahi[4][4], falo[4][4], fbhi[4][4], fblo[4][4];
#pragma unroll
            for (int mt = 0; mt < 4; ++mt) {
                uint32_t ao = SWZ((arow + 16*mt)*128 + (t*16 + acol8)*2);
                ldsm4(fahi[mt], cb + SM_AHI + ao);
                ldsm4(falo[mt], cb + SM_ALO + ao);
            }
#pragma unroll
            for (int p = 0; p < 4; ++p) {
                uint32_t bo = SWZ((brow + 16*p)*128 + (t*16 + bk8)*2);
                ldsm4(fbhi[p], cb + SM_BHI + bo);
                ldsm4(fblo[p], cb + SM_BLO + bo);
            }
#pragma unroll
            for (int mt = 0; mt < 4; ++mt)
#pragma unroll
                for (int p = 0; p < 4; ++p) {
                    mma16816(acc[mt][2*p],   fahi[mt], &fbhi[p][0]);
                    mma16816(acc[mt][2*p+1], fahi[mt], &fbhi[p][2]);
                    mma16816(acc[mt][2*p],   fahi[mt], &fblo[p][0]);
                    mma16816(acc[mt][2*p+1], fahi[mt], &fblo[p][2]);
                    mma16816(acc[mt][2*p],   falo[mt], &fbhi[p][0]);
                    mma16816(acc[mt][2*p+1], falo[mt], &fbhi[p][2]);
                }
        }
        __syncthreads();
    }
}

__global__ __launch_bounds__(256, 1) void qkv_hmma()
{
    const bf16 *Bhi, *Blo;
    bf16 *Ohi, *Olo;
    float scale;
    if (blockIdx.z == 0)      { Bhi = g_Wqhi; Blo = g_Wqlo; Ohi = g_Qhi; Olo = g_Qlo; scale = 0.125f; }
    else if (blockIdx.z == 1) { Bhi = g_Wkhi; Blo = g_Wklo; Ohi = g_Khi; Olo = g_Klo; scale = 1.f; }
    else                      { Bhi = g_Wvhi; Blo = g_Wvlo; Ohi = g_Vhi; Olo = g_Vlo; scale = 1.f; }

    float acc[4][8][4];
    const int r0 = blockIdx.y * 256, c0 = blockIdx.x * 128;
    hgemm_core(g_xhi, g_xlo, Bhi, Blo, r0, c0, acc);

    const int tid = threadIdx.x, lane = tid & 31, wid = tid >> 5;
    const int wr = wid >> 1, wc = wid & 1;
#pragma unroll
    for (int mt = 0; mt < 4; ++mt)
#pragma unroll
        for (int nt = 0; nt < 8; ++nt) {
            int rg = r0 + 64*wr + 16*mt + (lane >> 2);
            int cg = c0 + 64*wc + 8*nt + 2*(lane & 3);
            int bidx = rg >> 11, s = rg & 2047, h = cg >> 6, hd = cg & 63;
            size_t base = (((size_t)bidx*HH + h)*SS + s)*HDIM + hd;
            split_store(Ohi, Olo, base, acc[mt][nt][0]*scale, acc[mt][nt][1]*scale);
            split_store(Ohi, Olo, base + 8*HDIM, acc[mt][nt][2]*scale, acc[mt][nt][3]*scale);
        }
}

__global__ __launch_bounds__(256, 1) void out_hmma(float* __restrict__ out,
                                                   const float* __restrict__ bo)
{
    float acc[4][8][4];
    const int r0 = blockIdx.y * 256, c0 = blockIdx.x * 128;
    hgemm_core(g_Chi, g_Clo, g_Wohi, g_Wolo, r0, c0, acc);

    const int tid = threadIdx.x, lane = tid & 31, wid = tid >> 5;
    const int wr = wid >> 1, wc = wid & 1;
#pragma unroll
    for (int mt = 0; mt < 4; ++mt)
#pragma unroll
        for (int nt = 0; nt < 8; ++nt) {
            int rg = r0 + 64*wr + 16*mt + (lane >> 2);
            int cg = c0 + 64*wc + 8*nt + 2*(lane & 3);
            float b0v = bo[cg], b1v = bo[cg+1];
            float2 o0 = make_float2(acc[mt][nt][0] + b0v, acc[mt][nt][1] + b1v);
            float2 o1 = make_float2(acc[mt][nt][2] + b0v, acc[mt][nt][3] + b1v);
            *(float2*)&out[(size_t)rg * DD + cg] = o0;
            *(float2*)&out[(size_t)(rg+8) * DD + cg] = o1;
        }
}

// ---------------- HMMA causal flash attention ------------------------------
// CTA: 128 q-rows, 4 warps x 32 rows (mt=2), kv tiles of 64 keys, 2-stage.
#define AQHI 0u
#define AQLO 16384u
#define AKV  32768u
#define KSTG 32768u
#define AKHI 0u
#define AKLO 8192u
#define AVHI 16384u
#define AVLO 24576u
#define ATTN_SMEM (32768 + 2*32768)

__device__ __forceinline__ void attn_load_kv(uint32_t sb, int st, size_t hb, int j0, int tid)
{
    const uint32_t base = sb + AKV + (uint32_t)st * KSTG;
#pragma unroll
    for (int i = 0; i < 4; ++i) {
        int idx = tid + i*128;               // 0..511
        int row = idx >> 3, c16 = idx & 7;
        uint32_t so = SWZ(row*128 + c16*16);
        size_t g = (hb + j0 + row)*HDIM + c16*8;
        cp16(base + AKHI + so, g_Khi + g);
        cp16(base + AKLO + so, g_Klo + g);
        cp16(base + AVHI + so, g_Vhi + g);
        cp16(base + AVLO + so, g_Vlo + g);
    }
}

__global__ __launch_bounds__(128, 2) void attn_hmma()
{
    extern __shared__ char smem[];
    const uint32_t sb = smem_u32(smem);
    const int tid = threadIdx.x, lane = tid & 31, wid = tid >> 5;
    const int qb = gridDim.x - 1 - blockIdx.x;   // heavy CTAs first
    const int h = blockIdx.y, b = blockIdx.z;
    const int q0 = qb * 128;
    const size_t hb = ((size_t)b*HH + h) * SS;

#pragma unroll
    for (int i = 0; i < 8; ++i) {
        int idx = tid + i*128;               // 0..1023
        int row = idx >> 3, c16 = idx & 7;
        uint32_t so = SWZ(row*128 + c16*16);
        size_t g = (hb + q0 + row)*HDIM + c16*8;
        cp16(sb + AQHI + so, g_Qhi + g);
        cp16(sb + AQLO + so, g_Qlo + g);
    }
    attn_load_kv(sb, 0, hb, 0, tid);
    CP_COMMIT();

    uint32_t fqhi[2][4][4];
    float oacc[2][8][4];
#pragma unroll
    for (int mt = 0; mt < 2; ++mt)
#pragma unroll
        for (int nt = 0; nt < 8; ++nt)
#pragma unroll
            for (int e = 0; e < 4; ++e) oacc[mt][nt][e] = 0.f;
    float m[2][2] = {{-1e30f,-1e30f},{-1e30f,-1e30f}};
    float l[2][2] = {{0.f,0.f},{0.f,0.f}};

    const int rb0 = q0 + 32*wid + (lane >> 2);
    const int ntiles = 2*qb + 2;

    for (int kt = 0; kt < ntiles; ++kt) {
        const int j0 = kt * 64;
        if (kt + 1 < ntiles) {
            attn_load_kv(sb, (kt+1) & 1, hb, j0 + 64, tid);
            CP_COMMIT();
            CP_WAIT1();
        } else {
            CP_WAIT0();
        }
        __syncthreads();

        if (kt == 0) {
#pragma unroll
            for (int mt = 0; mt < 2; ++mt)
#pragma unroll
                for (int t = 0; t < 4; ++t) {
                    uint32_t ao = SWZ((32*wid + 16*mt + (lane & 15))*128 + (t*16 + (lane >> 4)*8)*2);
                    ldsm4(fqhi[mt][t], sb + AQHI + ao);
                }
        }

        const uint32_t kb = sb + AKV + (uint32_t)(kt & 1) * KSTG;

        float sacc[2][8][4];
#pragma unroll
        for (int mt = 0; mt < 2; ++mt)
#pragma unroll
            for (int nt = 0; nt < 8; ++nt)
#pragma unroll
                for (int e = 0; e < 4; ++e) sacc[mt][nt][e] = 0.f;

#pragma unroll
        for (int t = 0; t < 4; ++t) {
            uint32_t fql[2][4];
#pragma unroll
            for (int mt = 0; mt < 2; ++mt) {
                uint32_t ao = SWZ((32*wid + 16*mt + (lane & 15))*128 + (t*16 + (lane >> 4)*8)*2);
                ldsm4(fql[mt], sb + AQLO + ao);
            }
#pragma unroll
            for (int p = 0; p < 4; ++p) {
                uint32_t bo_ = SWZ((16*p + (lane & 7) + ((lane & 16) >> 1))*128 + (t*16 + (lane & 8))*2);
                uint32_t kbh[4], kbl[4];
                ldsm4(kbh, kb + AKHI + bo_);
                ldsm4(kbl, kb + AKLO + bo_);
#pragma unroll
                for (int mt = 0; mt < 2; ++mt) {
                    mma16816(sacc[mt][2*p],   fqhi[mt][t], &kbh[0]);
                    mma16816(sacc[mt][2*p+1], fqhi[mt][t], &kbh[2]);
                    mma16816(sacc[mt][2*p],   fqhi[mt][t], &kbl[0]);
                    mma16816(sacc[mt][2*p+1], fqhi[mt][t], &kbl[2]);
                    mma16816(sacc[mt][2*p],   fql[mt], &kbh[0]);
                    mma16816(sacc[mt][2*p+1], fql[mt], &kbh[2]);
                }
            }
        }

#pragma unroll
        for (int mt = 0; mt < 2; ++mt) {
            const int rbase = rb0 + 16*mt;
            if (j0 + 63 > rbase) {
#pragma unroll
                for (int nt = 0; nt < 8; ++nt) {
                    int cg = j0 + 8*nt + 2*(lane & 3);
                    if (cg   > rbase)     sacc[mt][nt][0] = -1e30f;
                    if (cg+1 > rbase)     sacc[mt][nt][1] = -1e30f;
                    if (cg   > rbase + 8) sacc[mt][nt][2] = -1e30f;
                    if (cg+1 > rbase + 8) sacc[mt][nt][3] = -1e30f;
                }
            }
            float mx0 = -1e30f, mx1 = -1e30f;
#pragma unroll
            for (int nt = 0; nt < 8; ++nt) {
                mx0 = fmaxf(mx0, fmaxf(sacc[mt][nt][0], sacc[mt][nt][1]));
                mx1 = fmaxf(mx1, fmaxf(sacc[mt][nt][2], sacc[mt][nt][3]));
            }
            mx0 = fmaxf(mx0, __shfl_xor_sync(0xffffffffu, mx0, 1));
            mx0 = fmaxf(mx0, __shfl_xor_sync(0xffffffffu, mx0, 2));
            mx1 = fmaxf(mx1, __shfl_xor_sync(0xffffffffu, mx1, 1));
            mx1 = fmaxf(mx1, __shfl_xor_sync(0xffffffffu, mx1, 2));
            const float mn0 = fmaxf(m[mt][0], mx0), mn1 = fmaxf(m[mt][1], mx1);
            const float c0f = __expf(m[mt][0] - mn0), c1f = __expf(m[mt][1] - mn1);
            float s0 = 0.f, s1 = 0.f;
#pragma unroll
            for (int nt = 0; nt < 8; ++nt) {
                sacc[mt][nt][0] = __expf(sacc[mt][nt][0] - mn0); s0 += sacc[mt][nt][0];
                sacc[mt][nt][1] = __expf(sacc[mt][nt][1] - mn0); s0 += sacc[mt][nt][1];
                sacc[mt][nt][2] = __expf(sacc[mt][nt][2] - mn1); s1 += sacc[mt][nt][2];
                sacc[mt][nt][3] = __expf(sacc[mt][nt][3] - mn1); s1 += sacc[mt][nt][3];
            }
            s0 += __shfl_xor_sync(0xffffffffu, s0, 1);
            s0 += __shfl_xor_sync(0xffffffffu, s0, 2);
            s1 += __shfl_xor_sync(0xffffffffu, s1, 1);
            s1 += __shfl_xor_sync(0xffffffffu, s1, 2);
            l[mt][0] = l[mt][0] * c0f + s0;
            l[mt][1] = l[mt][1] * c1f + s1;
            m[mt][0] = mn0; m[mt][1] = mn1;
#pragma unroll
            for (int nt = 0; nt < 8; ++nt) {
                oacc[mt][nt][0] *= c0f; oacc[mt][nt][1] *= c0f;
                oacc[mt][nt][2] *= c1f; oacc[mt][nt][3] *= c1f;
            }
        }

#pragma unroll
        for (int kc = 0; kc < 4; ++kc) {
            uint32_t pahi[2][4], palo[2][4];
#pragma unroll
            for (int mt = 0; mt < 2; ++mt) {
                pk_split(pahi[mt][0], palo[mt][0], sacc[mt][2*kc][0],   sacc[mt][2*kc][1]);
                pk_split(pahi[mt][1], palo[mt][1], sacc[mt][2*kc][2],   sacc[mt][2*kc][3]);
                pk_split(pahi[mt][2], palo[mt][2], sacc[mt][2*kc+1][0], sacc[mt][2*kc+1][1]);
                pk_split(pahi[mt][3], palo[mt][3], sacc[mt][2*kc+1][2], sacc[mt][2*kc+1][3]);
            }
#pragma unroll
            for (int p = 0; p < 4; ++p) {
                uint32_t vo = SWZ((kc*16 + (lane & 15))*128 + (16*p + ((lane >> 1) & 8))*2);
                uint32_t vbh[4], vbl[4];
                ldsm4t(vbh, kb + AVHI + vo);
                ldsm4t(vbl, kb + AVLO + vo);
#pragma unroll
                for (int mt = 0; mt < 2; ++mt) {
                    mma16816(oacc[mt][2*p],   pahi[mt], &vbh[0]);
                    mma16816(oacc[mt][2*p+1], pahi[mt], &vbh[2]);
                    mma16816(oacc[mt][2*p],   pahi[mt], &vbl[0]);
                    mma16816(oacc[mt][2*p+1], pahi[mt], &vbl[2]);
                    mma16816(oacc[mt][2*p],   palo[mt], &vbh[0]);
                    mma16816(oacc[mt][2*p+1], palo[mt], &vbh[2]);
                }
            }
        }
        __syncthreads();
    }

#pragma unroll
    for (int mt = 0; mt < 2; ++mt) {
        const float inv0 = 1.f / l[mt][0], inv1 = 1.f / l[mt][1];
        const size_t tok = ((size_t)b*SS + rb0 + 16*mt)*DD + h*HDIM;
#pragma unroll
        for (int nt = 0; nt < 8; ++nt) {
            int col = 8*nt + 2*(lane & 3);
            split_store(g_Chi, g_Clo, tok + col,        oacc[mt][nt][0]*inv0, oacc[mt][nt][1]*inv0);
            split_store(g_Chi, g_Clo, tok + 8*DD + col, oacc[mt][nt][2]*inv1, oacc[mt][nt][3]*inv1);
        }
    }
}

// ---------------- launch ----------------
extern "C" void kernel_launch(void* const* d_in, const int* in_sizes, int n_in,
                              void* d_out, int out_size)
{
    const float* x  = (const float*)d_in[0];
    const float* Wq = (const float*)d_in[1];
    const float* Wk = (const float*)d_in[2];
    const float* Wv = (const float*)d_in[3];
    const float* Wo = (const float*)d_in[4];
    const float* bo = (const float*)d_in[5];
    float* out = (float*)d_out;
    (void)in_sizes; (void)n_in; (void)out_size;

    static bool attr_done = false;
    if (!attr_done) {
        cudaFuncSetAttribute(qkv_hmma, cudaFuncAttributeMaxDynamicSharedMemorySize, GEMM_SMEM);
        cudaFuncSetAttribute(out_hmma, cudaFuncAttributeMaxDynamicSharedMemorySize, GEMM_SMEM);
        cudaFuncSetAttribute(attn_hmma, cudaFuncAttributeMaxDynamicSharedMemorySize, ATTN_SMEM);
        attr_done = true;
    }

    // one fused split for x + 4 weights
    split_all<<<(XN4 + 4*WN4) / 256, 256>>>(x, Wq, Wk, Wv, Wo);

    dim3 qkv_grid(DD/128, MTOT/256, 3);
    qkv_hmma<<<qkv_grid, 256, GEMM_SMEM>>>();

    dim3 attn_grid(SS/128, HH, BB);
    attn_hmma<<<attn_grid, 128, ATTN_SMEM>>>();

    dim3 out_grid(DD/128, MTOT/256, 1);
    out_hmma<<<out_grid, 256, GEMM_SMEM>>>(out, bo);
}

// round 7
// speedup vs baseline: 4.2289x; 1.1170x over previous
#include <cuda_runtime.h>
#include <cuda_bf16.h>
#include <cuda_fp16.h>
#include <cstdint>
#include <cstddef>

#define BB 2
#define SS 2048
#define DD 1024
#define HH 16
#define HDIM 64
#define MTOT (BB*SS)   // 4096

typedef __nv_bfloat16 bf16;

// ---------------- device-global scratch ----------------
__device__ bf16 g_xhi[MTOT*DD], g_xlo[MTOT*DD];
__device__ bf16 g_Wqhi[DD*DD], g_Wqlo[DD*DD];
__device__ bf16 g_Wkhi[DD*DD], g_Wklo[DD*DD];
__device__ bf16 g_Wvhi[DD*DD], g_Wvlo[DD*DD];
__device__ bf16 g_Wohi[DD*DD], g_Wolo[DD*DD];
__device__ bf16 g_Qhi[MTOT*DD], g_Qlo[MTOT*DD];   // Q pre-scaled by 0.125*log2(e)
__device__ bf16 g_Khi[MTOT*DD], g_Klo[MTOT*DD];
__device__ __half g_Vhi[MTOT*DD], g_Vlo[MTOT*DD]; // V as f16 hi/lo for f16 PV MMA
__device__ bf16 g_Chi[MTOT*DD], g_Clo[MTOT*DD];

// ---------------- helpers ----------------
__device__ __forceinline__ uint32_t smem_u32(const void* p) {
    uint32_t a;
    asm("{ .reg .u64 t; cvta.to.shared.u64 t, %1; cvt.u32.u64 %0, t; }" : "=r"(a) : "l"(p));
    return a;
}
#define SWZ(o) ((uint32_t)(o) ^ ((((uint32_t)(o)) >> 3) & 0x70))

__device__ __forceinline__ void cp16(uint32_t d, const void* s) {
    asm volatile("cp.async.cg.shared.global [%0], [%1], 16;" :: "r"(d), "l"(s));
}
#define CP_COMMIT() asm volatile("cp.async.commit_group;" ::: "memory")
#define CP_WAIT1()  asm volatile("cp.async.wait_group 1;" ::: "memory")
#define CP_WAIT0()  asm volatile("cp.async.wait_group 0;" ::: "memory")

__device__ __forceinline__ void ldsm4(uint32_t* r, uint32_t a) {
    asm volatile("ldmatrix.sync.aligned.m8n8.x4.shared.b16 {%0,%1,%2,%3}, [%4];"
        : "=r"(r[0]), "=r"(r[1]), "=r"(r[2]), "=r"(r[3]) : "r"(a));
}
__device__ __forceinline__ void ldsm4t(uint32_t* r, uint32_t a) {
    asm volatile("ldmatrix.sync.aligned.m8n8.x4.trans.shared.b16 {%0,%1,%2,%3}, [%4];"
        : "=r"(r[0]), "=r"(r[1]), "=r"(r[2]), "=r"(r[3]) : "r"(a));
}
__device__ __forceinline__ void mma16816(float* c, const uint32_t* a, const uint32_t* b) {
    asm volatile("mma.sync.aligned.m16n8k16.row.col.f32.bf16.bf16.f32 "
        "{%0,%1,%2,%3}, {%4,%5,%6,%7}, {%8,%9}, {%0,%1,%2,%3};"
        : "+f"(c[0]), "+f"(c[1]), "+f"(c[2]), "+f"(c[3])
        : "r"(a[0]), "r"(a[1]), "r"(a[2]), "r"(a[3]), "r"(b[0]), "r"(b[1]));
}
__device__ __forceinline__ void mma16816h(float* c, const uint32_t* a, const uint32_t* b) {
    asm volatile("mma.sync.aligned.m16n8k16.row.col.f32.f16.f16.f32 "
        "{%0,%1,%2,%3}, {%4,%5,%6,%7}, {%8,%9}, {%0,%1,%2,%3};"
        : "+f"(c[0]), "+f"(c[1]), "+f"(c[2]), "+f"(c[3])
        : "r"(a[0]), "r"(a[1]), "r"(a[2]), "r"(a[3]), "r"(b[0]), "r"(b[1]));
}

// pack two f32 -> f16x2 {lo, hi}, then ex2 both halves (P fragment builder)
__device__ __forceinline__ uint32_t ex2pack(float lo, float hi) {
    uint32_t d, r;
    asm("cvt.rn.f16x2.f32 %0, %1, %2;" : "=r"(d) : "f"(hi), "f"(lo));
    asm("ex2.approx.f16x2 %0, %1;" : "=r"(r) : "r"(d));
    return r;
}
__device__ __forceinline__ float ex2f(float x) {
    float r; asm("ex2.approx.f32 %0, %1;" : "=f"(r) : "f"(x)); return r;
}

__device__ __forceinline__ void pk_split(uint32_t& hi, uint32_t& lo, float x, float y) {
    bf16 hx = __float2bfloat16_rn(x), hy = __float2bfloat16_rn(y);
    __nv_bfloat162 ph; ph.x = hx; ph.y = hy;
    float rx = x - __bfloat162float(hx), ry = y - __bfloat162float(hy);
    __nv_bfloat162 pl; pl.x = __float2bfloat16_rn(rx); pl.y = __float2bfloat16_rn(ry);
    hi = *(uint32_t*)&ph;
    lo = *(uint32_t*)&pl;
}
__device__ __forceinline__ void split_store(bf16* hi, bf16* lo, size_t off, float v0, float v1) {
    uint32_t h, l;
    pk_split(h, l, v0, v1);
    *(uint32_t*)(hi + off) = h;
    *(uint32_t*)(lo + off) = l;
}
__device__ __forceinline__ void split_store_h(__half* hi, __half* lo, size_t off, float v0, float v1) {
    __half hx = __float2half_rn(v0), hy = __float2half_rn(v1);
    __half2 ph; ph.x = hx; ph.y = hy;
    float rx = v0 - __half2float(hx), ry = v1 - __half2float(hy);
    __half2 pl; pl.x = __float2half_rn(rx); pl.y = __float2half_rn(ry);
    *(uint32_t*)(hi + off) = *(uint32_t*)&ph;
    *(uint32_t*)(lo + off) = *(uint32_t*)&pl;
}

// ---------------- fused fp32 -> bf16 hi/lo split (all 5 tensors) ------------
#define XN4 (MTOT*DD/4)          // 1048576
#define WN4 (DD*DD/4)            // 262144  (= 1<<18)

__global__ __launch_bounds__(256) void split_all(const float* __restrict__ x,
                                                 const float* __restrict__ Wq,
                                                 const float* __restrict__ Wk,
                                                 const float* __restrict__ Wv,
                                                 const float* __restrict__ Wo)
{
    int i = blockIdx.x * blockDim.x + threadIdx.x;
    const float* s;
    bf16 *hi, *lo;
    int off;
    if (i < XN4) { s = x; hi = g_xhi; lo = g_xlo; off = i; }
    else {
        int j = i - XN4;
        int w = j >> 18;
        off = j & (WN4 - 1);
        if (w == 0)      { s = Wq; hi = g_Wqhi; lo = g_Wqlo; }
        else if (w == 1) { s = Wk; hi = g_Wkhi; lo = g_Wklo; }
        else if (w == 2) { s = Wv; hi = g_Wvhi; lo = g_Wvlo; }
        else             { s = Wo; hi = g_Wohi; lo = g_Wolo; }
    }
    float4 v = ((const float4*)s)[off];
    uint32_t h0, l0, h1, l1;
    pk_split(h0, l0, v.x, v.y);
    pk_split(h1, l1, v.z, v.w);
    ((uint32_t*)hi)[off*2+0] = h0; ((uint32_t*)hi)[off*2+1] = h1;
    ((uint32_t*)lo)[off*2+0] = l0; ((uint32_t*)lo)[off*2+1] = l1;
}

// ---------------- HMMA split-bf16 GEMM core (2-stage, 256 thr, 64x64 warp) --
#define SM_AHI 0u
#define SM_ALO 32768u
#define SM_BHI 65536u
#define SM_BLO 81920u
#define STG    98304u
#define GEMM_SMEM (2*98304)

__device__ __forceinline__ void gemm_load(uint32_t sb, int st,
    const bf16* __restrict__ Ahi, const bf16* __restrict__ Alo,
    const bf16* __restrict__ Bhi, const bf16* __restrict__ Blo,
    int r0, int c0, int kt, int tid)
{
    const uint32_t base = sb + (uint32_t)st * STG;
#pragma unroll
    for (int i = 0; i < 8; ++i) {
        int idx = tid + i*256;                // 0..2047
        int row = idx >> 3, c16 = idx & 7;
        uint32_t so = SWZ(row*128 + c16*16);
        size_t ga = (size_t)(r0+row)*DD + kt + c16*8;
        cp16(base + SM_AHI + so, Ahi + ga);
        cp16(base + SM_ALO + so, Alo + ga);
    }
#pragma unroll
    for (int i = 0; i < 4; ++i) {
        int idx = tid + i*256;                // 0..1023
        int row = idx >> 3, c16 = idx & 7;
        uint32_t so = SWZ(row*128 + c16*16);
        size_t gb = (size_t)(c0+row)*DD + kt + c16*8;
        cp16(base + SM_BHI + so, Bhi + gb);
        cp16(base + SM_BLO + so, Blo + gb);
    }
}

__device__ __forceinline__ void hgemm_core(const bf16* __restrict__ Ahi, const bf16* __restrict__ Alo,
                                           const bf16* __restrict__ Bhi, const bf16* __restrict__ Blo,
                                           int r0, int c0, float acc[4][8][4])
{
    extern __shared__ char smem[];
    const uint32_t sb = smem_u32(smem);
    const int tid = threadIdx.x, lane = tid & 31, wid = tid >> 5;
    const int wr = wid >> 1, wc = wid & 1;

#pragma unroll
    for (int i = 0; i < 4; ++i)
#pragma unroll
        for (int j = 0; j < 8; ++j)
#pragma unroll
            for (int e = 0; e < 4; ++e) acc[i][j][e] = 0.f;

    const int arow  = 64*wr + (lane & 15);
    const int acol8 = (lane >> 4) * 8;
    const int brow  = 64*wc + (lane & 7) + ((lane & 16) >> 1);
    const int bk8   = lane & 8;

    gemm_load(sb, 0, Ahi, Alo, Bhi, Blo, r0, c0, 0, tid);
    CP_COMMIT();

    for (int ch = 0; ch < 16; ++ch) {
        if (ch < 15) {
            gemm_load(sb, (ch+1) & 1, Ahi, Alo, Bhi, Blo, r0, c0, (ch+1)*64, tid);
            CP_COMMIT();
            CP_WAIT1();
        } else {
            CP_WAIT0();
        }
        __syncthreads();

        const uint32_t cb = sb + (uint32_t)(ch & 1) * STG;
#pragma unroll
        for (int t = 0; t < 4; ++t) {
            uint32_t fahi[4][4], falo[4][4], fbhi[4][4], fblo[4][4];
#pragma unroll
            for (int mt = 0; mt < 4; ++mt) {
                uint32_t ao = SWZ((arow + 16*mt)*128 + (t*16 + acol8)*2);
                ldsm4(fahi[mt], cb + SM_AHI + ao);
                ldsm4(falo[mt], cb + SM_ALO + ao);
            }
#pragma unroll
            for (int p = 0; p < 4; ++p) {
                uint32_t bo = SWZ((brow + 16*p)*128 + (t*16 + bk8)*2);
                ldsm4(fbhi[p], cb + SM_BHI + bo);
                ldsm4(fblo[p], cb + SM_BLO + bo);
            }
#pragma unroll
            for (int mt = 0; mt < 4; ++mt)
#pragma unroll
                for (int p = 0; p < 4; ++p) {
                    mma16816(acc[mt][2*p],   fahi[mt], &fbhi[p][0]);
                    mma16816(acc[mt][2*p+1], fahi[mt], &fbhi[p][2]);
                    mma16816(acc[mt][2*p],   fahi[mt], &fblo[p][0]);
                    mma16816(acc[mt][2*p+1], fahi[mt], &fblo[p][2]);
                    mma16816(acc[mt][2*p],   falo[mt], &fbhi[p][0]);
                    mma16816(acc[mt][2*p+1], falo[mt], &fbhi[p][2]);
                }
        }
        __syncthreads();
    }
}

__global__ __launch_bounds__(256, 1) void qkv_hmma()
{
    const bf16 *Bhi, *Blo;
    if (blockIdx.z == 0)      { Bhi = g_Wqhi; Blo = g_Wqlo; }
    else if (blockIdx.z == 1) { Bhi = g_Wkhi; Blo = g_Wklo; }
    else                      { Bhi = g_Wvhi; Blo = g_Wvlo; }

    float acc[4][8][4];
    const int r0 = blockIdx.y * 256, c0 = blockIdx.x * 128;
    hgemm_core(g_xhi, g_xlo, Bhi, Blo, r0, c0, acc);

    const int tid = threadIdx.x, lane = tid & 31, wid = tid >> 5;
    const int wr = wid >> 1, wc = wid & 1;
    // Q gets 0.125 * log2(e) folded in (softmax runs in exp2 domain)
    const float scale = (blockIdx.z == 0) ? 0.18033688f : 1.f;
#pragma unroll
    for (int mt = 0; mt < 4; ++mt)
#pragma unroll
        for (int nt = 0; nt < 8; ++nt) {
            int rg = r0 + 64*wr + 16*mt + (lane >> 2);
            int cg = c0 + 64*wc + 8*nt + 2*(lane & 3);
            int bidx = rg >> 11, s = rg & 2047, h = cg >> 6, hd = cg & 63;
            size_t base = (((size_t)bidx*HH + h)*SS + s)*HDIM + hd;
            if (blockIdx.z == 2) {
                split_store_h(g_Vhi, g_Vlo, base,          acc[mt][nt][0], acc[mt][nt][1]);
                split_store_h(g_Vhi, g_Vlo, base + 8*HDIM, acc[mt][nt][2], acc[mt][nt][3]);
            } else {
                bf16 *Ohi = (blockIdx.z == 0) ? g_Qhi : g_Khi;
                bf16 *Olo = (blockIdx.z == 0) ? g_Qlo : g_Klo;
                split_store(Ohi, Olo, base,          acc[mt][nt][0]*scale, acc[mt][nt][1]*scale);
                split_store(Ohi, Olo, base + 8*HDIM, acc[mt][nt][2]*scale, acc[mt][nt][3]*scale);
            }
        }
}

__global__ __launch_bounds__(256, 1) void out_hmma(float* __restrict__ out,
                                                   const float* __restrict__ bo)
{
    float acc[4][8][4];
    const int r0 = blockIdx.y * 256, c0 = blockIdx.x * 128;
    hgemm_core(g_Chi, g_Clo, g_Wohi, g_Wolo, r0, c0, acc);

    const int tid = threadIdx.x, lane = tid & 31, wid = tid >> 5;
    const int wr = wid >> 1, wc = wid & 1;
#pragma unroll
    for (int mt = 0; mt < 4; ++mt)
#pragma unroll
        for (int nt = 0; nt < 8; ++nt) {
            int rg = r0 + 64*wr + 16*mt + (lane >> 2);
            int cg = c0 + 64*wc + 8*nt + 2*(lane & 3);
            float b0v = bo[cg], b1v = bo[cg+1];
            float2 o0 = make_float2(acc[mt][nt][0] + b0v, acc[mt][nt][1] + b1v);
            float2 o1 = make_float2(acc[mt][nt][2] + b0v, acc[mt][nt][3] + b1v);
            *(float2*)&out[(size_t)rg * DD + cg] = o0;
            *(float2*)&out[(size_t)(rg+8) * DD + cg] = o1;
        }
}

// ---------------- HMMA causal flash attention (exp2-domain, f16 P&V) -------
#define AQHI 0u
#define AQLO 16384u
#define AKV  32768u
#define KSTG 32768u
#define AKHI 0u
#define AKLO 8192u
#define AVHI 16384u
#define AVLO 24576u
#define ATTN_SMEM (32768 + 2*32768)

__device__ __forceinline__ void attn_load_kv(uint32_t sb, int st, size_t hb, int j0, int tid)
{
    const uint32_t base = sb + AKV + (uint32_t)st * KSTG;
#pragma unroll
    for (int i = 0; i < 4; ++i) {
        int idx = tid + i*128;               // 0..511
        int row = idx >> 3, c16 = idx & 7;
        uint32_t so = SWZ(row*128 + c16*16);
        size_t g = (hb + j0 + row)*HDIM + c16*8;
        cp16(base + AKHI + so, g_Khi + g);
        cp16(base + AKLO + so, g_Klo + g);
        cp16(base + AVHI + so, g_Vhi + g);
        cp16(base + AVLO + so, g_Vlo + g);
    }
}

__global__ __launch_bounds__(128, 2) void attn_hmma()
{
    extern __shared__ char smem[];
    const uint32_t sb = smem_u32(smem);
    const int tid = threadIdx.x, lane = tid & 31, wid = tid >> 5;
    const int qb = gridDim.x - 1 - blockIdx.x;   // heavy CTAs first
    const int h = blockIdx.y, b = blockIdx.z;
    const int q0 = qb * 128;
    const size_t hb = ((size_t)b*HH + h) * SS;

#pragma unroll
    for (int i = 0; i < 8; ++i) {
        int idx = tid + i*128;               // 0..1023
        int row = idx >> 3, c16 = idx & 7;
        uint32_t so = SWZ(row*128 + c16*16);
        size_t g = (hb + q0 + row)*HDIM + c16*8;
        cp16(sb + AQHI + so, g_Qhi + g);
        cp16(sb + AQLO + so, g_Qlo + g);
    }
    attn_load_kv(sb, 0, hb, 0, tid);
    CP_COMMIT();

    uint32_t fqhi[2][4][4];
    float oacc[2][8][4];
#pragma unroll
    for (int mt = 0; mt < 2; ++mt)
#pragma unroll
        for (int nt = 0; nt < 8; ++nt)
#pragma unroll
            for (int e = 0; e < 4; ++e) oacc[mt][nt][e] = 0.f;
    float m[2][2] = {{-1e30f,-1e30f},{-1e30f,-1e30f}};
    float l[2][2] = {{0.f,0.f},{0.f,0.f}};

    const int rb0 = q0 + 32*wid + (lane >> 2);
    const int ntiles = 2*qb + 2;

    for (int kt = 0; kt < ntiles; ++kt) {
        const int j0 = kt * 64;
        if (kt + 1 < ntiles) {
            attn_load_kv(sb, (kt+1) & 1, hb, j0 + 64, tid);
            CP_COMMIT();
            CP_WAIT1();
        } else {
            CP_WAIT0();
        }
        __syncthreads();

        if (kt == 0) {
#pragma unroll
            for (int mt = 0; mt < 2; ++mt)
#pragma unroll
                for (int t = 0; t < 4; ++t) {
                    uint32_t ao = SWZ((32*wid + 16*mt + (lane & 15))*128 + (t*16 + (lane >> 4)*8)*2);
                    ldsm4(fqhi[mt][t], sb + AQHI + ao);
                }
        }

        const uint32_t kb = sb + AKV + (uint32_t)(kt & 1) * KSTG;

        // S = Q K^T in exp2 domain (3-pass bf16 split)
        float sacc[2][8][4];
#pragma unroll
        for (int mt = 0; mt < 2; ++mt)
#pragma unroll
            for (int nt = 0; nt < 8; ++nt)
#pragma unroll
                for (int e = 0; e < 4; ++e) sacc[mt][nt][e] = 0.f;

#pragma unroll
        for (int t = 0; t < 4; ++t) {
            uint32_t fql[2][4];
#pragma unroll
            for (int mt = 0; mt < 2; ++mt) {
                uint32_t ao = SWZ((32*wid + 16*mt + (lane & 15))*128 + (t*16 + (lane >> 4)*8)*2);
                ldsm4(fql[mt], sb + AQLO + ao);
            }
#pragma unroll
            for (int p = 0; p < 4; ++p) {
                uint32_t bo_ = SWZ((16*p + (lane & 7) + ((lane & 16) >> 1))*128 + (t*16 + (lane & 8))*2);
                uint32_t kbh[4], kbl[4];
                ldsm4(kbh, kb + AKHI + bo_);
                ldsm4(kbl, kb + AKLO + bo_);
#pragma unroll
                for (int mt = 0; mt < 2; ++mt) {
                    mma16816(sacc[mt][2*p],   fqhi[mt][t], &kbh[0]);
                    mma16816(sacc[mt][2*p+1], fqhi[mt][t], &kbh[2]);
                    mma16816(sacc[mt][2*p],   fqhi[mt][t], &kbl[0]);
                    mma16816(sacc[mt][2*p+1], fqhi[mt][t], &kbl[2]);
                    mma16816(sacc[mt][2*p],   fql[mt], &kbh[0]);
                    mma16816(sacc[mt][2*p+1], fql[mt], &kbh[2]);
                }
            }
        }

        // causal mask, online softmax (exp2 domain), P -> packed f16 fragments
        uint32_t pp[2][8][2];
#pragma unroll
        for (int mt = 0; mt < 2; ++mt) {
            const int rbase = rb0 + 16*mt;
            if (j0 + 63 > rbase) {
#pragma unroll
                for (int nt = 0; nt < 8; ++nt) {
                    int cg = j0 + 8*nt + 2*(lane & 3);
                    if (cg   > rbase)     sacc[mt][nt][0] = -1e30f;
                    if (cg+1 > rbase)     sacc[mt][nt][1] = -1e30f;
                    if (cg   > rbase + 8) sacc[mt][nt][2] = -1e30f;
                    if (cg+1 > rbase + 8) sacc[mt][nt][3] = -1e30f;
                }
            }
            float mx0 = -1e30f, mx1 = -1e30f;
#pragma unroll
            for (int nt = 0; nt < 8; ++nt) {
                mx0 = fmaxf(mx0, fmaxf(sacc[mt][nt][0], sacc[mt][nt][1]));
                mx1 = fmaxf(mx1, fmaxf(sacc[mt][nt][2], sacc[mt][nt][3]));
            }
            mx0 = fmaxf(mx0, __shfl_xor_sync(0xffffffffu, mx0, 1));
            mx0 = fmaxf(mx0, __shfl_xor_sync(0xffffffffu, mx0, 2));
            mx1 = fmaxf(mx1, __shfl_xor_sync(0xffffffffu, mx1, 1));
            mx1 = fmaxf(mx1, __shfl_xor_sync(0xffffffffu, mx1, 2));
            const float mn0 = fmaxf(m[mt][0], mx0), mn1 = fmaxf(m[mt][1], mx1);
            const float c0f = ex2f(m[mt][0] - mn0), c1f = ex2f(m[mt][1] - mn1);
            float s0 = 0.f, s1 = 0.f;
#pragma unroll
            for (int nt = 0; nt < 8; ++nt) {
                uint32_t p01 = ex2pack(sacc[mt][nt][0] - mn0, sacc[mt][nt][1] - mn0);
                uint32_t p23 = ex2pack(sacc[mt][nt][2] - mn1, sacc[mt][nt][3] - mn1);
                pp[mt][nt][0] = p01;
                pp[mt][nt][1] = p23;
                __half2 h01 = *(__half2*)&p01;
                __half2 h23 = *(__half2*)&p23;
                s0 += __half2float(h01.x) + __half2float(h01.y);
                s1 += __half2float(h23.x) + __half2float(h23.y);
            }
            s0 += __shfl_xor_sync(0xffffffffu, s0, 1);
            s0 += __shfl_xor_sync(0xffffffffu, s0, 2);
            s1 += __shfl_xor_sync(0xffffffffu, s1, 1);
            s1 += __shfl_xor_sync(0xffffffffu, s1, 2);
            l[mt][0] = l[mt][0] * c0f + s0;
            l[mt][1] = l[mt][1] * c1f + s1;
            m[mt][0] = mn0; m[mt][1] = mn1;
#pragma unroll
            for (int nt = 0; nt < 8; ++nt) {
                oacc[mt][nt][0] *= c0f; oacc[mt][nt][1] *= c0f;
                oacc[mt][nt][2] *= c1f; oacc[mt][nt][3] *= c1f;
            }
        }

        // O += P V   (2-pass: P exact f16, V f16 hi/lo)
#pragma unroll
        for (int kc = 0; kc < 4; ++kc) {
#pragma unroll
            for (int p = 0; p < 4; ++p) {
                uint32_t vo = SWZ((kc*16 + (lane & 15))*128 + (16*p + ((lane >> 1) & 8))*2);
                uint32_t vbh[4], vbl[4];
                ldsm4t(vbh, kb + AVHI + vo);
                ldsm4t(vbl, kb + AVLO + vo);
#pragma unroll
                for (int mt = 0; mt < 2; ++mt) {
                    uint32_t pa[4] = { pp[mt][2*kc][0], pp[mt][2*kc][1],
                                       pp[mt][2*kc+1][0], pp[mt][2*kc+1][1] };
                    mma16816h(oacc[mt][2*p],   pa, &vbh[0]);
                    mma16816h(oacc[mt][2*p+1], pa, &vbh[2]);
                    mma16816h(oacc[mt][2*p],   pa, &vbl[0]);
                    mma16816h(oacc[mt][2*p+1], pa, &vbl[2]);
                }
            }
        }
        __syncthreads();
    }

#pragma unroll
    for (int mt = 0; mt < 2; ++mt) {
        const float inv0 = 1.f / l[mt][0], inv1 = 1.f / l[mt][1];
        const size_t tok = ((size_t)b*SS + rb0 + 16*mt)*DD + h*HDIM;
#pragma unroll
        for (int nt = 0; nt < 8; ++nt) {
            int col = 8*nt + 2*(lane & 3);
            split_store(g_Chi, g_Clo, tok + col,        oacc[mt][nt][0]*inv0, oacc[mt][nt][1]*inv0);
            split_store(g_Chi, g_Clo, tok + 8*DD + col, oacc[mt][nt][2]*inv1, oacc[mt][nt][3]*inv1);
        }
    }
}

// ---------------- launch ----------------
extern "C" void kernel_launch(void* const* d_in, const int* in_sizes, int n_in,
                              void* d_out, int out_size)
{
    const float* x  = (const float*)d_in[0];
    const float* Wq = (const float*)d_in[1];
    const float* Wk = (const float*)d_in[2];
    const float* Wv = (const float*)d_in[3];
    const float* Wo = (const float*)d_in[4];
    const float* bo = (const float*)d_in[5];
    float* out = (float*)d_out;
    (void)in_sizes; (void)n_in; (void)out_size;

    static bool attr_done = false;
    if (!attr_done) {
        cudaFuncSetAttribute(qkv_hmma, cudaFuncAttributeMaxDynamicSharedMemorySize, GEMM_SMEM);
        cudaFuncSetAttribute(out_hmma, cudaFuncAttributeMaxDynamicSharedMemorySize, GEMM_SMEM);
        cudaFuncSetAttribute(attn_hmma, cudaFuncAttributeMaxDynamicSharedMemorySize, ATTN_SMEM);
        attr_done = true;
    }

    split_all<<<(XN4 + 4*WN4) / 256, 256>>>(x, Wq, Wk, Wv, Wo);

    dim3 qkv_grid(DD/128, MTOT/256, 3);
    qkv_hmma<<<qkv_grid, 256, GEMM_SMEM>>>();

    dim3 attn_grid(SS/128, HH, BB);
    attn_hmma<<<attn_grid, 128, ATTN_SMEM>>>();

    dim3 out_grid(DD/128, MTOT/256, 1);
    out_hmma<<<out_grid, 256, GEMM_SMEM>>>(out, bo);
}

// round 8
// speedup vs baseline: 4.3159x; 1.0206x over previous
#include <cuda_runtime.h>
#include <cuda_bf16.h>
#include <cuda_fp16.h>
#include <cstdint>
#include <cstddef>

#define BB 2
#define SS 2048
#define DD 1024
#define HH 16
#define HDIM 64
#define MTOT (BB*SS)   // 4096

typedef __nv_bfloat16 bf16;

// ---------------- device-global scratch ----------------
__device__ bf16 g_xhi[MTOT*DD], g_xlo[MTOT*DD];
__device__ bf16 g_Wqhi[DD*DD], g_Wqlo[DD*DD];
__device__ bf16 g_Wkhi[DD*DD], g_Wklo[DD*DD];
__device__ bf16 g_Wvhi[DD*DD], g_Wvlo[DD*DD];
__device__ bf16 g_Wohi[DD*DD], g_Wolo[DD*DD];
__device__ bf16 g_Qhi[MTOT*DD], g_Qlo[MTOT*DD];   // Q pre-scaled by 0.125*log2(e)
__device__ bf16 g_Khi[MTOT*DD], g_Klo[MTOT*DD];
__device__ __half g_Vhi[MTOT*DD], g_Vlo[MTOT*DD]; // V as f16 hi/lo for f16 PV MMA
__device__ bf16 g_Chi[MTOT*DD], g_Clo[MTOT*DD];

// ---------------- helpers ----------------
__device__ __forceinline__ uint32_t smem_u32(const void* p) {
    uint32_t a;
    asm("{ .reg .u64 t; cvta.to.shared.u64 t, %1; cvt.u32.u64 %0, t; }" : "=r"(a) : "l"(p));
    return a;
}
#define SWZ(o)   ((uint32_t)(o) ^ ((((uint32_t)(o)) >> 3) & 0x70))
#define SWZ64(o) ((uint32_t)(o) ^ ((((uint32_t)(o)) >> 3) & 0x30))

__device__ __forceinline__ void cp16(uint32_t d, const void* s) {
    asm volatile("cp.async.cg.shared.global [%0], [%1], 16;" :: "r"(d), "l"(s));
}
#define CP_COMMIT() asm volatile("cp.async.commit_group;" ::: "memory")
#define CP_WAIT1()  asm volatile("cp.async.wait_group 1;" ::: "memory")
#define CP_WAIT0()  asm volatile("cp.async.wait_group 0;" ::: "memory")

__device__ __forceinline__ void ldsm4(uint32_t* r, uint32_t a) {
    asm volatile("ldmatrix.sync.aligned.m8n8.x4.shared.b16 {%0,%1,%2,%3}, [%4];"
        : "=r"(r[0]), "=r"(r[1]), "=r"(r[2]), "=r"(r[3]) : "r"(a));
}
__device__ __forceinline__ void ldsm4t(uint32_t* r, uint32_t a) {
    asm volatile("ldmatrix.sync.aligned.m8n8.x4.trans.shared.b16 {%0,%1,%2,%3}, [%4];"
        : "=r"(r[0]), "=r"(r[1]), "=r"(r[2]), "=r"(r[3]) : "r"(a));
}
__device__ __forceinline__ void mma16816(float* c, const uint32_t* a, const uint32_t* b) {
    asm volatile("mma.sync.aligned.m16n8k16.row.col.f32.bf16.bf16.f32 "
        "{%0,%1,%2,%3}, {%4,%5,%6,%7}, {%8,%9}, {%0,%1,%2,%3};"
        : "+f"(c[0]), "+f"(c[1]), "+f"(c[2]), "+f"(c[3])
        : "r"(a[0]), "r"(a[1]), "r"(a[2]), "r"(a[3]), "r"(b[0]), "r"(b[1]));
}
__device__ __forceinline__ void mma16816h(float* c, const uint32_t* a, const uint32_t* b) {
    asm volatile("mma.sync.aligned.m16n8k16.row.col.f32.f16.f16.f32 "
        "{%0,%1,%2,%3}, {%4,%5,%6,%7}, {%8,%9}, {%0,%1,%2,%3};"
        : "+f"(c[0]), "+f"(c[1]), "+f"(c[2]), "+f"(c[3])
        : "r"(a[0]), "r"(a[1]), "r"(a[2]), "r"(a[3]), "r"(b[0]), "r"(b[1]));
}

__device__ __forceinline__ uint32_t ex2pack(float lo, float hi) {
    uint32_t d, r;
    asm("cvt.rn.f16x2.f32 %0, %1, %2;" : "=r"(d) : "f"(hi), "f"(lo));
    asm("ex2.approx.f16x2 %0, %1;" : "=r"(r) : "r"(d));
    return r;
}
__device__ __forceinline__ float ex2f(float x) {
    float r; asm("ex2.approx.f32 %0, %1;" : "=f"(r) : "f"(x)); return r;
}

__device__ __forceinline__ void pk_split(uint32_t& hi, uint32_t& lo, float x, float y) {
    bf16 hx = __float2bfloat16_rn(x), hy = __float2bfloat16_rn(y);
    __nv_bfloat162 ph; ph.x = hx; ph.y = hy;
    float rx = x - __bfloat162float(hx), ry = y - __bfloat162float(hy);
    __nv_bfloat162 pl; pl.x = __float2bfloat16_rn(rx); pl.y = __float2bfloat16_rn(ry);
    hi = *(uint32_t*)&ph;
    lo = *(uint32_t*)&pl;
}
__device__ __forceinline__ void split_store(bf16* hi, bf16* lo, size_t off, float v0, float v1) {
    uint32_t h, l;
    pk_split(h, l, v0, v1);
    *(uint32_t*)(hi + off) = h;
    *(uint32_t*)(lo + off) = l;
}
__device__ __forceinline__ void split_store_h(__half* hi, __half* lo, size_t off, float v0, float v1) {
    __half hx = __float2half_rn(v0), hy = __float2half_rn(v1);
    __half2 ph; ph.x = hx; ph.y = hy;
    float rx = v0 - __half2float(hx), ry = v1 - __half2float(hy);
    __half2 pl; pl.x = __float2half_rn(rx); pl.y = __float2half_rn(ry);
    *(uint32_t*)(hi + off) = *(uint32_t*)&ph;
    *(uint32_t*)(lo + off) = *(uint32_t*)&pl;
}

// ---------------- fused fp32 -> bf16 hi/lo split (all 5 tensors) ------------
#define XN4 (MTOT*DD/4)          // 1048576
#define WN4 (DD*DD/4)            // 262144  (= 1<<18)

__global__ __launch_bounds__(256) void split_all(const float* __restrict__ x,
                                                 const float* __restrict__ Wq,
                                                 const float* __restrict__ Wk,
                                                 const float* __restrict__ Wv,
                                                 const float* __restrict__ Wo)
{
    int i = blockIdx.x * blockDim.x + threadIdx.x;
    const float* s;
    bf16 *hi, *lo;
    int off;
    if (i < XN4) { s = x; hi = g_xhi; lo = g_xlo; off = i; }
    else {
        int j = i - XN4;
        int w = j >> 18;
        off = j & (WN4 - 1);
        if (w == 0)      { s = Wq; hi = g_Wqhi; lo = g_Wqlo; }
        else if (w == 1) { s = Wk; hi = g_Wkhi; lo = g_Wklo; }
        else if (w == 2) { s = Wv; hi = g_Wvhi; lo = g_Wvlo; }
        else             { s = Wo; hi = g_Wohi; lo = g_Wolo; }
    }
    float4 v = ((const float4*)s)[off];
    uint32_t h0, l0, h1, l1;
    pk_split(h0, l0, v.x, v.y);
    pk_split(h1, l1, v.z, v.w);
    ((uint32_t*)hi)[off*2+0] = h0; ((uint32_t*)hi)[off*2+1] = h1;
    ((uint32_t*)lo)[off*2+0] = l0; ((uint32_t*)lo)[off*2+1] = l1;
}

// ---------------- HMMA split-bf16 GEMM core -------------------------------
// CTA tile 128x128, 128 threads (4 warps, 2x2), warp tile 64x64.
// K-chunk 32 (SW64 swizzle, 64B rows), 2-stage cp.async, 2 CTAs/SM.
#define SM_AHI 0u
#define SM_ALO 8192u
#define SM_BHI 16384u
#define SM_BLO 24576u
#define STG    32768u
#define GEMM_SMEM (2*32768)

__device__ __forceinline__ void gemm_load(uint32_t sb, int st,
    const bf16* __restrict__ Ahi, const bf16* __restrict__ Alo,
    const bf16* __restrict__ Bhi, const bf16* __restrict__ Blo,
    int r0, int c0, int kt, int tid)
{
    const uint32_t base = sb + (uint32_t)st * STG;
#pragma unroll
    for (int i = 0; i < 4; ++i) {
        int idx = tid + i*128;                // 0..511
        int row = idx >> 2, c16 = idx & 3;
        uint32_t so = SWZ64(row*64 + c16*16);
        size_t ga = (size_t)(r0+row)*DD + kt + c16*8;
        size_t gb = (size_t)(c0+row)*DD + kt + c16*8;
        cp16(base + SM_AHI + so, Ahi + ga);
        cp16(base + SM_ALO + so, Alo + ga);
        cp16(base + SM_BHI + so, Bhi + gb);
        cp16(base + SM_BLO + so, Blo + gb);
    }
}

__device__ __forceinline__ void hgemm_core(const bf16* __restrict__ Ahi, const bf16* __restrict__ Alo,
                                           const bf16* __restrict__ Bhi, const bf16* __restrict__ Blo,
                                           int r0, int c0, float acc[4][8][4])
{
    extern __shared__ char smem[];
    const uint32_t sb = smem_u32(smem);
    const int tid = threadIdx.x, lane = tid & 31, wid = tid >> 5;
    const int wr = wid >> 1, wc = wid & 1;

#pragma unroll
    for (int i = 0; i < 4; ++i)
#pragma unroll
        for (int j = 0; j < 8; ++j)
#pragma unroll
            for (int e = 0; e < 4; ++e) acc[i][j][e] = 0.f;

    const int arow  = 64*wr + (lane & 15);
    const int acol8 = (lane >> 4) * 8;
    const int brow  = 64*wc + (lane & 7) + ((lane & 16) >> 1);
    const int bk8   = lane & 8;

    gemm_load(sb, 0, Ahi, Alo, Bhi, Blo, r0, c0, 0, tid);
    CP_COMMIT();

    for (int ch = 0; ch < 32; ++ch) {
        if (ch < 31) {
            gemm_load(sb, (ch+1) & 1, Ahi, Alo, Bhi, Blo, r0, c0, (ch+1)*32, tid);
            CP_COMMIT();
            CP_WAIT1();
        } else {
            CP_WAIT0();
        }
        __syncthreads();

        const uint32_t cb = sb + (uint32_t)(ch & 1) * STG;
#pragma unroll
        for (int t = 0; t < 2; ++t) {
            uint32_t fahi[4][4], falo[4][4], fbhi[4][4], fblo[4][4];
#pragma unroll
            for (int mt = 0; mt < 4; ++mt) {
                uint32_t ao = SWZ64((arow + 16*mt)*64 + (t*16 + acol8)*2);
                ldsm4(fahi[mt], cb + SM_AHI + ao);
                ldsm4(falo[mt], cb + SM_ALO + ao);
            }
#pragma unroll
            for (int p = 0; p < 4; ++p) {
                uint32_t bo = SWZ64((brow + 16*p)*64 + (t*16 + bk8)*2);
                ldsm4(fbhi[p], cb + SM_BHI + bo);
                ldsm4(fblo[p], cb + SM_BLO + bo);
            }
#pragma unroll
            for (int mt = 0; mt < 4; ++mt)
#pragma unroll
                for (int p = 0; p < 4; ++p) {
                    mma16816(acc[mt][2*p],   fahi[mt], &fbhi[p][0]);
                    mma16816(acc[mt][2*p+1], fahi[mt], &fbhi[p][2]);
                    mma16816(acc[mt][2*p],   fahi[mt], &fblo[p][0]);
                    mma16816(acc[mt][2*p+1], fahi[mt], &fblo[p][2]);
                    mma16816(acc[mt][2*p],   falo[mt], &fbhi[p][0]);
                    mma16816(acc[mt][2*p+1], falo[mt], &fbhi[p][2]);
                }
        }
        __syncthreads();
    }
}

__global__ __launch_bounds__(128, 2) void qkv_hmma()
{
    const bf16 *Bhi, *Blo;
    if (blockIdx.z == 0)      { Bhi = g_Wqhi; Blo = g_Wqlo; }
    else if (blockIdx.z == 1) { Bhi = g_Wkhi; Blo = g_Wklo; }
    else                      { Bhi = g_Wvhi; Blo = g_Wvlo; }

    float acc[4][8][4];
    const int r0 = blockIdx.y * 128, c0 = blockIdx.x * 128;
    hgemm_core(g_xhi, g_xlo, Bhi, Blo, r0, c0, acc);

    const int tid = threadIdx.x, lane = tid & 31, wid = tid >> 5;
    const int wr = wid >> 1, wc = wid & 1;
    const float scale = (blockIdx.z == 0) ? 0.18033688f : 1.f;  // 0.125*log2(e) for Q
#pragma unroll
    for (int mt = 0; mt < 4; ++mt)
#pragma unroll
        for (int nt = 0; nt < 8; ++nt) {
            int rg = r0 + 64*wr + 16*mt + (lane >> 2);
            int cg = c0 + 64*wc + 8*nt + 2*(lane & 3);
            int bidx = rg >> 11, s = rg & 2047, h = cg >> 6, hd = cg & 63;
            size_t base = (((size_t)bidx*HH + h)*SS + s)*HDIM + hd;
            if (blockIdx.z == 2) {
                split_store_h(g_Vhi, g_Vlo, base,          acc[mt][nt][0], acc[mt][nt][1]);
                split_store_h(g_Vhi, g_Vlo, base + 8*HDIM, acc[mt][nt][2], acc[mt][nt][3]);
            } else {
                bf16 *Ohi = (blockIdx.z == 0) ? g_Qhi : g_Khi;
                bf16 *Olo = (blockIdx.z == 0) ? g_Qlo : g_Klo;
                split_store(Ohi, Olo, base,          acc[mt][nt][0]*scale, acc[mt][nt][1]*scale);
                split_store(Ohi, Olo, base + 8*HDIM, acc[mt][nt][2]*scale, acc[mt][nt][3]*scale);
            }
        }
}

__global__ __launch_bounds__(128, 2) void out_hmma(float* __restrict__ out,
                                                   const float* __restrict__ bo)
{
    float acc[4][8][4];
    const int r0 = blockIdx.y * 128, c0 = blockIdx.x * 128;
    hgemm_core(g_Chi, g_Clo, g_Wohi, g_Wolo, r0, c0, acc);

    const int tid = threadIdx.x, lane = tid & 31, wid = tid >> 5;
    const int wr = wid >> 1, wc = wid & 1;
#pragma unroll
    for (int mt = 0; mt < 4; ++mt)
#pragma unroll
        for (int nt = 0; nt < 8; ++nt) {
            int rg = r0 + 64*wr + 16*mt + (lane >> 2);
            int cg = c0 + 64*wc + 8*nt + 2*(lane & 3);
            float b0v = bo[cg], b1v = bo[cg+1];
            float2 o0 = make_float2(acc[mt][nt][0] + b0v, acc[mt][nt][1] + b1v);
            float2 o1 = make_float2(acc[mt][nt][2] + b0v, acc[mt][nt][3] + b1v);
            *(float2*)&out[(size_t)rg * DD + cg] = o0;
            *(float2*)&out[(size_t)(rg+8) * DD + cg] = o1;
        }
}

// ---------------- HMMA causal flash attention (exp2-domain, f16 P&V) -------
#define AQHI 0u
#define AQLO 16384u
#define AKV  32768u
#define KSTG 32768u
#define AKHI 0u
#define AKLO 8192u
#define AVHI 16384u
#define AVLO 24576u
#define ATTN_SMEM (32768 + 2*32768)

__device__ __forceinline__ void attn_load_kv(uint32_t sb, int st, size_t hb, int j0, int tid)
{
    const uint32_t base = sb + AKV + (uint32_t)st * KSTG;
#pragma unroll
    for (int i = 0; i < 4; ++i) {
        int idx = tid + i*128;               // 0..511
        int row = idx >> 3, c16 = idx & 7;
        uint32_t so = SWZ(row*128 + c16*16);
        size_t g = (hb + j0 + row)*HDIM + c16*8;
        cp16(base + AKHI + so, g_Khi + g);
        cp16(base + AKLO + so, g_Klo + g);
        cp16(base + AVHI + so, g_Vhi + g);
        cp16(base + AVLO + so, g_Vlo + g);
    }
}

__global__ __launch_bounds__(128, 2) void attn_hmma()
{
    extern __shared__ char smem[];
    const uint32_t sb = smem_u32(smem);
    const int tid = threadIdx.x, lane = tid & 31, wid = tid >> 5;
    const int qb = gridDim.x - 1 - blockIdx.x;   // heavy CTAs first
    const int h = blockIdx.y, b = blockIdx.z;
    const int q0 = qb * 128;
    const size_t hb = ((size_t)b*HH + h) * SS;

#pragma unroll
    for (int i = 0; i < 8; ++i) {
        int idx = tid + i*128;               // 0..1023
        int row = idx >> 3, c16 = idx & 7;
        uint32_t so = SWZ(row*128 + c16*16);
        size_t g = (hb + q0 + row)*HDIM + c16*8;
        cp16(sb + AQHI + so, g_Qhi + g);
        cp16(sb + AQLO + so, g_Qlo + g);
    }
    attn_load_kv(sb, 0, hb, 0, tid);
    CP_COMMIT();

    uint32_t fqhi[2][4][4];
    float oacc[2][8][4];
#pragma unroll
    for (int mt = 0; mt < 2; ++mt)
#pragma unroll
        for (int nt = 0; nt < 8; ++nt)
#pragma unroll
            for (int e = 0; e < 4; ++e) oacc[mt][nt][e] = 0.f;
    float m[2][2] = {{-1e30f,-1e30f},{-1e30f,-1e30f}};
    float l[2][2] = {{0.f,0.f},{0.f,0.f}};

    const int rb0 = q0 + 32*wid + (lane >> 2);
    const int ntiles = 2*qb + 2;

    for (int kt = 0; kt < ntiles; ++kt) {
        const int j0 = kt * 64;
        if (kt + 1 < ntiles) {
            attn_load_kv(sb, (kt+1) & 1, hb, j0 + 64, tid);
            CP_COMMIT();
            CP_WAIT1();
        } else {
            CP_WAIT0();
        }
        __syncthreads();

        if (kt == 0) {
#pragma unroll
            for (int mt = 0; mt < 2; ++mt)
#pragma unroll
                for (int t = 0; t < 4; ++t) {
                    uint32_t ao = SWZ((32*wid + 16*mt + (lane & 15))*128 + (t*16 + (lane >> 4)*8)*2);
                    ldsm4(fqhi[mt][t], sb + AQHI + ao);
                }
        }

        const uint32_t kb = sb + AKV + (uint32_t)(kt & 1) * KSTG;

        // S = Q K^T in exp2 domain (3-pass bf16 split)
        float sacc[2][8][4];
#pragma unroll
        for (int mt = 0; mt < 2; ++mt)
#pragma unroll
            for (int nt = 0; nt < 8; ++nt)
#pragma unroll
                for (int e = 0; e < 4; ++e) sacc[mt][nt][e] = 0.f;

#pragma unroll
        for (int t = 0; t < 4; ++t) {
            uint32_t fql[2][4];
#pragma unroll
            for (int mt = 0; mt < 2; ++mt) {
                uint32_t ao = SWZ((32*wid + 16*mt + (lane & 15))*128 + (t*16 + (lane >> 4)*8)*2);
                ldsm4(fql[mt], sb + AQLO + ao);
            }
#pragma unroll
            for (int p = 0; p < 4; ++p) {
                uint32_t bo_ = SWZ((16*p + (lane & 7) + ((lane & 16) >> 1))*128 + (t*16 + (lane & 8))*2);
                uint32_t kbh[4], kbl[4];
                ldsm4(kbh, kb + AKHI + bo_);
                ldsm4(kbl, kb + AKLO + bo_);
#pragma unroll
                for (int mt = 0; mt < 2; ++mt) {
                    mma16816(sacc[mt][2*p],   fqhi[mt][t], &kbh[0]);
                    mma16816(sacc[mt][2*p+1], fqhi[mt][t], &kbh[2]);
                    mma16816(sacc[mt][2*p],   fqhi[mt][t], &kbl[0]);
                    mma16816(sacc[mt][2*p+1], fqhi[mt][t], &kbl[2]);
                    mma16816(sacc[mt][2*p],   fql[mt], &kbh[0]);
                    mma16816(sacc[mt][2*p+1], fql[mt], &kbh[2]);
                }
            }
        }

        // causal mask, online softmax (exp2 domain), P -> packed f16 fragments
        uint32_t pp[2][8][2];
#pragma unroll
        for (int mt = 0; mt < 2; ++mt) {
            const int rbase = rb0 + 16*mt;
            if (j0 + 63 > rbase) {
#pragma unroll
                for (int nt = 0; nt < 8; ++nt) {
                    int cg = j0 + 8*nt + 2*(lane & 3);
                    if (cg   > rbase)     sacc[mt][nt][0] = -1e30f;
                    if (cg+1 > rbase)     sacc[mt][nt][1] = -1e30f;
                    if (cg   > rbase + 8) sacc[mt][nt][2] = -1e30f;
                    if (cg+1 > rbase + 8) sacc[mt][nt][3] = -1e30f;
                }
            }
            float mx0 = -1e30f, mx1 = -1e30f;
#pragma unroll
            for (int nt = 0; nt < 8; ++nt) {
                mx0 = fmaxf(mx0, fmaxf(sacc[mt][nt][0], sacc[mt][nt][1]));
                mx1 = fmaxf(mx1, fmaxf(sacc[mt][nt][2], sacc[mt][nt][3]));
            }
            mx0 = fmaxf(mx0, __shfl_xor_sync(0xffffffffu, mx0, 1));
            mx0 = fmaxf(mx0, __shfl_xor_sync(0xffffffffu, mx0, 2));
            mx1 = fmaxf(mx1, __shfl_xor_sync(0xffffffffu, mx1, 1));
            mx1 = fmaxf(mx1, __shfl_xor_sync(0xffffffffu, mx1, 2));
            const float mn0 = fmaxf(m[mt][0], mx0), mn1 = fmaxf(m[mt][1], mx1);
            const float c0f = ex2f(m[mt][0] - mn0), c1f = ex2f(m[mt][1] - mn1);
            float s0 = 0.f, s1 = 0.f;
#pragma unroll
            for (int nt = 0; nt < 8; ++nt) {
                uint32_t p01 = ex2pack(sacc[mt][nt][0] - mn0, sacc[mt][nt][1] - mn0);
                uint32_t p23 = ex2pack(sacc[mt][nt][2] - mn1, sacc[mt][nt][3] - mn1);
                pp[mt][nt][0] = p01;
                pp[mt][nt][1] = p23;
                __half2 h01 = *(__half2*)&p01;
                __half2 h23 = *(__half2*)&p23;
                s0 += __half2float(h01.x) + __half2float(h01.y);
                s1 += __half2float(h23.x) + __half2float(h23.y);
            }
            s0 += __shfl_xor_sync(0xffffffffu, s0, 1);
            s0 += __shfl_xor_sync(0xffffffffu, s0, 2);
            s1 += __shfl_xor_sync(0xffffffffu, s1, 1);
            s1 += __shfl_xor_sync(0xffffffffu, s1, 2);
            l[mt][0] = l[mt][0] * c0f + s0;
            l[mt][1] = l[mt][1] * c1f + s1;
            m[mt][0] = mn0; m[mt][1] = mn1;
#pragma unroll
            for (int nt = 0; nt < 8; ++nt) {
                oacc[mt][nt][0] *= c0f; oacc[mt][nt][1] *= c0f;
                oacc[mt][nt][2] *= c1f; oacc[mt][nt][3] *= c1f;
            }
        }

        // O += P V   (2-pass: P exact f16, V f16 hi/lo)
#pragma unroll
        for (int kc = 0; kc < 4; ++kc) {
#pragma unroll
            for (int p = 0; p < 4; ++p) {
                uint32_t vo = SWZ((kc*16 + (lane & 15))*128 + (16*p + ((lane >> 1) & 8))*2);
                uint32_t vbh[4], vbl[4];
                ldsm4t(vbh, kb + AVHI + vo);
                ldsm4t(vbl, kb + AVLO + vo);
#pragma unroll
                for (int mt = 0; mt < 2; ++mt) {
                    uint32_t pa[4] = { pp[mt][2*kc][0], pp[mt][2*kc][1],
                                       pp[mt][2*kc+1][0], pp[mt][2*kc+1][1] };
                    mma16816h(oacc[mt][2*p],   pa, &vbh[0]);
                    mma16816h(oacc[mt][2*p+1], pa, &vbh[2]);
                    mma16816h(oacc[mt][2*p],   pa, &vbl[0]);
                    mma16816h(oacc[mt][2*p+1], pa, &vbl[2]);
                }
            }
        }
        __syncthreads();
    }

#pragma unroll
    for (int mt = 0; mt < 2; ++mt) {
        const float inv0 = 1.f / l[mt][0], inv1 = 1.f / l[mt][1];
        const size_t tok = ((size_t)b*SS + rb0 + 16*mt)*DD + h*HDIM;
#pragma unroll
        for (int nt = 0; nt < 8; ++nt) {
            int col = 8*nt + 2*(lane & 3);
            split_store(g_Chi, g_Clo, tok + col,        oacc[mt][nt][0]*inv0, oacc[mt][nt][1]*inv0);
            split_store(g_Chi, g_Clo, tok + 8*DD + col, oacc[mt][nt][2]*inv1, oacc[mt][nt][3]*inv1);
        }
    }
}

// ---------------- launch ----------------
extern "C" void kernel_launch(void* const* d_in, const int* in_sizes, int n_in,
                              void* d_out, int out_size)
{
    const float* x  = (const float*)d_in[0];
    const float* Wq = (const float*)d_in[1];
    const float* Wk = (const float*)d_in[2];
    const float* Wv = (const float*)d_in[3];
    const float* Wo = (const float*)d_in[4];
    const float* bo = (const float*)d_in[5];
    float* out = (float*)d_out;
    (void)in_sizes; (void)n_in; (void)out_size;

    static bool attr_done = false;
    if (!attr_done) {
        cudaFuncSetAttribute(qkv_hmma, cudaFuncAttributeMaxDynamicSharedMemorySize, GEMM_SMEM);
        cudaFuncSetAttribute(out_hmma, cudaFuncAttributeMaxDynamicSharedMemorySize, GEMM_SMEM);
        cudaFuncSetAttribute(attn_hmma, cudaFuncAttributeMaxDynamicSharedMemorySize, ATTN_SMEM);
        attr_done = true;
    }

    split_all<<<(XN4 + 4*WN4) / 256, 256>>>(x, Wq, Wk, Wv, Wo);

    dim3 qkv_grid(DD/128, MTOT/128, 3);
    qkv_hmma<<<qkv_grid, 128, GEMM_SMEM>>>();

    dim3 attn_grid(SS/128, HH, BB);
    attn_hmma<<<attn_grid, 128, ATTN_SMEM>>>();

    dim3 out_grid(DD/128, MTOT/128, 1);
    out_hmma<<<out_grid, 128, GEMM_SMEM>>>(out, bo);
}

// round 9
// speedup vs baseline: 5.6870x; 1.3177x over previous
#include <cuda_runtime.h>
#include <cuda_bf16.h>
#include <cuda_fp16.h>
#include <cstdint>
#include <cstddef>

#define BB 2
#define SS 2048
#define DD 1024
#define HH 16
#define HDIM 64
#define MTOT (BB*SS)   // 4096

// ---------------- device-global scratch (all f16 now) ----------------
__device__ __half g_xh[MTOT*DD];                  // x, single f16 (A-side)
__device__ __half g_Wqh[DD*DD], g_Wql[DD*DD];     // weights f16 hi/lo (B-side)
__device__ __half g_Wkh[DD*DD], g_Wkl[DD*DD];
__device__ __half g_Wvh[DD*DD], g_Wvl[DD*DD];
__device__ __half g_Woh[DD*DD], g_Wol[DD*DD];
__device__ __half g_Qh[MTOT*DD];                  // Q single f16, pre-scaled 0.125*log2(e)
__device__ __half g_Kh[MTOT*DD], g_Kl[MTOT*DD];   // K f16 hi/lo
__device__ __half g_Vh[MTOT*DD], g_Vl[MTOT*DD];   // V f16 hi/lo
__device__ __half g_Ch[MTOT*DD];                  // ctx single f16 (A-side of out GEMM)

// ---------------- helpers ----------------
__device__ __forceinline__ uint32_t smem_u32(const void* p) {
    uint32_t a;
    asm("{ .reg .u64 t; cvta.to.shared.u64 t, %1; cvt.u32.u64 %0, t; }" : "=r"(a) : "l"(p));
    return a;
}
#define SWZ(o)   ((uint32_t)(o) ^ ((((uint32_t)(o)) >> 3) & 0x70))
#define SWZ64(o) ((uint32_t)(o) ^ ((((uint32_t)(o)) >> 3) & 0x30))

__device__ __forceinline__ void cp16(uint32_t d, const void* s) {
    asm volatile("cp.async.cg.shared.global [%0], [%1], 16;" :: "r"(d), "l"(s));
}
#define CP_COMMIT() asm volatile("cp.async.commit_group;" ::: "memory")
#define CP_WAIT1()  asm volatile("cp.async.wait_group 1;" ::: "memory")
#define CP_WAIT0()  asm volatile("cp.async.wait_group 0;" ::: "memory")

__device__ __forceinline__ void ldsm4(uint32_t* r, uint32_t a) {
    asm volatile("ldmatrix.sync.aligned.m8n8.x4.shared.b16 {%0,%1,%2,%3}, [%4];"
        : "=r"(r[0]), "=r"(r[1]), "=r"(r[2]), "=r"(r[3]) : "r"(a));
}
__device__ __forceinline__ void ldsm4t(uint32_t* r, uint32_t a) {
    asm volatile("ldmatrix.sync.aligned.m8n8.x4.trans.shared.b16 {%0,%1,%2,%3}, [%4];"
        : "=r"(r[0]), "=r"(r[1]), "=r"(r[2]), "=r"(r[3]) : "r"(a));
}
__device__ __forceinline__ void mma16816h(float* c, const uint32_t* a, const uint32_t* b) {
    asm volatile("mma.sync.aligned.m16n8k16.row.col.f32.f16.f16.f32 "
        "{%0,%1,%2,%3}, {%4,%5,%6,%7}, {%8,%9}, {%0,%1,%2,%3};"
        : "+f"(c[0]), "+f"(c[1]), "+f"(c[2]), "+f"(c[3])
        : "r"(a[0]), "r"(a[1]), "r"(a[2]), "r"(a[3]), "r"(b[0]), "r"(b[1]));
}

__device__ __forceinline__ uint32_t ex2pack(float lo, float hi) {
    uint32_t d, r;
    asm("cvt.rn.f16x2.f32 %0, %1, %2;" : "=r"(d) : "f"(hi), "f"(lo));
    asm("ex2.approx.f16x2 %0, %1;" : "=r"(r) : "r"(d));
    return r;
}
__device__ __forceinline__ float ex2f(float x) {
    float r; asm("ex2.approx.f32 %0, %1;" : "=f"(r) : "f"(x)); return r;
}

// pack two f32 -> f16x2 word
__device__ __forceinline__ uint32_t pk_h2(float v0, float v1) {
    __half2 p; p.x = __float2half_rn(v0); p.y = __float2half_rn(v1);
    return *(uint32_t*)&p;
}
// f16 hi/lo split of two floats
__device__ __forceinline__ void pk_split_h(uint32_t& hi, uint32_t& lo, float v0, float v1) {
    __half hx = __float2half_rn(v0), hy = __float2half_rn(v1);
    __half2 ph; ph.x = hx; ph.y = hy;
    float rx = v0 - __half2float(hx), ry = v1 - __half2float(hy);
    __half2 pl; pl.x = __float2half_rn(rx); pl.y = __float2half_rn(ry);
    hi = *(uint32_t*)&ph;
    lo = *(uint32_t*)&pl;
}
__device__ __forceinline__ void split_store_h(__half* hi, __half* lo, size_t off, float v0, float v1) {
    uint32_t h, l;
    pk_split_h(h, l, v0, v1);
    *(uint32_t*)(hi + off) = h;
    *(uint32_t*)(lo + off) = l;
}

// ---------------- fused fp32 -> f16 split (x single + 4 weights hi/lo) -----
#define XN4 (MTOT*DD/4)          // 1048576
#define WN4 (DD*DD/4)            // 262144  (= 1<<18)

__global__ __launch_bounds__(256) void split_all(const float* __restrict__ x,
                                                 const float* __restrict__ Wq,
                                                 const float* __restrict__ Wk,
                                                 const float* __restrict__ Wv,
                                                 const float* __restrict__ Wo)
{
    int i = blockIdx.x * blockDim.x + threadIdx.x;
    if (i < XN4) {
        float4 v = ((const float4*)x)[i];
        ((uint32_t*)g_xh)[i*2+0] = pk_h2(v.x, v.y);
        ((uint32_t*)g_xh)[i*2+1] = pk_h2(v.z, v.w);
        return;
    }
    int j = i - XN4;
    int w = j >> 18;
    int off = j & (WN4 - 1);
    const float* s;
    __half *hi, *lo;
    if (w == 0)      { s = Wq; hi = g_Wqh; lo = g_Wql; }
    else if (w == 1) { s = Wk; hi = g_Wkh; lo = g_Wkl; }
    else if (w == 2) { s = Wv; hi = g_Wvh; lo = g_Wvl; }
    else             { s = Wo; hi = g_Woh; lo = g_Wol; }
    float4 v = ((const float4*)s)[off];
    uint32_t h0, l0, h1, l1;
    pk_split_h(h0, l0, v.x, v.y);
    pk_split_h(h1, l1, v.z, v.w);
    ((uint32_t*)hi)[off*2+0] = h0; ((uint32_t*)hi)[off*2+1] = h1;
    ((uint32_t*)lo)[off*2+0] = l0; ((uint32_t*)lo)[off*2+1] = l1;
}

// ---------------- f16 2-pass HMMA GEMM core --------------------------------
// C = A @ (Bh + Bl)^T.  CTA tile 128x128, 128 threads (2x2 warps, 64x64/warp).
// K-chunk 32 (SW64, 64B rows), 2-stage cp.async, 2 CTAs/SM.
#define SM_A  0u
#define SM_BH 8192u
#define SM_BL 16384u
#define STG   24576u
#define GEMM_SMEM (2*24576)

__device__ __forceinline__ void gemm_load(uint32_t sb, int st,
    const __half* __restrict__ A,
    const __half* __restrict__ Bh, const __half* __restrict__ Bl,
    int r0, int c0, int kt, int tid)
{
    const uint32_t base = sb + (uint32_t)st * STG;
#pragma unroll
    for (int i = 0; i < 4; ++i) {
        int idx = tid + i*128;                // 0..511
        int row = idx >> 2, c16 = idx & 3;
        uint32_t so = SWZ64(row*64 + c16*16);
        size_t ga = (size_t)(r0+row)*DD + kt + c16*8;
        size_t gb = (size_t)(c0+row)*DD + kt + c16*8;
        cp16(base + SM_A  + so, A  + ga);
        cp16(base + SM_BH + so, Bh + gb);
        cp16(base + SM_BL + so, Bl + gb);
    }
}

__device__ __forceinline__ void hgemm_core(const __half* __restrict__ A,
                                           const __half* __restrict__ Bh,
                                           const __half* __restrict__ Bl,
                                           int r0, int c0, float acc[4][8][4])
{
    extern __shared__ char smem[];
    const uint32_t sb = smem_u32(smem);
    const int tid = threadIdx.x, lane = tid & 31, wid = tid >> 5;
    const int wr = wid >> 1, wc = wid & 1;

#pragma unroll
    for (int i = 0; i < 4; ++i)
#pragma unroll
        for (int j = 0; j < 8; ++j)
#pragma unroll
            for (int e = 0; e < 4; ++e) acc[i][j][e] = 0.f;

    const int arow  = 64*wr + (lane & 15);
    const int acol8 = (lane >> 4) * 8;
    const int brow  = 64*wc + (lane & 7) + ((lane & 16) >> 1);
    const int bk8   = lane & 8;

    gemm_load(sb, 0, A, Bh, Bl, r0, c0, 0, tid);
    CP_COMMIT();

    for (int ch = 0; ch < 32; ++ch) {
        if (ch < 31) {
            gemm_load(sb, (ch+1) & 1, A, Bh, Bl, r0, c0, (ch+1)*32, tid);
            CP_COMMIT();
            CP_WAIT1();
        } else {
            CP_WAIT0();
        }
        __syncthreads();

        const uint32_t cb = sb + (uint32_t)(ch & 1) * STG;
#pragma unroll
        for (int t = 0; t < 2; ++t) {
            uint32_t fa[4][4], fbh[4][4], fbl[4][4];
#pragma unroll
            for (int mt = 0; mt < 4; ++mt) {
                uint32_t ao = SWZ64((arow + 16*mt)*64 + (t*16 + acol8)*2);
                ldsm4(fa[mt], cb + SM_A + ao);
            }
#pragma unroll
            for (int p = 0; p < 4; ++p) {
                uint32_t bo = SWZ64((brow + 16*p)*64 + (t*16 + bk8)*2);
                ldsm4(fbh[p], cb + SM_BH + bo);
                ldsm4(fbl[p], cb + SM_BL + bo);
            }
#pragma unroll
            for (int mt = 0; mt < 4; ++mt)
#pragma unroll
                for (int p = 0; p < 4; ++p) {
                    mma16816h(acc[mt][2*p],   fa[mt], &fbh[p][0]);
                    mma16816h(acc[mt][2*p+1], fa[mt], &fbh[p][2]);
                    mma16816h(acc[mt][2*p],   fa[mt], &fbl[p][0]);
                    mma16816h(acc[mt][2*p+1], fa[mt], &fbl[p][2]);
                }
        }
        __syncthreads();
    }
}

__global__ __launch_bounds__(128, 2) void qkv_hmma()
{
    const __half *Bh, *Bl;
    if (blockIdx.z == 0)      { Bh = g_Wqh; Bl = g_Wql; }
    else if (blockIdx.z == 1) { Bh = g_Wkh; Bl = g_Wkl; }
    else                      { Bh = g_Wvh; Bl = g_Wvl; }

    float acc[4][8][4];
    const int r0 = blockIdx.y * 128, c0 = blockIdx.x * 128;
    hgemm_core(g_xh, Bh, Bl, r0, c0, acc);

    const int tid = threadIdx.x, lane = tid & 31, wid = tid >> 5;
    const int wr = wid >> 1, wc = wid & 1;
    const float scale = 0.18033688f;   // 0.125 * log2(e), Q only
#pragma unroll
    for (int mt = 0; mt < 4; ++mt)
#pragma unroll
        for (int nt = 0; nt < 8; ++nt) {
            int rg = r0 + 64*wr + 16*mt + (lane >> 2);
            int cg = c0 + 64*wc + 8*nt + 2*(lane & 3);
            int bidx = rg >> 11, s = rg & 2047, h = cg >> 6, hd = cg & 63;
            size_t base = (((size_t)bidx*HH + h)*SS + s)*HDIM + hd;
            if (blockIdx.z == 0) {
                *(uint32_t*)(g_Qh + base)          = pk_h2(acc[mt][nt][0]*scale, acc[mt][nt][1]*scale);
                *(uint32_t*)(g_Qh + base + 8*HDIM) = pk_h2(acc[mt][nt][2]*scale, acc[mt][nt][3]*scale);
            } else if (blockIdx.z == 1) {
                split_store_h(g_Kh, g_Kl, base,          acc[mt][nt][0], acc[mt][nt][1]);
                split_store_h(g_Kh, g_Kl, base + 8*HDIM, acc[mt][nt][2], acc[mt][nt][3]);
            } else {
                split_store_h(g_Vh, g_Vl, base,          acc[mt][nt][0], acc[mt][nt][1]);
                split_store_h(g_Vh, g_Vl, base + 8*HDIM, acc[mt][nt][2], acc[mt][nt][3]);
            }
        }
}

__global__ __launch_bounds__(128, 2) void out_hmma(float* __restrict__ out,
                                                   const float* __restrict__ bo)
{
    float acc[4][8][4];
    const int r0 = blockIdx.y * 128, c0 = blockIdx.x * 128;
    hgemm_core(g_Ch, g_Woh, g_Wol, r0, c0, acc);

    const int tid = threadIdx.x, lane = tid & 31, wid = tid >> 5;
    const int wr = wid >> 1, wc = wid & 1;
#pragma unroll
    for (int mt = 0; mt < 4; ++mt)
#pragma unroll
        for (int nt = 0; nt < 8; ++nt) {
            int rg = r0 + 64*wr + 16*mt + (lane >> 2);
            int cg = c0 + 64*wc + 8*nt + 2*(lane & 3);
            float b0v = bo[cg], b1v = bo[cg+1];
            float2 o0 = make_float2(acc[mt][nt][0] + b0v, acc[mt][nt][1] + b1v);
            float2 o1 = make_float2(acc[mt][nt][2] + b0v, acc[mt][nt][3] + b1v);
            *(float2*)&out[(size_t)rg * DD + cg] = o0;
            *(float2*)&out[(size_t)(rg+8) * DD + cg] = o1;
        }
}

// ---------------- f16 causal flash attention (exp2-domain) -----------------
// Q single f16 (A-side), K f16 hi/lo (2-pass S), P exact f16, V f16 hi/lo.
#define AQ   0u
#define AKV  16384u
#define KSTG 32768u
#define AKH  0u
#define AKL  8192u
#define AVH  16384u
#define AVL  24576u
#define ATTN_SMEM (16384 + 2*32768)

__device__ __forceinline__ void attn_load_kv(uint32_t sb, int st, size_t hb, int j0, int tid)
{
    const uint32_t base = sb + AKV + (uint32_t)st * KSTG;
#pragma unroll
    for (int i = 0; i < 4; ++i) {
        int idx = tid + i*128;               // 0..511
        int row = idx >> 3, c16 = idx & 7;
        uint32_t so = SWZ(row*128 + c16*16);
        size_t g = (hb + j0 + row)*HDIM + c16*8;
        cp16(base + AKH + so, g_Kh + g);
        cp16(base + AKL + so, g_Kl + g);
        cp16(base + AVH + so, g_Vh + g);
        cp16(base + AVL + so, g_Vl + g);
    }
}

__global__ __launch_bounds__(128, 2) void attn_hmma()
{
    extern __shared__ char smem[];
    const uint32_t sb = smem_u32(smem);
    const int tid = threadIdx.x, lane = tid & 31, wid = tid >> 5;
    const int qb = gridDim.x - 1 - blockIdx.x;   // heavy CTAs first
    const int h = blockIdx.y, b = blockIdx.z;
    const int q0 = qb * 128;
    const size_t hb = ((size_t)b*HH + h) * SS;

    // Q tile: 128 x 64 f16 = 16KB
#pragma unroll
    for (int i = 0; i < 8; ++i) {
        int idx = tid + i*128;               // 0..1023
        int row = idx >> 3, c16 = idx & 7;
        uint32_t so = SWZ(row*128 + c16*16);
        cp16(sb + AQ + so, g_Qh + (hb + q0 + row)*HDIM + c16*8);
    }
    attn_load_kv(sb, 0, hb, 0, tid);
    CP_COMMIT();

    uint32_t fq[2][4][4];
    float oacc[2][8][4];
#pragma unroll
    for (int mt = 0; mt < 2; ++mt)
#pragma unroll
        for (int nt = 0; nt < 8; ++nt)
#pragma unroll
            for (int e = 0; e < 4; ++e) oacc[mt][nt][e] = 0.f;
    float m[2][2] = {{-1e30f,-1e30f},{-1e30f,-1e30f}};
    float l[2][2] = {{0.f,0.f},{0.f,0.f}};

    const int rb0 = q0 + 32*wid + (lane >> 2);
    const int ntiles = 2*qb + 2;

    for (int kt = 0; kt < ntiles; ++kt) {
        const int j0 = kt * 64;
        if (kt + 1 < ntiles) {
            attn_load_kv(sb, (kt+1) & 1, hb, j0 + 64, tid);
            CP_COMMIT();
            CP_WAIT1();
        } else {
            CP_WAIT0();
        }
        __syncthreads();

        if (kt == 0) {
#pragma unroll
            for (int mt = 0; mt < 2; ++mt)
#pragma unroll
                for (int t = 0; t < 4; ++t) {
                    uint32_t ao = SWZ((32*wid + 16*mt + (lane & 15))*128 + (t*16 + (lane >> 4)*8)*2);
                    ldsm4(fq[mt][t], sb + AQ + ao);
                }
        }

        const uint32_t kb = sb + AKV + (uint32_t)(kt & 1) * KSTG;

        // S = Q (Kh + Kl)^T   (2-pass f16)
        float sacc[2][8][4];
#pragma unroll
        for (int mt = 0; mt < 2; ++mt)
#pragma unroll
            for (int nt = 0; nt < 8; ++nt)
#pragma unroll
                for (int e = 0; e < 4; ++e) sacc[mt][nt][e] = 0.f;

#pragma unroll
        for (int t = 0; t < 4; ++t) {
#pragma unroll
            for (int p = 0; p < 4; ++p) {
                uint32_t bo_ = SWZ((16*p + (lane & 7) + ((lane & 16) >> 1))*128 + (t*16 + (lane & 8))*2);
                uint32_t kbh[4], kbl[4];
                ldsm4(kbh, kb + AKH + bo_);
                ldsm4(kbl, kb + AKL + bo_);
#pragma unroll
                for (int mt = 0; mt < 2; ++mt) {
                    mma16816h(sacc[mt][2*p],   fq[mt][t], &kbh[0]);
                    mma16816h(sacc[mt][2*p+1], fq[mt][t], &kbh[2]);
                    mma16816h(sacc[mt][2*p],   fq[mt][t], &kbl[0]);
                    mma16816h(sacc[mt][2*p+1], fq[mt][t], &kbl[2]);
                }
            }
        }

        // causal mask, online softmax (exp2), P -> packed f16 fragments
        uint32_t pp[2][8][2];
#pragma unroll
        for (int mt = 0; mt < 2; ++mt) {
            const int rbase = rb0 + 16*mt;
            if (j0 + 63 > rbase) {
#pragma unroll
                for (int nt = 0; nt < 8; ++nt) {
                    int cg = j0 + 8*nt + 2*(lane & 3);
                    if (cg   > rbase)     sacc[mt][nt][0] = -1e30f;
                    if (cg+1 > rbase)     sacc[mt][nt][1] = -1e30f;
                    if (cg   > rbase + 8) sacc[mt][nt][2] = -1e30f;
                    if (cg+1 > rbase + 8) sacc[mt][nt][3] = -1e30f;
                }
            }
            float mx0 = -1e30f, mx1 = -1e30f;
#pragma unroll
            for (int nt = 0; nt < 8; ++nt) {
                mx0 = fmaxf(mx0, fmaxf(sacc[mt][nt][0], sacc[mt][nt][1]));
                mx1 = fmaxf(mx1, fmaxf(sacc[mt][nt][2], sacc[mt][nt][3]));
            }
            mx0 = fmaxf(mx0, __shfl_xor_sync(0xffffffffu, mx0, 1));
            mx0 = fmaxf(mx0, __shfl_xor_sync(0xffffffffu, mx0, 2));
            mx1 = fmaxf(mx1, __shfl_xor_sync(0xffffffffu, mx1, 1));
            mx1 = fmaxf(mx1, __shfl_xor_sync(0xffffffffu, mx1, 2));
            const float mn0 = fmaxf(m[mt][0], mx0), mn1 = fmaxf(m[mt][1], mx1);
            const float c0f = ex2f(m[mt][0] - mn0), c1f = ex2f(m[mt][1] - mn1);
            float s0 = 0.f, s1 = 0.f;
#pragma unroll
            for (int nt = 0; nt < 8; ++nt) {
                uint32_t p01 = ex2pack(sacc[mt][nt][0] - mn0, sacc[mt][nt][1] - mn0);
                uint32_t p23 = ex2pack(sacc[mt][nt][2] - mn1, sacc[mt][nt][3] - mn1);
                pp[mt][nt][0] = p01;
                pp[mt][nt][1] = p23;
                __half2 h01 = *(__half2*)&p01;
                __half2 h23 = *(__half2*)&p23;
                s0 += __half2float(h01.x) + __half2float(h01.y);
                s1 += __half2float(h23.x) + __half2float(h23.y);
            }
            s0 += __shfl_xor_sync(0xffffffffu, s0, 1);
            s0 += __shfl_xor_sync(0xffffffffu, s0, 2);
            s1 += __shfl_xor_sync(0xffffffffu, s1, 1);
            s1 += __shfl_xor_sync(0xffffffffu, s1, 2);
            l[mt][0] = l[mt][0] * c0f + s0;
            l[mt][1] = l[mt][1] * c1f + s1;
            m[mt][0] = mn0; m[mt][1] = mn1;
#pragma unroll
            for (int nt = 0; nt < 8; ++nt) {
                oacc[mt][nt][0] *= c0f; oacc[mt][nt][1] *= c0f;
                oacc[mt][nt][2] *= c1f; oacc[mt][nt][3] *= c1f;
            }
        }

        // O += P (Vh + Vl)   (2-pass f16)
#pragma unroll
        for (int kc = 0; kc < 4; ++kc) {
#pragma unroll
            for (int p = 0; p < 4; ++p) {
                uint32_t vo = SWZ((kc*16 + (lane & 15))*128 + (16*p + ((lane >> 1) & 8))*2);
                uint32_t vbh[4], vbl[4];
                ldsm4t(vbh, kb + AVH + vo);
                ldsm4t(vbl, kb + AVL + vo);
#pragma unroll
                for (int mt = 0; mt < 2; ++mt) {
                    uint32_t pa[4] = { pp[mt][2*kc][0], pp[mt][2*kc][1],
                                       pp[mt][2*kc+1][0], pp[mt][2*kc+1][1] };
                    mma16816h(oacc[mt][2*p],   pa, &vbh[0]);
                    mma16816h(oacc[mt][2*p+1], pa, &vbh[2]);
                    mma16816h(oacc[mt][2*p],   pa, &vbl[0]);
                    mma16816h(oacc[mt][2*p+1], pa, &vbl[2]);
                }
            }
        }
        __syncthreads();
    }

    // epilogue: ctx as single f16 [token][d]
#pragma unroll
    for (int mt = 0; mt < 2; ++mt) {
        const float inv0 = 1.f / l[mt][0], inv1 = 1.f / l[mt][1];
        const size_t tok = ((size_t)b*SS + rb0 + 16*mt)*DD + h*HDIM;
#pragma unroll
        for (int nt = 0; nt < 8; ++nt) {
            int col = 8*nt + 2*(lane & 3);
            *(uint32_t*)(g_Ch + tok + col)        = pk_h2(oacc[mt][nt][0]*inv0, oacc[mt][nt][1]*inv0);
            *(uint32_t*)(g_Ch + tok + 8*DD + col) = pk_h2(oacc[mt][nt][2]*inv1, oacc[mt][nt][3]*inv1);
        }
    }
}

// ---------------- launch ----------------
extern "C" void kernel_launch(void* const* d_in, const int* in_sizes, int n_in,
                              void* d_out, int out_size)
{
    const float* x  = (const float*)d_in[0];
    const float* Wq = (const float*)d_in[1];
    const float* Wk = (const float*)d_in[2];
    const float* Wv = (const float*)d_in[3];
    const float* Wo = (const float*)d_in[4];
    const float* bo = (const float*)d_in[5];
    float* out = (float*)d_out;
    (void)in_sizes; (void)n_in; (void)out_size;

    static bool attr_done = false;
    if (!attr_done) {
        cudaFuncSetAttribute(qkv_hmma, cudaFuncAttributeMaxDynamicSharedMemorySize, GEMM_SMEM);
        cudaFuncSetAttribute(out_hmma, cudaFuncAttributeMaxDynamicSharedMemorySize, GEMM_SMEM);
        cudaFuncSetAttribute(attn_hmma, cudaFuncAttributeMaxDynamicSharedMemorySize, ATTN_SMEM);
        attr_done = true;
    }

    split_all<<<(XN4 + 4*WN4) / 256, 256>>>(x, Wq, Wk, Wv, Wo);

    dim3 qkv_grid(DD/128, MTOT/128, 3);
    qkv_hmma<<<qkv_grid, 128, GEMM_SMEM>>>();

    dim3 attn_grid(SS/128, HH, BB);
    attn_hmma<<<attn_grid, 128, ATTN_SMEM>>>();

    dim3 out_grid(DD/128, MTOT/128, 1);
    out_hmma<<<out_grid, 128, GEMM_SMEM>>>(out, bo);
}

// round 10
// speedup vs baseline: 6.6262x; 1.1652x over previous
#include <cuda_runtime.h>
#include <cuda_bf16.h>
#include <cuda_fp16.h>
#include <cstdint>
#include <cstddef>

#define BB 2
#define SS 2048
#define DD 1024
#define HH 16
#define HDIM 64
#define MTOT (BB*SS)   // 4096

// ---------------- device-global scratch ----------------
__device__ __half g_xh[MTOT*DD];                  // x, single f16 (A-side)
__device__ __half g_Wqh[DD*DD], g_Wql[DD*DD];     // weights f16 hi/lo (B-side)
__device__ __half g_Wkh[DD*DD], g_Wkl[DD*DD];
__device__ __half g_Wvh[DD*DD], g_Wvl[DD*DD];
__device__ __half g_Woh[DD*DD], g_Wol[DD*DD];
__device__ __half g_Qh[MTOT*DD];                  // Q single f16, pre-scaled 0.125*log2(e)
__device__ __half g_Kh[MTOT*DD];                  // K single f16
__device__ __half g_Vh[MTOT*DD];                  // V single f16
__device__ __half g_Ch[MTOT*DD];                  // ctx single f16

// ---------------- helpers ----------------
__device__ __forceinline__ uint32_t smem_u32(const void* p) {
    uint32_t a;
    asm("{ .reg .u64 t; cvta.to.shared.u64 t, %1; cvt.u32.u64 %0, t; }" : "=r"(a) : "l"(p));
    return a;
}
#define SWZ(o)   ((uint32_t)(o) ^ ((((uint32_t)(o)) >> 3) & 0x70))
#define SWZ64(o) ((uint32_t)(o) ^ ((((uint32_t)(o)) >> 3) & 0x30))

__device__ __forceinline__ void cp16(uint32_t d, const void* s) {
    asm volatile("cp.async.cg.shared.global [%0], [%1], 16;" :: "r"(d), "l"(s));
}
#define CP_COMMIT() asm volatile("cp.async.commit_group;" ::: "memory")
#define CP_WAIT1()  asm volatile("cp.async.wait_group 1;" ::: "memory")
#define CP_WAIT0()  asm volatile("cp.async.wait_group 0;" ::: "memory")

__device__ __forceinline__ void ldsm4(uint32_t* r, uint32_t a) {
    asm volatile("ldmatrix.sync.aligned.m8n8.x4.shared.b16 {%0,%1,%2,%3}, [%4];"
        : "=r"(r[0]), "=r"(r[1]), "=r"(r[2]), "=r"(r[3]) : "r"(a));
}
__device__ __forceinline__ void ldsm4t(uint32_t* r, uint32_t a) {
    asm volatile("ldmatrix.sync.aligned.m8n8.x4.trans.shared.b16 {%0,%1,%2,%3}, [%4];"
        : "=r"(r[0]), "=r"(r[1]), "=r"(r[2]), "=r"(r[3]) : "r"(a));
}
__device__ __forceinline__ void mma16816h(float* c, const uint32_t* a, const uint32_t* b) {
    asm volatile("mma.sync.aligned.m16n8k16.row.col.f32.f16.f16.f32 "
        "{%0,%1,%2,%3}, {%4,%5,%6,%7}, {%8,%9}, {%0,%1,%2,%3};"
        : "+f"(c[0]), "+f"(c[1]), "+f"(c[2]), "+f"(c[3])
        : "r"(a[0]), "r"(a[1]), "r"(a[2]), "r"(a[3]), "r"(b[0]), "r"(b[1]));
}

__device__ __forceinline__ uint32_t ex2pack(float lo, float hi) {
    uint32_t d, r;
    asm("cvt.rn.f16x2.f32 %0, %1, %2;" : "=r"(d) : "f"(hi), "f"(lo));
    asm("ex2.approx.f16x2 %0, %1;" : "=r"(r) : "r"(d));
    return r;
}
__device__ __forceinline__ float ex2f(float x) {
    float r; asm("ex2.approx.f32 %0, %1;" : "=f"(r) : "f"(x)); return r;
}

__device__ __forceinline__ uint32_t pk_h2(float v0, float v1) {
    __half2 p; p.x = __float2half_rn(v0); p.y = __float2half_rn(v1);
    return *(uint32_t*)&p;
}
__device__ __forceinline__ void pk_split_h(uint32_t& hi, uint32_t& lo, float v0, float v1) {
    __half hx = __float2half_rn(v0), hy = __float2half_rn(v1);
    __half2 ph; ph.x = hx; ph.y = hy;
    float rx = v0 - __half2float(hx), ry = v1 - __half2float(hy);
    __half2 pl; pl.x = __float2half_rn(rx); pl.y = __float2half_rn(ry);
    hi = *(uint32_t*)&ph;
    lo = *(uint32_t*)&pl;
}

// ---------------- fused fp32 -> f16 split (x single + 4 weights hi/lo) -----
#define XN4 (MTOT*DD/4)          // 1048576
#define WN4 (DD*DD/4)            // 262144  (= 1<<18)

__global__ __launch_bounds__(256) void split_all(const float* __restrict__ x,
                                                 const float* __restrict__ Wq,
                                                 const float* __restrict__ Wk,
                                                 const float* __restrict__ Wv,
                                                 const float* __restrict__ Wo)
{
    int i = blockIdx.x * blockDim.x + threadIdx.x;
    if (i < XN4) {
        float4 v = ((const float4*)x)[i];
        ((uint32_t*)g_xh)[i*2+0] = pk_h2(v.x, v.y);
        ((uint32_t*)g_xh)[i*2+1] = pk_h2(v.z, v.w);
        return;
    }
    int j = i - XN4;
    int w = j >> 18;
    int off = j & (WN4 - 1);
    const float* s;
    __half *hi, *lo;
    if (w == 0)      { s = Wq; hi = g_Wqh; lo = g_Wql; }
    else if (w == 1) { s = Wk; hi = g_Wkh; lo = g_Wkl; }
    else if (w == 2) { s = Wv; hi = g_Wvh; lo = g_Wvl; }
    else             { s = Wo; hi = g_Woh; lo = g_Wol; }
    float4 v = ((const float4*)s)[off];
    uint32_t h0, l0, h1, l1;
    pk_split_h(h0, l0, v.x, v.y);
    pk_split_h(h1, l1, v.z, v.w);
    ((uint32_t*)hi)[off*2+0] = h0; ((uint32_t*)hi)[off*2+1] = h1;
    ((uint32_t*)lo)[off*2+0] = l0; ((uint32_t*)lo)[off*2+1] = l1;
}

// ---------------- f16 2-pass HMMA GEMM core --------------------------------
// C = A @ (Bh + Bl)^T.  CTA tile 128x128, 128 threads (2x2 warps, 64x64/warp).
// K-chunk 32 (SW64, 64B rows), 2-stage cp.async, 2 CTAs/SM.
#define SM_A  0u
#define SM_BH 8192u
#define SM_BL 16384u
#define STG   24576u
#define GEMM_SMEM (2*24576)

__device__ __forceinline__ void gemm_load(uint32_t sb, int st,
    const __half* __restrict__ A,
    const __half* __restrict__ Bh, const __half* __restrict__ Bl,
    int r0, int c0, int kt, int tid)
{
    const uint32_t base = sb + (uint32_t)st * STG;
#pragma unroll
    for (int i = 0; i < 4; ++i) {
        int idx = tid + i*128;                // 0..511
        int row = idx >> 2, c16 = idx & 3;
        uint32_t so = SWZ64(row*64 + c16*16);
        size_t ga = (size_t)(r0+row)*DD + kt + c16*8;
        size_t gb = (size_t)(c0+row)*DD + kt + c16*8;
        cp16(base + SM_A  + so, A  + ga);
        cp16(base + SM_BH + so, Bh + gb);
        cp16(base + SM_BL + so, Bl + gb);
    }
}

__device__ __forceinline__ void hgemm_core(const __half* __restrict__ A,
                                           const __half* __restrict__ Bh,
                                           const __half* __restrict__ Bl,
                                           int r0, int c0, float acc[4][8][4])
{
    extern __shared__ char smem[];
    const uint32_t sb = smem_u32(smem);
    const int tid = threadIdx.x, lane = tid & 31, wid = tid >> 5;
    const int wr = wid >> 1, wc = wid & 1;

#pragma unroll
    for (int i = 0; i < 4; ++i)
#pragma unroll
        for (int j = 0; j < 8; ++j)
#pragma unroll
            for (int e = 0; e < 4; ++e) acc[i][j][e] = 0.f;

    const int arow  = 64*wr + (lane & 15);
    const int acol8 = (lane >> 4) * 8;
    const int brow  = 64*wc + (lane & 7) + ((lane & 16) >> 1);
    const int bk8   = lane & 8;

    gemm_load(sb, 0, A, Bh, Bl, r0, c0, 0, tid);
    CP_COMMIT();

    for (int ch = 0; ch < 32; ++ch) {
        if (ch < 31) {
            gemm_load(sb, (ch+1) & 1, A, Bh, Bl, r0, c0, (ch+1)*32, tid);
            CP_COMMIT();
            CP_WAIT1();
        } else {
            CP_WAIT0();
        }
        __syncthreads();

        const uint32_t cb = sb + (uint32_t)(ch & 1) * STG;
#pragma unroll
        for (int t = 0; t < 2; ++t) {
            uint32_t fa[4][4], fbh[4][4], fbl[4][4];
#pragma unroll
            for (int mt = 0; mt < 4; ++mt) {
                uint32_t ao = SWZ64((arow + 16*mt)*64 + (t*16 + acol8)*2);
                ldsm4(fa[mt], cb + SM_A + ao);
            }
#pragma unroll
            for (int p = 0; p < 4; ++p) {
                uint32_t bo = SWZ64((brow + 16*p)*64 + (t*16 + bk8)*2);
                ldsm4(fbh[p], cb + SM_BH + bo);
                ldsm4(fbl[p], cb + SM_BL + bo);
            }
            // pass 1: Bh sweep (same-acc reuse distance = full sweep)
#pragma unroll
            for (int mt = 0; mt < 4; ++mt)
#pragma unroll
                for (int p = 0; p < 4; ++p) {
                    mma16816h(acc[mt][2*p],   fa[mt], &fbh[p][0]);
                    mma16816h(acc[mt][2*p+1], fa[mt], &fbh[p][2]);
                }
            // pass 2: Bl sweep
#pragma unroll
            for (int mt = 0; mt < 4; ++mt)
#pragma unroll
                for (int p = 0; p < 4; ++p) {
                    mma16816h(acc[mt][2*p],   fa[mt], &fbl[p][0]);
                    mma16816h(acc[mt][2*p+1], fa[mt], &fbl[p][2]);
                }
        }
        __syncthreads();
    }
}

__global__ __launch_bounds__(128, 2) void qkv_hmma()
{
    const __half *Bh, *Bl;
    if (blockIdx.z == 0)      { Bh = g_Wqh; Bl = g_Wql; }
    else if (blockIdx.z == 1) { Bh = g_Wkh; Bl = g_Wkl; }
    else                      { Bh = g_Wvh; Bl = g_Wvl; }

    float acc[4][8][4];
    const int r0 = blockIdx.y * 128, c0 = blockIdx.x * 128;
    hgemm_core(g_xh, Bh, Bl, r0, c0, acc);

    const int tid = threadIdx.x, lane = tid & 31, wid = tid >> 5;
    const int wr = wid >> 1, wc = wid & 1;
    __half* O = (blockIdx.z == 0) ? g_Qh : (blockIdx.z == 1) ? g_Kh : g_Vh;
    const float scale = (blockIdx.z == 0) ? 0.18033688f : 1.f;  // 0.125*log2(e) for Q
#pragma unroll
    for (int mt = 0; mt < 4; ++mt)
#pragma unroll
        for (int nt = 0; nt < 8; ++nt) {
            int rg = r0 + 64*wr + 16*mt + (lane >> 2);
            int cg = c0 + 64*wc + 8*nt + 2*(lane & 3);
            int bidx = rg >> 11, s = rg & 2047, h = cg >> 6, hd = cg & 63;
            size_t base = (((size_t)bidx*HH + h)*SS + s)*HDIM + hd;
            *(uint32_t*)(O + base)          = pk_h2(acc[mt][nt][0]*scale, acc[mt][nt][1]*scale);
            *(uint32_t*)(O + base + 8*HDIM) = pk_h2(acc[mt][nt][2]*scale, acc[mt][nt][3]*scale);
        }
}

__global__ __launch_bounds__(128, 2) void out_hmma(float* __restrict__ out,
                                                   const float* __restrict__ bo)
{
    float acc[4][8][4];
    const int r0 = blockIdx.y * 128, c0 = blockIdx.x * 128;
    hgemm_core(g_Ch, g_Woh, g_Wol, r0, c0, acc);

    const int tid = threadIdx.x, lane = tid & 31, wid = tid >> 5;
    const int wr = wid >> 1, wc = wid & 1;
#pragma unroll
    for (int mt = 0; mt < 4; ++mt)
#pragma unroll
        for (int nt = 0; nt < 8; ++nt) {
            int rg = r0 + 64*wr + 16*mt + (lane >> 2);
            int cg = c0 + 64*wc + 8*nt + 2*(lane & 3);
            float b0v = bo[cg], b1v = bo[cg+1];
            float2 o0 = make_float2(acc[mt][nt][0] + b0v, acc[mt][nt][1] + b1v);
            float2 o1 = make_float2(acc[mt][nt][2] + b0v, acc[mt][nt][3] + b1v);
            *(float2*)&out[(size_t)rg * DD + cg] = o0;
            *(float2*)&out[(size_t)(rg+8) * DD + cg] = o1;
        }
}

// ---------------- f16 causal flash attention (single-pass K & V) -----------
// Q/K/V all single f16; P exact f16; exp2-domain softmax.
#define AQ   0u
#define AKV  16384u
#define KSTG 16384u
#define AKH  0u
#define AVH  8192u
#define ATTN_SMEM (16384 + 2*16384)

__device__ __forceinline__ void attn_load_kv(uint32_t sb, int st, size_t hb, int j0, int tid)
{
    const uint32_t base = sb + AKV + (uint32_t)st * KSTG;
#pragma unroll
    for (int i = 0; i < 4; ++i) {
        int idx = tid + i*128;               // 0..511
        int row = idx >> 3, c16 = idx & 7;
        uint32_t so = SWZ(row*128 + c16*16);
        size_t g = (hb + j0 + row)*HDIM + c16*8;
        cp16(base + AKH + so, g_Kh + g);
        cp16(base + AVH + so, g_Vh + g);
    }
}

__global__ __launch_bounds__(128, 2) void attn_hmma()
{
    extern __shared__ char smem[];
    const uint32_t sb = smem_u32(smem);
    const int tid = threadIdx.x, lane = tid & 31, wid = tid >> 5;
    const int qb = gridDim.x - 1 - blockIdx.x;   // heavy CTAs first
    const int h = blockIdx.y, b = blockIdx.z;
    const int q0 = qb * 128;
    const size_t hb = ((size_t)b*HH + h) * SS;

    // Q tile: 128 x 64 f16 = 16KB
#pragma unroll
    for (int i = 0; i < 8; ++i) {
        int idx = tid + i*128;               // 0..1023
        int row = idx >> 3, c16 = idx & 7;
        uint32_t so = SWZ(row*128 + c16*16);
        cp16(sb + AQ + so, g_Qh + (hb + q0 + row)*HDIM + c16*8);
    }
    attn_load_kv(sb, 0, hb, 0, tid);
    CP_COMMIT();

    uint32_t fq[2][4][4];
    float oacc[2][8][4];
#pragma unroll
    for (int mt = 0; mt < 2; ++mt)
#pragma unroll
        for (int nt = 0; nt < 8; ++nt)
#pragma unroll
            for (int e = 0; e < 4; ++e) oacc[mt][nt][e] = 0.f;
    float m[2][2] = {{-1e30f,-1e30f},{-1e30f,-1e30f}};
    float l[2][2] = {{0.f,0.f},{0.f,0.f}};

    const int rb0 = q0 + 32*wid + (lane >> 2);
    const int ntiles = 2*qb + 2;

    for (int kt = 0; kt < ntiles; ++kt) {
        const int j0 = kt * 64;
        if (kt + 1 < ntiles) {
            attn_load_kv(sb, (kt+1) & 1, hb, j0 + 64, tid);
            CP_COMMIT();
            CP_WAIT1();
        } else {
            CP_WAIT0();
        }
        __syncthreads();

        if (kt == 0) {
#pragma unroll
            for (int mt = 0; mt < 2; ++mt)
#pragma unroll
                for (int t = 0; t < 4; ++t) {
                    uint32_t ao = SWZ((32*wid + 16*mt + (lane & 15))*128 + (t*16 + (lane >> 4)*8)*2);
                    ldsm4(fq[mt][t], sb + AQ + ao);
                }
        }

        const uint32_t kb = sb + AKV + (uint32_t)(kt & 1) * KSTG;

        // S = Q K^T   (single-pass f16)
        float sacc[2][8][4];
#pragma unroll
        for (int mt = 0; mt < 2; ++mt)
#pragma unroll
            for (int nt = 0; nt < 8; ++nt)
#pragma unroll
                for (int e = 0; e < 4; ++e) sacc[mt][nt][e] = 0.f;

#pragma unroll
        for (int t = 0; t < 4; ++t) {
#pragma unroll
            for (int p = 0; p < 4; ++p) {
                uint32_t bo_ = SWZ((16*p + (lane & 7) + ((lane & 16) >> 1))*128 + (t*16 + (lane & 8))*2);
                uint32_t kbh[4];
                ldsm4(kbh, kb + AKH + bo_);
#pragma unroll
                for (int mt = 0; mt < 2; ++mt) {
                    mma16816h(sacc[mt][2*p],   fq[mt][t], &kbh[0]);
                    mma16816h(sacc[mt][2*p+1], fq[mt][t], &kbh[2]);
                }
            }
        }

        // causal mask, online softmax (exp2), P -> packed f16 fragments
        uint32_t pp[2][8][2];
#pragma unroll
        for (int mt = 0; mt < 2; ++mt) {
            const int rbase = rb0 + 16*mt;
            if (j0 + 63 > rbase) {
#pragma unroll
                for (int nt = 0; nt < 8; ++nt) {
                    int cg = j0 + 8*nt + 2*(lane & 3);
                    if (cg   > rbase)     sacc[mt][nt][0] = -1e30f;
                    if (cg+1 > rbase)     sacc[mt][nt][1] = -1e30f;
                    if (cg   > rbase + 8) sacc[mt][nt][2] = -1e30f;
                    if (cg+1 > rbase + 8) sacc[mt][nt][3] = -1e30f;
                }
            }
            float mx0 = -1e30f, mx1 = -1e30f;
#pragma unroll
            for (int nt = 0; nt < 8; ++nt) {
                mx0 = fmaxf(mx0, fmaxf(sacc[mt][nt][0], sacc[mt][nt][1]));
                mx1 = fmaxf(mx1, fmaxf(sacc[mt][nt][2], sacc[mt][nt][3]));
            }
            mx0 = fmaxf(mx0, __shfl_xor_sync(0xffffffffu, mx0, 1));
            mx0 = fmaxf(mx0, __shfl_xor_sync(0xffffffffu, mx0, 2));
            mx1 = fmaxf(mx1, __shfl_xor_sync(0xffffffffu, mx1, 1));
            mx1 = fmaxf(mx1, __shfl_xor_sync(0xffffffffu, mx1, 2));
            const float mn0 = fmaxf(m[mt][0], mx0), mn1 = fmaxf(m[mt][1], mx1);
            const float c0f = ex2f(m[mt][0] - mn0), c1f = ex2f(m[mt][1] - mn1);
            float s0 = 0.f, s1 = 0.f;
#pragma unroll
            for (int nt = 0; nt < 8; ++nt) {
                uint32_t p01 = ex2pack(sacc[mt][nt][0] - mn0, sacc[mt][nt][1] - mn0);
                uint32_t p23 = ex2pack(sacc[mt][nt][2] - mn1, sacc[mt][nt][3] - mn1);
                pp[mt][nt][0] = p01;
                pp[mt][nt][1] = p23;
                __half2 h01 = *(__half2*)&p01;
                __half2 h23 = *(__half2*)&p23;
                s0 += __half2float(h01.x) + __half2float(h01.y);
                s1 += __half2float(h23.x) + __half2float(h23.y);
            }
            s0 += __shfl_xor_sync(0xffffffffu, s0, 1);
            s0 += __shfl_xor_sync(0xffffffffu, s0, 2);
            s1 += __shfl_xor_sync(0xffffffffu, s1, 1);
            s1 += __shfl_xor_sync(0xffffffffu, s1, 2);
            l[mt][0] = l[mt][0] * c0f + s0;
            l[mt][1] = l[mt][1] * c1f + s1;
            m[mt][0] = mn0; m[mt][1] = mn1;
#pragma unroll
            for (int nt = 0; nt < 8; ++nt) {
                oacc[mt][nt][0] *= c0f; oacc[mt][nt][1] *= c0f;
                oacc[mt][nt][2] *= c1f; oacc[mt][nt][3] *= c1f;
            }
        }

        // O += P V   (single-pass f16)
#pragma unroll
        for (int kc = 0; kc < 4; ++kc) {
#pragma unroll
            for (int p = 0; p < 4; ++p) {
                uint32_t vo = SWZ((kc*16 + (lane & 15))*128 + (16*p + ((lane >> 1) & 8))*2);
                uint32_t vbh[4];
                ldsm4t(vbh, kb + AVH + vo);
#pragma unroll
                for (int mt = 0; mt < 2; ++mt) {
                    uint32_t pa[4] = { pp[mt][2*kc][0], pp[mt][2*kc][1],
                                       pp[mt][2*kc+1][0], pp[mt][2*kc+1][1] };
                    mma16816h(oacc[mt][2*p],   pa, &vbh[0]);
                    mma16816h(oacc[mt][2*p+1], pa, &vbh[2]);
                }
            }
        }
        __syncthreads();
    }

    // epilogue: ctx as single f16 [token][d]
#pragma unroll
    for (int mt = 0; mt < 2; ++mt) {
        const float inv0 = 1.f / l[mt][0], inv1 = 1.f / l[mt][1];
        const size_t tok = ((size_t)b*SS + rb0 + 16*mt)*DD + h*HDIM;
#pragma unroll
        for (int nt = 0; nt < 8; ++nt) {
            int col = 8*nt + 2*(lane & 3);
            *(uint32_t*)(g_Ch + tok + col)        = pk_h2(oacc[mt][nt][0]*inv0, oacc[mt][nt][1]*inv0);
            *(uint32_t*)(g_Ch + tok + 8*DD + col) = pk_h2(oacc[mt][nt][2]*inv1, oacc[mt][nt][3]*inv1);
        }
    }
}

// ---------------- launch ----------------
extern "C" void kernel_launch(void* const* d_in, const int* in_sizes, int n_in,
                              void* d_out, int out_size)
{
    const float* x  = (const float*)d_in[0];
    const float* Wq = (const float*)d_in[1];
    const float* Wk = (const float*)d_in[2];
    const float* Wv = (const float*)d_in[3];
    const float* Wo = (const float*)d_in[4];
    const float* bo = (const float*)d_in[5];
    float* out = (float*)d_out;
    (void)in_sizes; (void)n_in; (void)out_size;

    static bool attr_done = false;
    if (!attr_done) {
        cudaFuncSetAttribute(qkv_hmma, cudaFuncAttributeMaxDynamicSharedMemorySize, GEMM_SMEM);
        cudaFuncSetAttribute(out_hmma, cudaFuncAttributeMaxDynamicSharedMemorySize, GEMM_SMEM);
        cudaFuncSetAttribute(attn_hmma, cudaFuncAttributeMaxDynamicSharedMemorySize, ATTN_SMEM);
        attr_done = true;
    }

    split_all<<<(XN4 + 4*WN4) / 256, 256>>>(x, Wq, Wk, Wv, Wo);

    dim3 qkv_grid(DD/128, MTOT/128, 3);
    qkv_hmma<<<qkv_grid, 128, GEMM_SMEM>>>();

    dim3 attn_grid(SS/128, HH, BB);
    attn_hmma<<<attn_grid, 128, ATTN_SMEM>>>();

    dim3 out_grid(DD/128, MTOT/128, 1);
    out_hmma<<<out_grid, 128, GEMM_SMEM>>>(out, bo);
}